// round 6
// baseline (speedup 1.0000x reference)
#include <cuda_runtime.h>
#include <math.h>
#include <stdint.h>

#define HIDC 256
#define NHEAD 8
#define CLAMP_V 5.0f

static const int NMAXC = 50000;
static const int EMAXC = 320000;

// ---------------- scratch layout (floats) ----------------
#define O_QKV  ((size_t)0)                          // N*768
#define O_CA   (O_QKV  + (size_t)NMAXC*768)         // E*256
#define O_OE   (O_CA   + (size_t)EMAXC*256)         // E*256
#define O_SCB  (O_OE   + (size_t)EMAXC*256)         // E*8
#define O_SMAX (O_SCB  + (size_t)EMAXC*8)           // N*8
#define O_SSUM (O_SMAX + (size_t)NMAXC*8)           // N*8
#define O_AGG  (O_SSUM + (size_t)NMAXC*8)           // N*256
#define O_ROWV (O_AGG  + (size_t)NMAXC*256)         // N*256
#define O_ON   (O_ROWV + (size_t)NMAXC*256)         // N*256
#define O_H1   (O_ON   + (size_t)NMAXC*256)         // N*256
#define O_HLN  (O_H1   + (size_t)NMAXC*256)         // N*256
#define O_HLNT (O_HLN  + (size_t)NMAXC*256)         // N*256
#define O_FFN  (O_HLNT + (size_t)NMAXC*256)         // N*512
#define O_H2   (O_FFN  + (size_t)NMAXC*512)         // N*256
#define O_XT   (O_H2   + (size_t)NMAXC*256)         // N*256
#define O_CT   (O_XT   + (size_t)NMAXC*256)         // E*256
#define O_WQKV (O_CT   + (size_t)EMAXC*256)         // 768*256 (transposed [N][K])
#define O_WEWB (O_WQKV + (size_t)768*256)           // 512*256
#define O_WEO  (O_WEWB + (size_t)512*256)           // 256*256
#define O_WOH  (O_WEO  + (size_t)256*256)           // 256*256
#define O_WOE  (O_WOH  + (size_t)256*256)           // 256*256
#define O_W1   (O_WOE  + (size_t)256*256)           // 512*256
#define O_W2   (O_W1   + (size_t)512*256)           // 256*512
#define O_TOTAL (O_W2  + (size_t)256*512)

__device__ float g_scratch[O_TOTAL];

static inline int cdiv(int a, int b) { return (a + b - 1) / b; }

// ---------------- tf32 helpers ----------------
__device__ __forceinline__ float tf32r(float f) {
    uint32_t r;
    asm("cvt.rna.tf32.f32 %0, %1;" : "=r"(r) : "f"(f));
    return __uint_as_float(r);
}

__device__ __forceinline__ void mma_tf32(float c[4], const uint32_t a[4], const uint32_t b[2]) {
    asm volatile(
        "mma.sync.aligned.m16n8k8.row.col.f32.tf32.tf32.f32 "
        "{%0,%1,%2,%3}, {%4,%5,%6,%7}, {%8,%9}, {%0,%1,%2,%3};"
        : "+f"(c[0]), "+f"(c[1]), "+f"(c[2]), "+f"(c[3])
        : "r"(a[0]), "r"(a[1]), "r"(a[2]), "r"(a[3]), "r"(b[0]), "r"(b[1]));
}

__device__ __forceinline__ void ldsm4(uint32_t& r0, uint32_t& r1, uint32_t& r2, uint32_t& r3,
                                      uint32_t addr) {
    asm volatile("ldmatrix.sync.aligned.m8n8.x4.shared.b16 {%0,%1,%2,%3}, [%4];"
                 : "=r"(r0), "=r"(r1), "=r"(r2), "=r"(r3) : "r"(addr));
}

__device__ __forceinline__ void cp16(uint32_t saddr, const float* g, bool pred) {
    int sz = pred ? 16 : 0;
    asm volatile("cp.async.cg.shared.global [%0], [%1], 16, %2;\n"
                 :: "r"(saddr), "l"(g), "r"(sz));
}
#define CP_COMMIT() asm volatile("cp.async.commit_group;\n" ::)
#define CP_WAIT(n)  asm volatile("cp.async.wait_group %0;\n" :: "n"(n))

__device__ __forceinline__ void atomicMaxF(float* addr, float val) {
    int* ai = (int*)addr;
    int old = *ai;
    while (__int_as_float(old) < val) {
        int assumed = old;
        old = atomicCAS(ai, assumed, __float_as_int(val));
        if (old == assumed) break;
    }
}

// ---------------- tensor-core tf32 GEMM ----------------
// A row-major [M][K] (tf32-rounded fp32). B = weights packed TRANSPOSED [N][K].
// BM=128, BN=128, BK=32, 256 thr = 8 warps (4m x 2n), warp tile 32x64.
// 3-stage cp.async pipeline, ONE barrier per k-tile, fully unrolled (K template).
// ACT: 0 normal (bias?+resid?), 1 bias+relu, 2 fused edge message
// CVT: round output to tf32. SCORE: fuse attention score (Oe GEMM only).
#define ASZ (128 * 36)
#define BSZ (128 * 36)
#define NSTAGE 3
#define GEMM_SMEM ((NSTAGE * ASZ + NSTAGE * BSZ) * 4)

template <int ACT, int CVT, int SCORE, int KVAL>
__global__ __launch_bounds__(256, 2)
void gemm_tc(const float* __restrict__ A, const float* __restrict__ B,
             const float* __restrict__ bias, const float* __restrict__ resid,
             float* __restrict__ C, int M, int N,
             const int* __restrict__ dst, const int* __restrict__ src,
             const float* __restrict__ QKV, const float* __restrict__ Aw,
             float* __restrict__ scb, float* __restrict__ smax) {
    extern __shared__ float sm[];
    constexpr int KT = KVAL / 32;

    const int tid = threadIdx.x;
    const int warp = tid >> 5;
    const int lane = tid & 31;
    const int g = lane >> 2;
    const int t = lane & 3;
    const int warp_m = warp & 3;
    const int warp_n = warp >> 2;
    const int m0 = blockIdx.x * 128;
    const int n0 = blockIdx.y * 128;

    const uint32_t sbase = (uint32_t)__cvta_generic_to_shared(sm);
    const uint32_t bbase = sbase + NSTAGE * ASZ * 4;

    // staging indices (A and B tiles: 128 rows x 32 cols)
    const int srow = tid >> 3;       // + u*32
    const int scol = (tid & 7) * 4;
    const bool apred[4] = { m0 + srow + 0 < M, m0 + srow + 32 < M,
                            m0 + srow + 64 < M, m0 + srow + 96 < M };
    const float* Aptr = A + (size_t)(m0 + srow) * KVAL + scol;
    const float* Bptr = B + (size_t)(n0 + srow) * KVAL + scol;

    // ldmatrix per-lane address components
    const int a_row = lane & 15;
    const int a_kh  = (lane >> 4) << 2;
    const int b_row = (lane & 7) + ((lane >> 4) << 3);
    const int b_kh  = ((lane >> 3) & 1) << 2;

    float acc[2][8][4];
#pragma unroll
    for (int i = 0; i < 2; i++)
#pragma unroll
        for (int j = 0; j < 8; j++)
#pragma unroll
            for (int q = 0; q < 4; q++) acc[i][j][q] = 0.0f;

    // prologue: stage tiles 0 and 1
#pragma unroll
    for (int p = 0; p < 2; p++) {
        const int k0 = p << 5;
#pragma unroll
        for (int u = 0; u < 4; u++) {
            cp16(sbase + (p * ASZ + (srow + u * 32) * 36 + scol) * 4,
                 Aptr + (size_t)(u * 32) * KVAL + k0, apred[u]);
            cp16(bbase + (p * BSZ + (srow + u * 32) * 36 + scol) * 4,
                 Bptr + (size_t)(u * 32) * KVAL + k0, true);
        }
        CP_COMMIT();
    }

#pragma unroll
    for (int kt = 0; kt < KT; kt++) {
        if (kt < KT - 2) { CP_WAIT(1); } else { CP_WAIT(0); }
        __syncthreads();

        // issue loads for tile kt+2 (buffer consumed 2 iterations ago)
        if (kt + 2 < KT) {
            const int k0 = (kt + 2) << 5;
            const int nb = (kt + 2) % NSTAGE;
#pragma unroll
            for (int u = 0; u < 4; u++) {
                cp16(sbase + (nb * ASZ + (srow + u * 32) * 36 + scol) * 4,
                     Aptr + (size_t)(u * 32) * KVAL + k0, apred[u]);
                cp16(bbase + (nb * BSZ + (srow + u * 32) * 36 + scol) * 4,
                     Bptr + (size_t)(u * 32) * KVAL + k0, true);
            }
            CP_COMMIT();
        }

        const int buf = kt % NSTAGE;
        const uint32_t abuf = sbase + buf * ASZ * 4;
        const uint32_t bbuf = bbase + buf * BSZ * 4;

#pragma unroll
        for (int ks = 0; ks < 4; ks++) {
            const int kk = ks * 8;
            uint32_t af[2][4];
#pragma unroll
            for (int i = 0; i < 2; i++) {
                int rm = warp_m * 32 + i * 16;
                ldsm4(af[i][0], af[i][1], af[i][2], af[i][3],
                      abuf + ((rm + a_row) * 36 + kk + a_kh) * 4);
            }
            uint32_t bf[8][2];
#pragma unroll
            for (int jj = 0; jj < 4; jj++) {
                int nb2 = warp_n * 64 + jj * 16;
                uint32_t r0, r1, r2, r3;
                ldsm4(r0, r1, r2, r3, bbuf + ((nb2 + b_row) * 36 + kk + b_kh) * 4);
                bf[2 * jj][0] = r0; bf[2 * jj][1] = r1;
                bf[2 * jj + 1][0] = r2; bf[2 * jj + 1][1] = r3;
            }
#pragma unroll
            for (int i = 0; i < 2; i++)
#pragma unroll
                for (int j = 0; j < 8; j++)
                    mma_tf32(acc[i][j], af[i], bf[j]);
        }
        __syncthreads();
    }

    // ---- epilogue ----
    if (ACT == 2) {
        // fused edge message: acc col pairs (even,odd) = (Ew, Eb), out col = c>>1
        float bebv[8];
        int cqv[8];
#pragma unroll
        for (int j = 0; j < 8; j++) {
            int cq = (n0 >> 1) + warp_n * 32 + j * 4 + t;
            cqv[j] = cq;
            bebv[j] = bias[cq];
        }
#pragma unroll
        for (int i = 0; i < 2; i++) {
#pragma unroll
            for (int half = 0; half < 2; half++) {
                int r = m0 + warp_m * 32 + i * 16 + half * 8 + g;
                if (r >= M) continue;
                int dn = dst[r], sn = src[r];
                const float* qrow = QKV + (size_t)dn * 768;
                const float* krow = QKV + (size_t)sn * 768 + 256;
#pragma unroll
                for (int j = 0; j < 8; j++) {
                    float ew = acc[i][j][half * 2 + 0];
                    float eb = acc[i][j][half * 2 + 1] + bebv[j];
                    float aqk = qrow[cqv[j]] + krow[cqv[j]];
                    float c1 = aqk * ew;
                    float c2 = copysignf(sqrtf(fabsf(c1)), c1);
                    float v = fmaxf(c2 + eb, 0.f);
                    C[(size_t)r * 256 + cqv[j]] = tf32r(v);
                }
            }
        }
    } else if (SCORE) {
        // Oe epilogue + fused attention score (2 heads per warp)
        const int h0 = (n0 + warp_n * 64) >> 5;
        float aw0[8], aw1[8];
#pragma unroll
        for (int j4 = 0; j4 < 4; j4++) {
            int d = j4 * 8 + 2 * t;
            aw0[2 * j4]     = __ldg(&Aw[d * 8 + h0]);
            aw0[2 * j4 + 1] = __ldg(&Aw[(d + 1) * 8 + h0]);
            aw1[2 * j4]     = __ldg(&Aw[d * 8 + h0 + 1]);
            aw1[2 * j4 + 1] = __ldg(&Aw[(d + 1) * 8 + h0 + 1]);
        }
        float2 bvj[8];
#pragma unroll
        for (int j = 0; j < 8; j++)
            bvj[j] = *(const float2*)&bias[n0 + warp_n * 64 + j * 8 + 2 * t];
#pragma unroll
        for (int i = 0; i < 2; i++) {
#pragma unroll
            for (int half = 0; half < 2; half++) {
                int r = m0 + warp_m * 32 + i * 16 + half * 8 + g;
                float s0 = 0.f, s1 = 0.f;
                if (r < M) {
#pragma unroll
                    for (int j = 0; j < 8; j++) {
                        float2 o;
                        o.x = tf32r(acc[i][j][half * 2 + 0] + bvj[j].x);
                        o.y = tf32r(acc[i][j][half * 2 + 1] + bvj[j].y);
                        int c = n0 + warp_n * 64 + j * 8 + 2 * t;
                        *(float2*)&C[(size_t)r * N + c] = o;
                        if (j < 4) {
                            s0 += o.x * aw0[2 * j] + o.y * aw0[2 * j + 1];
                        } else {
                            s1 += o.x * aw1[2 * (j - 4)] + o.y * aw1[2 * (j - 4) + 1];
                        }
                    }
                }
                s0 += __shfl_xor_sync(0xffffffffu, s0, 1);
                s0 += __shfl_xor_sync(0xffffffffu, s0, 2);
                s1 += __shfl_xor_sync(0xffffffffu, s1, 1);
                s1 += __shfl_xor_sync(0xffffffffu, s1, 2);
                if (r < M && t == 0) {
                    s0 = fminf(fmaxf(s0, -CLAMP_V), CLAMP_V);
                    s1 = fminf(fmaxf(s1, -CLAMP_V), CLAMP_V);
                    scb[(size_t)r * 8 + h0] = s0;
                    scb[(size_t)r * 8 + h0 + 1] = s1;
                    int dn = dst[r];
                    atomicMaxF(&smax[dn * 8 + h0], s0);
                    atomicMaxF(&smax[dn * 8 + h0 + 1], s1);
                }
            }
        }
    } else {
#pragma unroll
        for (int j = 0; j < 8; j++) {
            int c = n0 + warp_n * 64 + j * 8 + 2 * t;
            float2 bv = make_float2(0.f, 0.f);
            if (bias) bv = *(const float2*)&bias[c];
#pragma unroll
            for (int i = 0; i < 2; i++) {
                int rbase = m0 + warp_m * 32 + i * 16 + g;
#pragma unroll
                for (int half = 0; half < 2; half++) {
                    int r = rbase + half * 8;
                    if (r >= M) continue;
                    float2 o;
                    o.x = acc[i][j][half * 2 + 0] + bv.x;
                    o.y = acc[i][j][half * 2 + 1] + bv.y;
                    if (resid) {
                        float2 rv = *(const float2*)&resid[(size_t)r * N + c];
                        o.x += rv.x; o.y += rv.y;
                    }
                    if (ACT == 1) { o.x = fmaxf(o.x, 0.f); o.y = fmaxf(o.y, 0.f); }
                    if (CVT == 1) { o.x = tf32r(o.x); o.y = tf32r(o.y); }
                    *(float2*)&C[(size_t)r * N + c] = o;
                }
            }
        }
    }
}

// ---------------- weight pack: TRANSPOSED [N][K] + tf32 round ----------------
__global__ void pack_kernel(const float* Wq, const float* Wk, const float* Wv,
                            const float* Wew, const float* Web, const float* Weo,
                            const float* Wo_h, const float* Wo_e,
                            const float* W1, const float* W2, float* S) {
    int i = blockIdx.x * 256 + threadIdx.x;
    if (i < 196608) {  // wqkvT [768][256]
        int n = i >> 8, k = i & 255;
        float v = (n < 256) ? Wq[k * 256 + n]
                : (n < 512) ? Wk[k * 256 + n - 256]
                            : Wv[k * 256 + n - 512];
        (S + O_WQKV)[i] = tf32r(v);
    }
    int i2 = i - 196608;
    if (i2 >= 0 && i2 < 131072) {  // wewbT [512][256], rows interleaved Ew/Eb
        int n = i2 >> 8, k = i2 & 255, c = n >> 1;
        float v = (n & 1) ? Web[k * 256 + c] : Wew[k * 256 + c];
        (S + O_WEWB)[i2] = tf32r(v);
    }
    int i3 = i - 327680;
    if (i3 >= 0 && i3 < 65536) {   // weoT [256][256]
        int n = i3 >> 8, k = i3 & 255;
        (S + O_WEO)[i3] = tf32r(Weo[k * 256 + n]);
    }
    int i4 = i - 393216;
    if (i4 >= 0 && i4 < 65536) {
        int n = i4 >> 8, k = i4 & 255;
        (S + O_WOH)[i4] = tf32r(Wo_h[k * 256 + n]);
    }
    int i5 = i - 458752;
    if (i5 >= 0 && i5 < 65536) {
        int n = i5 >> 8, k = i5 & 255;
        (S + O_WOE)[i5] = tf32r(Wo_e[k * 256 + n]);
    }
    int i6 = i - 524288;
    if (i6 >= 0 && i6 < 131072) {  // w1T [512][256]
        int n = i6 >> 8, k = i6 & 255;
        (S + O_W1)[i6] = tf32r(W1[k * 512 + n]);
    }
    int i7 = i - 655360;
    if (i7 >= 0 && i7 < 131072) {  // w2T [256][512]
        int n = i7 >> 9, k = i7 & 511;
        (S + O_W2)[i7] = tf32r(W2[k * 256 + n]);
    }
}

// ---------------- tf32-round copy (float4) ----------------
__global__ void cvt_kernel(const float* __restrict__ in, float* __restrict__ out, long n4) {
    long i = (long)blockIdx.x * 256 + threadIdx.x;
    if (i >= n4) return;
    float4 v = ((const float4*)in)[i];
    v.x = tf32r(v.x); v.y = tf32r(v.y); v.z = tf32r(v.z); v.w = tf32r(v.w);
    ((float4*)out)[i] = v;
}

// ---------------- LayerNorm (optional second tf32 output) ----------------
__global__ void ln_kernel(const float* __restrict__ in, const float* __restrict__ g,
                          const float* __restrict__ b, float* __restrict__ out,
                          float* __restrict__ out_t, int M) {
    int row = blockIdx.x * 8 + (threadIdx.x >> 5);
    int lane = threadIdx.x & 31;
    if (row >= M) return;
    const float* p = in + (size_t)row * HIDC;
    float v[8];
    float s = 0.f;
#pragma unroll
    for (int i = 0; i < 8; i++) { v[i] = p[lane + i * 32]; s += v[i]; }
#pragma unroll
    for (int o = 16; o > 0; o >>= 1) s += __shfl_xor_sync(0xffffffffu, s, o);
    float mean = s * (1.0f / HIDC);
    float vs = 0.f;
#pragma unroll
    for (int i = 0; i < 8; i++) { float d = v[i] - mean; vs += d * d; }
#pragma unroll
    for (int o = 16; o > 0; o >>= 1) vs += __shfl_xor_sync(0xffffffffu, vs, o);
    float rstd = rsqrtf(vs * (1.0f / HIDC) + 1e-5f);
    float* q = out + (size_t)row * HIDC;
    float* qt = out_t ? out_t + (size_t)row * HIDC : nullptr;
#pragma unroll
    for (int i = 0; i < 8; i++) {
        int c = lane + i * 32;
        float val = (v[i] - mean) * rstd * g[c] + b[c];
        q[c] = val;
        if (qt) qt[c] = tf32r(val);
    }
}

// ---------------- init ----------------
__global__ void init_kernel(float* agg, float* rowv, float* smax, float* ssum, int Nn) {
    int t = blockIdx.x * 256 + threadIdx.x;
    if (t < Nn * HIDC) { agg[t] = 0.f; rowv[t] = 0.f; }
    if (t < Nn * NHEAD) { smax[t] = -CLAMP_V; ssum[t] = 0.f; }
}

// ---------------- exp + segment sum ----------------
__global__ void ex_kernel(float* __restrict__ score, const float* __restrict__ smax,
                          float* __restrict__ ssum, const int* __restrict__ dst, int E) {
    int t = blockIdx.x * 256 + threadIdx.x;
    if (t >= E * NHEAD) return;
    int e = t >> 3, h = t & 7;
    int dn = dst[e];
    float ex = expf(score[t] - smax[dn * NHEAD + h]);
    score[t] = ex;
    atomicAdd(&ssum[dn * NHEAD + h], ex);
}

// ---------------- scatter (V rows in QKV, col offset 512, stride 768) ----------------
__global__ void scatter_kernel(const float* __restrict__ exv, const float* __restrict__ ssum,
                               const float* __restrict__ QKV, const float* __restrict__ Oe,
                               float* __restrict__ agg, float* __restrict__ rowv,
                               const int* __restrict__ dst, const int* __restrict__ src, int E) {
    long t = (long)blockIdx.x * 256 + threadIdx.x;
    if (t >= (long)E * 64) return;
    int e = (int)(t >> 6), q = (int)(t & 63);
    int h = q >> 3;
    int dn = dst[e], sn = src[e];
    float sc = exv[e * NHEAD + h] / (ssum[dn * NHEAD + h] + 1e-16f);
    float4 v = *(const float4*)&QKV[(size_t)sn * 768 + 512 + q * 4];
    float4 o = *(const float4*)&Oe[(size_t)e * HIDC + q * 4];
    float* ap = &agg[(size_t)dn * HIDC + q * 4];
    atomicAdd(ap + 0, v.x * sc); atomicAdd(ap + 1, v.y * sc);
    atomicAdd(ap + 2, v.z * sc); atomicAdd(ap + 3, v.w * sc);
    float* rp = &rowv[(size_t)dn * HIDC + q * 4];
    atomicAdd(rp + 0, o.x * sc); atomicAdd(rp + 1, o.y * sc);
    atomicAdd(rp + 2, o.z * sc); atomicAdd(rp + 3, o.w * sc);
}

// ---------------- combine: On = tf32(agg + einsum(rowv, BW)) ----------------
__global__ void combine_kernel(const float* __restrict__ agg, const float* __restrict__ rowv,
                               const float* __restrict__ BW, float* __restrict__ On, int Nn) {
    __shared__ float sBW[32 * 8 * 32];
    __shared__ float srv[HIDC];
    int tid = threadIdx.x;
    for (int i = tid; i < 32 * 8 * 32; i += 256) sBW[i] = BW[i];
    int h = tid >> 5, c = tid & 31;
    for (int r = 0; r < 4; r++) {
        int n = blockIdx.x * 4 + r;
        __syncthreads();
        if (n < Nn) srv[tid] = rowv[(size_t)n * HIDC + tid];
        __syncthreads();
        if (n < Nn) {
            float s = agg[(size_t)n * HIDC + tid];
#pragma unroll
            for (int d = 0; d < 32; d++)
                s += srv[h * 32 + d] * sBW[d * HIDC + h * 32 + c];
            On[(size_t)n * HIDC + tid] = tf32r(s);
        }
    }
}

// ---------------- launch ----------------
extern "C" void kernel_launch(void* const* d_in, const int* in_sizes, int n_in,
                              void* d_out, int out_size) {
    const float* x     = (const float*)d_in[0];
    const float* conn  = (const float*)d_in[1];
    const float* Wq    = (const float*)d_in[2];
    const float* Wk    = (const float*)d_in[3];
    const float* Wv    = (const float*)d_in[4];
    const float* Wew   = (const float*)d_in[5];
    const float* Web   = (const float*)d_in[6];
    const float* beb   = (const float*)d_in[7];
    const float* Weo   = (const float*)d_in[8];
    const float* beo   = (const float*)d_in[9];
    const float* Aw    = (const float*)d_in[10];
    const float* BW    = (const float*)d_in[11];
    const float* Wo_h  = (const float*)d_in[12];
    const float* bo_h  = (const float*)d_in[13];
    const float* Wo_e  = (const float*)d_in[14];
    const float* bo_e  = (const float*)d_in[15];
    const float* ln1hg = (const float*)d_in[16];
    const float* ln1hb = (const float*)d_in[17];
    const float* ln1eg = (const float*)d_in[18];
    const float* ln1eb = (const float*)d_in[19];
    const float* W1    = (const float*)d_in[20];
    const float* b1    = (const float*)d_in[21];
    const float* W2    = (const float*)d_in[22];
    const float* b2    = (const float*)d_in[23];
    const float* ln2hg = (const float*)d_in[24];
    const float* ln2hb = (const float*)d_in[25];
    const int*   ei    = (const int*)d_in[26];

    int Nn = in_sizes[0] / HIDC;
    int Ee = in_sizes[26] / 2;
    const int* dst = ei;
    const int* src = ei + Ee;

    float* S = nullptr;
    cudaGetSymbolAddress((void**)&S, g_scratch);

    float* QKV  = S + O_QKV;
    float* cA   = S + O_CA;
    float* Oe   = S + O_OE;
    float* scb  = S + O_SCB;
    float* smax = S + O_SMAX;
    float* ssum = S + O_SSUM;
    float* agg  = S + O_AGG;
    float* rowv = S + O_ROWV;
    float* On   = S + O_ON;
    float* h1   = S + O_H1;
    float* hln  = S + O_HLN;
    float* hlnt = S + O_HLNT;
    float* ffn  = S + O_FFN;
    float* h2   = S + O_H2;
    float* xt   = S + O_XT;
    float* ct   = S + O_CT;

    float* outH = (float*)d_out;
    float* outE = outH + (size_t)Nn * HIDC;

    cudaFuncSetAttribute(gemm_tc<0, 0, 0, 256>, cudaFuncAttributeMaxDynamicSharedMemorySize, GEMM_SMEM);
    cudaFuncSetAttribute(gemm_tc<0, 0, 0, 512>, cudaFuncAttributeMaxDynamicSharedMemorySize, GEMM_SMEM);
    cudaFuncSetAttribute(gemm_tc<0, 1, 1, 256>, cudaFuncAttributeMaxDynamicSharedMemorySize, GEMM_SMEM);
    cudaFuncSetAttribute(gemm_tc<1, 1, 0, 256>, cudaFuncAttributeMaxDynamicSharedMemorySize, GEMM_SMEM);
    cudaFuncSetAttribute(gemm_tc<2, 0, 0, 256>, cudaFuncAttributeMaxDynamicSharedMemorySize, GEMM_SMEM);

    // prep
    pack_kernel<<<cdiv(786432, 256), 256>>>(Wq, Wk, Wv, Wew, Web, Weo, Wo_h, Wo_e, W1, W2, S);
    cvt_kernel<<<cdiv(Nn * 64, 256), 256>>>(x, xt, (long)Nn * 64);
    cvt_kernel<<<(int)cdiv((long)Ee * 64, 256), 256>>>(conn, ct, (long)Ee * 64);
    init_kernel<<<cdiv(Nn * HIDC, 256), 256>>>(agg, rowv, smax, ssum, Nn);

    // QKV = xt @ Wqkv  [N, 768]
    {
        dim3 g(cdiv(Nn, 128), 6);
        gemm_tc<0, 0, 0, 256><<<g, 256, GEMM_SMEM>>>(xt, S + O_WQKV, nullptr, nullptr, QKV,
                                                     Nn, 768, nullptr, nullptr, nullptr,
                                                     nullptr, nullptr, nullptr);
    }
    // fused: EwEb GEMM + edge message -> cA (tf32)
    {
        dim3 g(cdiv(Ee, 128), 4);
        gemm_tc<2, 0, 0, 256><<<g, 256, GEMM_SMEM>>>(ct, S + O_WEWB, beb, nullptr, cA,
                                                     Ee, 512, dst, src, QKV,
                                                     nullptr, nullptr, nullptr);
    }
    // Oe = cA @ Weo + beo (tf32 out) + fused score/clamp/segment-max
    {
        dim3 g(cdiv(Ee, 128), 2);
        gemm_tc<0, 1, 1, 256><<<g, 256, GEMM_SMEM>>>(cA, S + O_WEO, beo, nullptr, Oe,
                                                     Ee, 256, dst, nullptr, nullptr,
                                                     Aw, scb, smax);
    }

    ex_kernel<<<cdiv(Ee * NHEAD, 256), 256>>>(scb, smax, ssum, dst, Ee);
    scatter_kernel<<<(int)cdiv((long)Ee * 64, 256), 256>>>(scb, ssum, QKV, Oe, agg, rowv, dst, src, Ee);
    combine_kernel<<<cdiv(Nn, 4), 256>>>(agg, rowv, BW, On, Nn);

    // h path
    {
        dim3 g(cdiv(Nn, 128), 2);
        gemm_tc<0, 0, 0, 256><<<g, 256, GEMM_SMEM>>>(On, S + O_WOH, bo_h, x, h1,
                                                     Nn, 256, nullptr, nullptr, nullptr,
                                                     nullptr, nullptr, nullptr);
    }
    ln_kernel<<<cdiv(Nn, 8), 256>>>(h1, ln1hg, ln1hb, hln, hlnt, Nn);

    // e path
    {
        dim3 g(cdiv(Ee, 128), 2);
        gemm_tc<0, 0, 0, 256><<<g, 256, GEMM_SMEM>>>(Oe, S + O_WOE, bo_e, conn, cA,
                                                     Ee, 256, nullptr, nullptr, nullptr,
                                                     nullptr, nullptr, nullptr);
    }
    ln_kernel<<<cdiv(Ee, 8), 256>>>(cA, ln1eg, ln1eb, outE, nullptr, Ee);

    // FFN
    {
        dim3 g(cdiv(Nn, 128), 4);
        gemm_tc<1, 1, 0, 256><<<g, 256, GEMM_SMEM>>>(hlnt, S + O_W1, b1, nullptr, ffn,
                                                     Nn, 512, nullptr, nullptr, nullptr,
                                                     nullptr, nullptr, nullptr);
    }
    {
        dim3 g(cdiv(Nn, 128), 2);
        gemm_tc<0, 0, 0, 512><<<g, 256, GEMM_SMEM>>>(ffn, S + O_W2, b2, hln, h2,
                                                     Nn, 256, nullptr, nullptr, nullptr,
                                                     nullptr, nullptr, nullptr);
    }
    ln_kernel<<<cdiv(Nn, 8), 256>>>(h2, ln2hg, ln2hb, outH, nullptr, Nn);
}

// round 8
// speedup vs baseline: 1.3436x; 1.3436x over previous
#include <cuda_runtime.h>
#include <cuda_fp16.h>
#include <math.h>
#include <stdint.h>

#define HIDC 256
#define NHEAD 8
#define CLAMP_V 5.0f

static const int NMAXC = 50000;
static const int EMAXC = 320000;

// ---------------- scratch layout (slots sized in floats; half arrays reuse) ----
#define O_QKV  ((size_t)0)                          // N*768 (half)
#define O_CA   (O_QKV  + (size_t)NMAXC*768)         // E*256 (half)
#define O_OE   (O_CA   + (size_t)EMAXC*256)         // E*256 (half)
#define O_SCB  (O_OE   + (size_t)EMAXC*256)         // E*8  (f32)
#define O_SMAX (O_SCB  + (size_t)EMAXC*8)           // N*8  (f32)
#define O_SSUM (O_SMAX + (size_t)NMAXC*8)           // N*8  (f32)
#define O_AGG  (O_SSUM + (size_t)NMAXC*8)           // N*256 (f32)
#define O_ROWV (O_AGG  + (size_t)NMAXC*256)         // N*256 (f32)
#define O_ON   (O_ROWV + (size_t)NMAXC*256)         // N*256 (half)
#define O_H1   (O_ON   + (size_t)NMAXC*256)         // N*256 (f32)
#define O_HLN  (O_H1   + (size_t)NMAXC*256)         // N*256 (f32)
#define O_HLNT (O_HLN  + (size_t)NMAXC*256)         // N*256 (half)
#define O_FFN  (O_HLNT + (size_t)NMAXC*256)         // N*512 (half)
#define O_H2   (O_FFN  + (size_t)NMAXC*512)         // N*256 (f32)
#define O_XT   (O_H2   + (size_t)NMAXC*256)         // N*256 (half)
#define O_CT   (O_XT   + (size_t)NMAXC*256)         // E*256 (half)
#define O_WQKV (O_CT   + (size_t)EMAXC*256)         // 768*256 (half, [N][K])
#define O_WEWB (O_WQKV + (size_t)768*256)           // 512*256 (half)
#define O_WEO  (O_WEWB + (size_t)512*256)           // 256*256 (half)
#define O_WOH  (O_WEO  + (size_t)256*256)           // 256*256 (half)
#define O_WOE  (O_WOH  + (size_t)256*256)           // 256*256 (half)
#define O_W1   (O_WOE  + (size_t)256*256)           // 512*256 (half)
#define O_W2   (O_W1   + (size_t)512*256)           // 256*512 (half)
#define O_TOTAL (O_W2  + (size_t)256*512)

__device__ float g_scratch[O_TOTAL];

static inline int cdiv(int a, int b) { return (a + b - 1) / b; }

// ---------------- helpers ----------------
__device__ __forceinline__ void mma_f16(float c[4], const uint32_t a[4], const uint32_t b[2]) {
    asm volatile(
        "mma.sync.aligned.m16n8k16.row.col.f32.f16.f16.f32 "
        "{%0,%1,%2,%3}, {%4,%5,%6,%7}, {%8,%9}, {%0,%1,%2,%3};"
        : "+f"(c[0]), "+f"(c[1]), "+f"(c[2]), "+f"(c[3])
        : "r"(a[0]), "r"(a[1]), "r"(a[2]), "r"(a[3]), "r"(b[0]), "r"(b[1]));
}

__device__ __forceinline__ void ldsm4(uint32_t& r0, uint32_t& r1, uint32_t& r2, uint32_t& r3,
                                      uint32_t addr) {
    asm volatile("ldmatrix.sync.aligned.m8n8.x4.shared.b16 {%0,%1,%2,%3}, [%4];"
                 : "=r"(r0), "=r"(r1), "=r"(r2), "=r"(r3) : "r"(addr));
}

__device__ __forceinline__ void cp16(uint32_t saddr, const void* g, bool pred) {
    int sz = pred ? 16 : 0;
    asm volatile("cp.async.cg.shared.global [%0], [%1], 16, %2;\n"
                 :: "r"(saddr), "l"(g), "r"(sz));
}
#define CP_COMMIT() asm volatile("cp.async.commit_group;\n" ::)
#define CP_WAIT(n)  asm volatile("cp.async.wait_group %0;\n" :: "n"(n))

__device__ __forceinline__ void atomicMaxF(float* addr, float val) {
    int* ai = (int*)addr;
    int old = *ai;
    while (__int_as_float(old) < val) {
        int assumed = old;
        old = atomicCAS(ai, assumed, __float_as_int(val));
        if (old == assumed) break;
    }
}

// ---------------- fp16 tensor-core GEMM ----------------
// A row-major [M][KVAL] half; B = weights [Ntot][KVAL] half (K-major).
// BM=128, BN=128, BK=64, 256 thr = 8 warps (4m x 2n), warp tile 32x64.
// 2-stage cp.async double buffer. Fragments via ldmatrix.x4 (b16).
// ACT: 0 normal (bias?+resid? fp32), 1 bias+relu, 2 fused edge message
// OUTH: store half. SCORE: fused attention score (Oe GEMM, implies half out).
#define SAH 72                    // smem row stride in halves (144B)
#define TILEH (128 * SAH)         // halves per tile
#define TILEB (TILEH * 2)         // bytes per tile (18432)
#define G16_SMEM (4 * TILEB)      // 2 A + 2 B tiles = 73728 B

template <int ACT, int OUTH, int SCORE, int KVAL>
__global__ __launch_bounds__(256, 2)
void gemm_f16(const __half* __restrict__ A, const __half* __restrict__ B,
              const float* __restrict__ bias, const float* __restrict__ resid,
              void* __restrict__ Cv, int M, int Ncol,
              const int* __restrict__ dst, const int* __restrict__ src,
              const __half* __restrict__ QKV, const float* __restrict__ Aw,
              float* __restrict__ scb, float* __restrict__ smax) {
    extern __shared__ __half smh[];
    constexpr int KT = KVAL / 64;

    const int tid = threadIdx.x;
    const int warp = tid >> 5;
    const int lane = tid & 31;
    const int g = lane >> 2;
    const int t = lane & 3;
    const int warp_m = warp & 3;
    const int warp_n = warp >> 2;
    const int m0 = blockIdx.x * 128;
    const int n0 = blockIdx.y * 128;

    const uint32_t sbase = (uint32_t)__cvta_generic_to_shared(smh);
    const uint32_t bbase = sbase + 2 * TILEB;

    // staging: 1024 x 16B per tile; v = tid + i*256 : row = v>>3, seg = v&7
    const int srow = tid >> 3;
    const int sseg = tid & 7;
    const bool apred[4] = { m0 + srow + 0 * 32 < M, m0 + srow + 1 * 32 < M,
                            m0 + srow + 2 * 32 < M, m0 + srow + 3 * 32 < M };
    const __half* Aptr = A + (size_t)(m0 + srow) * KVAL + sseg * 8;
    const __half* Bptr = B + (size_t)(n0 + srow) * KVAL + sseg * 8;

    // ldmatrix lane addressing: row = base + (lane&15), k-half = (lane>>4)*8
    const int lm_row = lane & 15;
    const int lm_k   = (lane >> 4) << 3;

    float acc[2][8][4];
#pragma unroll
    for (int i = 0; i < 2; i++)
#pragma unroll
        for (int j = 0; j < 8; j++)
#pragma unroll
            for (int q = 0; q < 4; q++) acc[i][j][q] = 0.0f;

    // prologue: stage tile 0 into buffer 0
#pragma unroll
    for (int u = 0; u < 4; u++) {
        int r = srow + u * 32;
        cp16(sbase + (r * SAH + sseg * 8) * 2, Aptr + (size_t)(u * 32) * KVAL, apred[u]);
        cp16(bbase + (r * SAH + sseg * 8) * 2, Bptr + (size_t)(u * 32) * KVAL, true);
    }
    CP_COMMIT();

#pragma unroll
    for (int kt = 0; kt < KT; kt++) {
        const int buf = kt & 1;
        if (kt + 1 < KT) {
            const int k0 = (kt + 1) << 6;
            const int nb = buf ^ 1;
#pragma unroll
            for (int u = 0; u < 4; u++) {
                int r = srow + u * 32;
                cp16(sbase + (nb * TILEH + r * SAH + sseg * 8) * 2,
                     Aptr + (size_t)(u * 32) * KVAL + k0, apred[u]);
                cp16(bbase + (nb * TILEH + r * SAH + sseg * 8) * 2,
                     Bptr + (size_t)(u * 32) * KVAL + k0, true);
            }
            CP_COMMIT();
            CP_WAIT(1);
        } else {
            CP_WAIT(0);
        }
        __syncthreads();

        const uint32_t abuf = sbase + buf * TILEB;
        const uint32_t bbuf = bbase + buf * TILEB;

#pragma unroll
        for (int ks = 0; ks < 4; ks++) {
            const int kk = ks * 16;
            uint32_t af[2][4];
#pragma unroll
            for (int i = 0; i < 2; i++) {
                int rm = warp_m * 32 + i * 16;
                ldsm4(af[i][0], af[i][1], af[i][2], af[i][3],
                      abuf + ((rm + lm_row) * SAH + kk + lm_k) * 2);
            }
            uint32_t bf[8][2];
#pragma unroll
            for (int jj = 0; jj < 4; jj++) {
                int nb2 = warp_n * 64 + jj * 16;
                uint32_t r0, r1, r2, r3;
                ldsm4(r0, r1, r2, r3, bbuf + ((nb2 + lm_row) * SAH + kk + lm_k) * 2);
                bf[2 * jj][0] = r0;     bf[2 * jj][1] = r2;
                bf[2 * jj + 1][0] = r1; bf[2 * jj + 1][1] = r3;
            }
#pragma unroll
            for (int i = 0; i < 2; i++)
#pragma unroll
                for (int j = 0; j < 8; j++)
                    mma_f16(acc[i][j], af[i], bf[j]);
        }
        __syncthreads();
    }

    // ---- epilogue ----
    if (ACT == 2) {
        // fused edge message: col pairs (even,odd) = (Ew, Eb), out col = c>>1
        __half* C = (__half*)Cv;
        float bebv[8];
        int cqv[8];
#pragma unroll
        for (int j = 0; j < 8; j++) {
            int cq = (n0 >> 1) + warp_n * 32 + j * 4 + t;
            cqv[j] = cq;
            bebv[j] = bias[cq];
        }
#pragma unroll
        for (int i = 0; i < 2; i++) {
#pragma unroll
            for (int half_ = 0; half_ < 2; half_++) {
                int r = m0 + warp_m * 32 + i * 16 + half_ * 8 + g;
                if (r >= M) continue;
                int dn = dst[r], sn = src[r];
                const __half* qrow = QKV + (size_t)dn * 768;
                const __half* krow = QKV + (size_t)sn * 768 + 256;
#pragma unroll
                for (int j = 0; j < 8; j++) {
                    float ew = acc[i][j][half_ * 2 + 0];
                    float eb = acc[i][j][half_ * 2 + 1] + bebv[j];
                    float aqk = __half2float(qrow[cqv[j]]) + __half2float(krow[cqv[j]]);
                    float c1 = aqk * ew;
                    float c2 = copysignf(sqrtf(fabsf(c1)), c1);
                    C[(size_t)r * 256 + cqv[j]] = __float2half(fmaxf(c2 + eb, 0.f));
                }
            }
        }
    } else if (SCORE) {
        // Oe epilogue (half out) + fused attention score (2 heads per warp)
        __half* C = (__half*)Cv;
        const int h0 = (n0 + warp_n * 64) >> 5;
        float aw0[8], aw1[8];
#pragma unroll
        for (int j4 = 0; j4 < 4; j4++) {
            int d = j4 * 8 + 2 * t;
            aw0[2 * j4]     = __ldg(&Aw[d * 8 + h0]);
            aw0[2 * j4 + 1] = __ldg(&Aw[(d + 1) * 8 + h0]);
            aw1[2 * j4]     = __ldg(&Aw[d * 8 + h0 + 1]);
            aw1[2 * j4 + 1] = __ldg(&Aw[(d + 1) * 8 + h0 + 1]);
        }
        float2 bvj[8];
#pragma unroll
        for (int j = 0; j < 8; j++)
            bvj[j] = *(const float2*)&bias[n0 + warp_n * 64 + j * 8 + 2 * t];
#pragma unroll
        for (int i = 0; i < 2; i++) {
#pragma unroll
            for (int half_ = 0; half_ < 2; half_++) {
                int r = m0 + warp_m * 32 + i * 16 + half_ * 8 + g;
                float s0 = 0.f, s1 = 0.f;
                if (r < M) {
#pragma unroll
                    for (int j = 0; j < 8; j++) {
                        float ox = acc[i][j][half_ * 2 + 0] + bvj[j].x;
                        float oy = acc[i][j][half_ * 2 + 1] + bvj[j].y;
                        __half2 h2v = __float22half2_rn(make_float2(ox, oy));
                        ox = __half2float(__low2half(h2v));
                        oy = __half2float(__high2half(h2v));
                        int c = n0 + warp_n * 64 + j * 8 + 2 * t;
                        *(__half2*)&C[(size_t)r * Ncol + c] = h2v;
                        if (j < 4) {
                            s0 += ox * aw0[2 * j] + oy * aw0[2 * j + 1];
                        } else {
                            s1 += ox * aw1[2 * (j - 4)] + oy * aw1[2 * (j - 4) + 1];
                        }
                    }
                }
                s0 += __shfl_xor_sync(0xffffffffu, s0, 1);
                s0 += __shfl_xor_sync(0xffffffffu, s0, 2);
                s1 += __shfl_xor_sync(0xffffffffu, s1, 1);
                s1 += __shfl_xor_sync(0xffffffffu, s1, 2);
                if (r < M && t == 0) {
                    s0 = fminf(fmaxf(s0, -CLAMP_V), CLAMP_V);
                    s1 = fminf(fmaxf(s1, -CLAMP_V), CLAMP_V);
                    scb[(size_t)r * 8 + h0] = s0;
                    scb[(size_t)r * 8 + h0 + 1] = s1;
                    int dn = dst[r];
                    atomicMaxF(&smax[dn * 8 + h0], s0);
                    atomicMaxF(&smax[dn * 8 + h0 + 1], s1);
                }
            }
        }
    } else {
#pragma unroll
        for (int j = 0; j < 8; j++) {
            int c = n0 + warp_n * 64 + j * 8 + 2 * t;
            float2 bv = make_float2(0.f, 0.f);
            if (bias) bv = *(const float2*)&bias[c];
#pragma unroll
            for (int i = 0; i < 2; i++) {
                int rbase = m0 + warp_m * 32 + i * 16 + g;
#pragma unroll
                for (int half_ = 0; half_ < 2; half_++) {
                    int r = rbase + half_ * 8;
                    if (r >= M) continue;
                    float ox = acc[i][j][half_ * 2 + 0] + bv.x;
                    float oy = acc[i][j][half_ * 2 + 1] + bv.y;
                    if (resid) {
                        float2 rv = *(const float2*)&resid[(size_t)r * Ncol + c];
                        ox += rv.x; oy += rv.y;
                    }
                    if (ACT == 1) { ox = fmaxf(ox, 0.f); oy = fmaxf(oy, 0.f); }
                    if (OUTH) {
                        *(__half2*)&((__half*)Cv)[(size_t)r * Ncol + c] =
                            __float22half2_rn(make_float2(ox, oy));
                    } else {
                        *(float2*)&((float*)Cv)[(size_t)r * Ncol + c] = make_float2(ox, oy);
                    }
                }
            }
        }
    }
}

// ---------------- weight pack: TRANSPOSED [N][K], half ----------------
__global__ void pack_kernel(const float* Wq, const float* Wk, const float* Wv,
                            const float* Wew, const float* Web, const float* Weo,
                            const float* Wo_h, const float* Wo_e,
                            const float* W1, const float* W2, float* S) {
    int i = blockIdx.x * 256 + threadIdx.x;
    if (i < 196608) {  // wqkvT [768][256]
        int n = i >> 8, k = i & 255;
        float v = (n < 256) ? Wq[k * 256 + n]
                : (n < 512) ? Wk[k * 256 + n - 256]
                            : Wv[k * 256 + n - 512];
        ((__half*)(S + O_WQKV))[i] = __float2half(v);
    }
    int i2 = i - 196608;
    if (i2 >= 0 && i2 < 131072) {  // wewbT [512][256], rows interleaved Ew/Eb
        int n = i2 >> 8, k = i2 & 255, c = n >> 1;
        float v = (n & 1) ? Web[k * 256 + c] : Wew[k * 256 + c];
        ((__half*)(S + O_WEWB))[i2] = __float2half(v);
    }
    int i3 = i - 327680;
    if (i3 >= 0 && i3 < 65536) {
        int n = i3 >> 8, k = i3 & 255;
        ((__half*)(S + O_WEO))[i3] = __float2half(Weo[k * 256 + n]);
    }
    int i4 = i - 393216;
    if (i4 >= 0 && i4 < 65536) {
        int n = i4 >> 8, k = i4 & 255;
        ((__half*)(S + O_WOH))[i4] = __float2half(Wo_h[k * 256 + n]);
    }
    int i5 = i - 458752;
    if (i5 >= 0 && i5 < 65536) {
        int n = i5 >> 8, k = i5 & 255;
        ((__half*)(S + O_WOE))[i5] = __float2half(Wo_e[k * 256 + n]);
    }
    int i6 = i - 524288;
    if (i6 >= 0 && i6 < 131072) {  // w1T [512][256]
        int n = i6 >> 8, k = i6 & 255;
        ((__half*)(S + O_W1))[i6] = __float2half(W1[k * 512 + n]);
    }
    int i7 = i - 655360;
    if (i7 >= 0 && i7 < 131072) {  // w2T [256][512]
        int n = i7 >> 9, k = i7 & 511;
        ((__half*)(S + O_W2))[i7] = __float2half(W2[k * 256 + n]);
    }
}

// ---------------- fp32 -> half copy (float4 -> half2 x2) ----------------
__global__ void cvt_kernel(const float* __restrict__ in, __half* __restrict__ out, long n4) {
    long i = (long)blockIdx.x * 256 + threadIdx.x;
    if (i >= n4) return;
    float4 v = ((const float4*)in)[i];
    __half2* o = (__half2*)out + 2 * i;
    o[0] = __float22half2_rn(make_float2(v.x, v.y));
    o[1] = __float22half2_rn(make_float2(v.z, v.w));
}

// ---------------- LayerNorm (optional half second output) ----------------
__global__ void ln_kernel(const float* __restrict__ in, const float* __restrict__ g,
                          const float* __restrict__ b, float* __restrict__ out,
                          __half* __restrict__ out_t, int M) {
    int row = blockIdx.x * 8 + (threadIdx.x >> 5);
    int lane = threadIdx.x & 31;
    if (row >= M) return;
    const float* p = in + (size_t)row * HIDC;
    float v[8];
    float s = 0.f;
#pragma unroll
    for (int i = 0; i < 8; i++) { v[i] = p[lane + i * 32]; s += v[i]; }
#pragma unroll
    for (int o = 16; o > 0; o >>= 1) s += __shfl_xor_sync(0xffffffffu, s, o);
    float mean = s * (1.0f / HIDC);
    float vs = 0.f;
#pragma unroll
    for (int i = 0; i < 8; i++) { float d = v[i] - mean; vs += d * d; }
#pragma unroll
    for (int o = 16; o > 0; o >>= 1) vs += __shfl_xor_sync(0xffffffffu, vs, o);
    float rstd = rsqrtf(vs * (1.0f / HIDC) + 1e-5f);
    float* q = out + (size_t)row * HIDC;
    __half* qt = out_t ? out_t + (size_t)row * HIDC : nullptr;
#pragma unroll
    for (int i = 0; i < 8; i++) {
        int c = lane + i * 32;
        float val = (v[i] - mean) * rstd * g[c] + b[c];
        q[c] = val;
        if (qt) qt[c] = __float2half(val);
    }
}

// ---------------- init ----------------
__global__ void init_kernel(float* agg, float* rowv, float* smax, float* ssum, int Nn) {
    int t = blockIdx.x * 256 + threadIdx.x;
    if (t < Nn * HIDC) { agg[t] = 0.f; rowv[t] = 0.f; }
    if (t < Nn * NHEAD) { smax[t] = -CLAMP_V; ssum[t] = 0.f; }
}

// ---------------- exp + segment sum ----------------
__global__ void ex_kernel(float* __restrict__ score, const float* __restrict__ smax,
                          float* __restrict__ ssum, const int* __restrict__ dst, int E) {
    int t = blockIdx.x * 256 + threadIdx.x;
    if (t >= E * NHEAD) return;
    int e = t >> 3, h = t & 7;
    int dn = dst[e];
    float ex = expf(score[t] - smax[dn * NHEAD + h]);
    score[t] = ex;
    atomicAdd(&ssum[dn * NHEAD + h], ex);
}

// ---------------- scatter (V in QKV half, col off 512, stride 768) ----------------
__global__ void scatter_kernel(const float* __restrict__ exv, const float* __restrict__ ssum,
                               const __half* __restrict__ QKV, const __half* __restrict__ Oe,
                               float* __restrict__ agg, float* __restrict__ rowv,
                               const int* __restrict__ dst, const int* __restrict__ src, int E) {
    long t = (long)blockIdx.x * 256 + threadIdx.x;
    if (t >= (long)E * 64) return;
    int e = (int)(t >> 6), q = (int)(t & 63);
    int h = q >> 3;
    int dn = dst[e], sn = src[e];
    float sc = exv[e * NHEAD + h] / (ssum[dn * NHEAD + h] + 1e-16f);
    const __half2* vp = (const __half2*)(QKV + (size_t)sn * 768 + 512 + q * 4);
    const __half2* op = (const __half2*)(Oe + (size_t)e * HIDC + q * 4);
    float2 v0 = __half22float2(vp[0]), v1 = __half22float2(vp[1]);
    float2 o0 = __half22float2(op[0]), o1 = __half22float2(op[1]);
    float* ap = &agg[(size_t)dn * HIDC + q * 4];
    atomicAdd(ap + 0, v0.x * sc); atomicAdd(ap + 1, v0.y * sc);
    atomicAdd(ap + 2, v1.x * sc); atomicAdd(ap + 3, v1.y * sc);
    float* rp = &rowv[(size_t)dn * HIDC + q * 4];
    atomicAdd(rp + 0, o0.x * sc); atomicAdd(rp + 1, o0.y * sc);
    atomicAdd(rp + 2, o1.x * sc); atomicAdd(rp + 3, o1.y * sc);
}

// ---------------- combine: On = half(agg + einsum(rowv, BW)) ----------------
__global__ void combine_kernel(const float* __restrict__ agg, const float* __restrict__ rowv,
                               const float* __restrict__ BW, __half* __restrict__ On, int Nn) {
    __shared__ float sBW[32 * 8 * 32];
    __shared__ float srv[HIDC];
    int tid = threadIdx.x;
    for (int i = tid; i < 32 * 8 * 32; i += 256) sBW[i] = BW[i];
    int h = tid >> 5, c = tid & 31;
    for (int r = 0; r < 4; r++) {
        int n = blockIdx.x * 4 + r;
        __syncthreads();
        if (n < Nn) srv[tid] = rowv[(size_t)n * HIDC + tid];
        __syncthreads();
        if (n < Nn) {
            float s = agg[(size_t)n * HIDC + tid];
#pragma unroll
            for (int d = 0; d < 32; d++)
                s += srv[h * 32 + d] * sBW[d * HIDC + h * 32 + c];
            On[(size_t)n * HIDC + tid] = __float2half(s);
        }
    }
}

// ---------------- launch ----------------
extern "C" void kernel_launch(void* const* d_in, const int* in_sizes, int n_in,
                              void* d_out, int out_size) {
    const float* x     = (const float*)d_in[0];
    const float* conn  = (const float*)d_in[1];
    const float* Wq    = (const float*)d_in[2];
    const float* Wk    = (const float*)d_in[3];
    const float* Wv    = (const float*)d_in[4];
    const float* Wew   = (const float*)d_in[5];
    const float* Web   = (const float*)d_in[6];
    const float* beb   = (const float*)d_in[7];
    const float* Weo   = (const float*)d_in[8];
    const float* beo   = (const float*)d_in[9];
    const float* Aw    = (const float*)d_in[10];
    const float* BW    = (const float*)d_in[11];
    const float* Wo_h  = (const float*)d_in[12];
    const float* bo_h  = (const float*)d_in[13];
    const float* Wo_e  = (const float*)d_in[14];
    const float* bo_e  = (const float*)d_in[15];
    const float* ln1hg = (const float*)d_in[16];
    const float* ln1hb = (const float*)d_in[17];
    const float* ln1eg = (const float*)d_in[18];
    const float* ln1eb = (const float*)d_in[19];
    const float* W1    = (const float*)d_in[20];
    const float* b1    = (const float*)d_in[21];
    const float* W2    = (const float*)d_in[22];
    const float* b2    = (const float*)d_in[23];
    const float* ln2hg = (const float*)d_in[24];
    const float* ln2hb = (const float*)d_in[25];
    const int*   ei    = (const int*)d_in[26];

    int Nn = in_sizes[0] / HIDC;
    int Ee = in_sizes[26] / 2;
    const int* dst = ei;
    const int* src = ei + Ee;

    float* S = nullptr;
    cudaGetSymbolAddress((void**)&S, g_scratch);

    __half* QKV  = (__half*)(S + O_QKV);
    __half* cA   = (__half*)(S + O_CA);
    __half* Oe   = (__half*)(S + O_OE);
    float*  scb  = S + O_SCB;
    float*  smax = S + O_SMAX;
    float*  ssum = S + O_SSUM;
    float*  agg  = S + O_AGG;
    float*  rowv = S + O_ROWV;
    __half* On   = (__half*)(S + O_ON);
    float*  h1   = S + O_H1;
    float*  hln  = S + O_HLN;
    __half* hlnt = (__half*)(S + O_HLNT);
    __half* ffn  = (__half*)(S + O_FFN);
    float*  h2   = S + O_H2;
    __half* xt   = (__half*)(S + O_XT);
    __half* ct   = (__half*)(S + O_CT);
    __half* wqkv = (__half*)(S + O_WQKV);
    __half* wewb = (__half*)(S + O_WEWB);
    __half* weo  = (__half*)(S + O_WEO);
    __half* woh  = (__half*)(S + O_WOH);
    __half* woe  = (__half*)(S + O_WOE);
    __half* w1   = (__half*)(S + O_W1);
    __half* w2   = (__half*)(S + O_W2);

    float* outH = (float*)d_out;
    float* outE = outH + (size_t)Nn * HIDC;

    cudaFuncSetAttribute(gemm_f16<0, 1, 0, 256>, cudaFuncAttributeMaxDynamicSharedMemorySize, G16_SMEM);
    cudaFuncSetAttribute(gemm_f16<0, 0, 0, 256>, cudaFuncAttributeMaxDynamicSharedMemorySize, G16_SMEM);
    cudaFuncSetAttribute(gemm_f16<0, 1, 1, 256>, cudaFuncAttributeMaxDynamicSharedMemorySize, G16_SMEM);
    cudaFuncSetAttribute(gemm_f16<1, 1, 0, 256>, cudaFuncAttributeMaxDynamicSharedMemorySize, G16_SMEM);
    cudaFuncSetAttribute(gemm_f16<2, 0, 0, 256>, cudaFuncAttributeMaxDynamicSharedMemorySize, G16_SMEM);
    cudaFuncSetAttribute(gemm_f16<0, 0, 0, 512>, cudaFuncAttributeMaxDynamicSharedMemorySize, G16_SMEM);

    // prep
    pack_kernel<<<cdiv(786432, 256), 256>>>(Wq, Wk, Wv, Wew, Web, Weo, Wo_h, Wo_e, W1, W2, S);
    cvt_kernel<<<cdiv(Nn * 64, 256), 256>>>(x, xt, (long)Nn * 64);
    cvt_kernel<<<(int)cdiv((long)Ee * 64, 256), 256>>>(conn, ct, (long)Ee * 64);
    init_kernel<<<cdiv(Nn * HIDC, 256), 256>>>(agg, rowv, smax, ssum, Nn);

    int gmN = cdiv(Nn, 128);
    int gmE = cdiv(Ee, 128);

    // QKV = xt @ WqkvT  [N, 768] (half out)
    gemm_f16<0, 1, 0, 256><<<dim3(gmN, 6), 256, G16_SMEM>>>(
        xt, wqkv, nullptr, nullptr, QKV, Nn, 768,
        nullptr, nullptr, nullptr, nullptr, nullptr, nullptr);
    // fused EwEb GEMM + edge message -> cA (half)
    gemm_f16<2, 0, 0, 256><<<dim3(gmE, 4), 256, G16_SMEM>>>(
        ct, wewb, beb, nullptr, cA, Ee, 512,
        dst, src, QKV, nullptr, nullptr, nullptr);
    // Oe = cA @ WeoT + beo (half) + fused score/clamp/segment-max
    gemm_f16<0, 1, 1, 256><<<dim3(gmE, 2), 256, G16_SMEM>>>(
        cA, weo, beo, nullptr, Oe, Ee, 256,
        dst, nullptr, nullptr, Aw, scb, smax);

    ex_kernel<<<cdiv(Ee * NHEAD, 256), 256>>>(scb, smax, ssum, dst, Ee);
    scatter_kernel<<<(int)cdiv((long)Ee * 64, 256), 256>>>(scb, ssum, QKV, Oe, agg, rowv, dst, src, Ee);
    combine_kernel<<<cdiv(Nn, 4), 256>>>(agg, rowv, BW, On, Nn);

    // h path: h1 = x + On @ Wo_h + bo_h (fp32 out)
    gemm_f16<0, 0, 0, 256><<<dim3(gmN, 2), 256, G16_SMEM>>>(
        On, woh, bo_h, x, h1, Nn, 256,
        nullptr, nullptr, nullptr, nullptr, nullptr, nullptr);
    ln_kernel<<<cdiv(Nn, 8), 256>>>(h1, ln1hg, ln1hb, hln, hlnt, Nn);

    // e path: outE = LN1e(conn + Oe @ Wo_e + bo_e) ; temp reuses h-free slot O_CA? (cA consumed)
    gemm_f16<0, 0, 0, 256><<<dim3(gmE, 2), 256, G16_SMEM>>>(
        Oe, woe, bo_e, conn, (float*)(S + O_CA), Ee, 256,
        nullptr, nullptr, nullptr, nullptr, nullptr, nullptr);
    ln_kernel<<<cdiv(Ee, 8), 256>>>((float*)(S + O_CA), ln1eg, ln1eb, outE, nullptr, Ee);

    // FFN: ffn = relu(hlnt @ W1 + b1) (half)
    gemm_f16<1, 1, 0, 256><<<dim3(gmN, 4), 256, G16_SMEM>>>(
        hlnt, w1, b1, nullptr, ffn, Nn, 512,
        nullptr, nullptr, nullptr, nullptr, nullptr, nullptr);
    // h2 = hln + ffn @ W2 + b2 (K=512, fp32 out)
    gemm_f16<0, 0, 0, 512><<<dim3(gmN, 2), 256, G16_SMEM>>>(
        ffn, w2, b2, hln, h2, Nn, 256,
        nullptr, nullptr, nullptr, nullptr, nullptr, nullptr);
    ln_kernel<<<cdiv(Nn, 8), 256>>>(h2, ln2hg, ln2hb, outH, nullptr, Nn);
}

// round 9
// speedup vs baseline: 1.3694x; 1.0192x over previous
#include <cuda_runtime.h>
#include <cuda_fp16.h>
#include <math.h>
#include <stdint.h>

#define HIDC 256
#define NHEAD 8
#define CLAMP_V 5.0f

static const int NMAXC = 50000;
static const int EMAXC = 320000;

// ---------------- scratch layout (slots sized in floats; half arrays reuse) ----
#define O_QKV  ((size_t)0)                          // N*768 (half)
#define O_CA   (O_QKV  + (size_t)NMAXC*768)         // E*256 (half)
#define O_OE   (O_CA   + (size_t)EMAXC*256)         // E*256 (half)
#define O_SCB  (O_OE   + (size_t)EMAXC*256)         // E*8  (f32)
#define O_SMAX (O_SCB  + (size_t)EMAXC*8)           // N*8  (f32)
#define O_SSUM (O_SMAX + (size_t)NMAXC*8)           // N*8  (f32)
#define O_AGG  (O_SSUM + (size_t)NMAXC*8)           // N*256 (f32)
#define O_ROWV (O_AGG  + (size_t)NMAXC*256)         // N*256 (f32)
#define O_ON   (O_ROWV + (size_t)NMAXC*256)         // N*256 (half)
#define O_HLN  (O_ON   + (size_t)NMAXC*256)         // N*256 (f32)
#define O_HLNT (O_HLN  + (size_t)NMAXC*256)         // N*256 (half)
#define O_FFN  (O_HLNT + (size_t)NMAXC*256)         // N*512 (half)
#define O_XT   (O_FFN  + (size_t)NMAXC*512)         // N*256 (half)
#define O_CT   (O_XT   + (size_t)NMAXC*256)         // E*256 (half)
#define O_WQKV (O_CT   + (size_t)EMAXC*256)         // 768*256 (half, [N][K])
#define O_WEWB (O_WQKV + (size_t)768*256)           // 512*256 (half)
#define O_WEO  (O_WEWB + (size_t)512*256)           // 256*256 (half)
#define O_WOH  (O_WEO  + (size_t)256*256)           // 256*256 (half)
#define O_WOE  (O_WOH  + (size_t)256*256)           // 256*256 (half)
#define O_W1   (O_WOE  + (size_t)256*256)           // 512*256 (half)
#define O_W2   (O_W1   + (size_t)512*256)           // 256*512 (half)
#define O_TOTAL (O_W2  + (size_t)256*512)

__device__ float g_scratch[O_TOTAL];

static inline int cdiv(int a, int b) { return (a + b - 1) / b; }

// ---------------- helpers ----------------
__device__ __forceinline__ void mma_f16(float c[4], const uint32_t a[4], const uint32_t b[2]) {
    asm volatile(
        "mma.sync.aligned.m16n8k16.row.col.f32.f16.f16.f32 "
        "{%0,%1,%2,%3}, {%4,%5,%6,%7}, {%8,%9}, {%0,%1,%2,%3};"
        : "+f"(c[0]), "+f"(c[1]), "+f"(c[2]), "+f"(c[3])
        : "r"(a[0]), "r"(a[1]), "r"(a[2]), "r"(a[3]), "r"(b[0]), "r"(b[1]));
}

__device__ __forceinline__ void ldsm4(uint32_t& r0, uint32_t& r1, uint32_t& r2, uint32_t& r3,
                                      uint32_t addr) {
    asm volatile("ldmatrix.sync.aligned.m8n8.x4.shared.b16 {%0,%1,%2,%3}, [%4];"
                 : "=r"(r0), "=r"(r1), "=r"(r2), "=r"(r3) : "r"(addr));
}

__device__ __forceinline__ void cp16(uint32_t saddr, const void* g, bool pred) {
    int sz = pred ? 16 : 0;
    asm volatile("cp.async.cg.shared.global [%0], [%1], 16, %2;\n"
                 :: "r"(saddr), "l"(g), "r"(sz));
}
#define CP_COMMIT() asm volatile("cp.async.commit_group;\n" ::)
#define CP_WAIT(n)  asm volatile("cp.async.wait_group %0;\n" :: "n"(n))

__device__ __forceinline__ void atomicMaxF(float* addr, float val) {
    int* ai = (int*)addr;
    int old = *ai;
    while (__int_as_float(old) < val) {
        int assumed = old;
        old = atomicCAS(ai, assumed, __float_as_int(val));
        if (old == assumed) break;
    }
}

// ---------------- fp16 tensor-core GEMM (BM=128, BN=128) ----------------
// A row-major [M][KVAL] half; B = weights [Ntot][KVAL] half (K-major).
// 256 thr = 8 warps (4m x 2n), warp tile 32x64, BK=64 double buffer.
// ACT: 0 normal (bias?+resid? fp32), 1 bias+relu, 2 fused edge message
// OUTH: store half. SCORE: fused attention score (Oe GEMM, implies half out).
#define SAH 72                    // smem row stride in halves (144B)
#define TILEH (128 * SAH)
#define TILEB (TILEH * 2)
#define G16_SMEM (4 * TILEB)

template <int ACT, int OUTH, int SCORE, int KVAL>
__global__ __launch_bounds__(256, 2)
void gemm_f16(const __half* __restrict__ A, const __half* __restrict__ B,
              const float* __restrict__ bias, const float* __restrict__ resid,
              void* __restrict__ Cv, int M, int Ncol,
              const int* __restrict__ dst, const int* __restrict__ src,
              const __half* __restrict__ QKV, const float* __restrict__ Aw,
              float* __restrict__ scb, float* __restrict__ smax) {
    extern __shared__ __half smh[];
    constexpr int KT = KVAL / 64;

    const int tid = threadIdx.x;
    const int warp = tid >> 5;
    const int lane = tid & 31;
    const int g = lane >> 2;
    const int t = lane & 3;
    const int warp_m = warp & 3;
    const int warp_n = warp >> 2;
    const int m0 = blockIdx.x * 128;
    const int n0 = blockIdx.y * 128;

    const uint32_t sbase = (uint32_t)__cvta_generic_to_shared(smh);
    const uint32_t bbase = sbase + 2 * TILEB;

    const int srow = tid >> 3;
    const int sseg = tid & 7;
    const bool apred[4] = { m0 + srow + 0 * 32 < M, m0 + srow + 1 * 32 < M,
                            m0 + srow + 2 * 32 < M, m0 + srow + 3 * 32 < M };
    const __half* Aptr = A + (size_t)(m0 + srow) * KVAL + sseg * 8;
    const __half* Bptr = B + (size_t)(n0 + srow) * KVAL + sseg * 8;

    const int lm_row = lane & 15;
    const int lm_k   = (lane >> 4) << 3;

    float acc[2][8][4];
#pragma unroll
    for (int i = 0; i < 2; i++)
#pragma unroll
        for (int j = 0; j < 8; j++)
#pragma unroll
            for (int q = 0; q < 4; q++) acc[i][j][q] = 0.0f;

#pragma unroll
    for (int u = 0; u < 4; u++) {
        int r = srow + u * 32;
        cp16(sbase + (r * SAH + sseg * 8) * 2, Aptr + (size_t)(u * 32) * KVAL, apred[u]);
        cp16(bbase + (r * SAH + sseg * 8) * 2, Bptr + (size_t)(u * 32) * KVAL, true);
    }
    CP_COMMIT();

#pragma unroll
    for (int kt = 0; kt < KT; kt++) {
        const int buf = kt & 1;
        if (kt + 1 < KT) {
            const int k0 = (kt + 1) << 6;
            const int nb = buf ^ 1;
#pragma unroll
            for (int u = 0; u < 4; u++) {
                int r = srow + u * 32;
                cp16(sbase + (nb * TILEH + r * SAH + sseg * 8) * 2,
                     Aptr + (size_t)(u * 32) * KVAL + k0, apred[u]);
                cp16(bbase + (nb * TILEH + r * SAH + sseg * 8) * 2,
                     Bptr + (size_t)(u * 32) * KVAL + k0, true);
            }
            CP_COMMIT();
            CP_WAIT(1);
        } else {
            CP_WAIT(0);
        }
        __syncthreads();

        const uint32_t abuf = sbase + buf * TILEB;
        const uint32_t bbuf = bbase + buf * TILEB;

#pragma unroll
        for (int ks = 0; ks < 4; ks++) {
            const int kk = ks * 16;
            uint32_t af[2][4];
#pragma unroll
            for (int i = 0; i < 2; i++) {
                int rm = warp_m * 32 + i * 16;
                ldsm4(af[i][0], af[i][1], af[i][2], af[i][3],
                      abuf + ((rm + lm_row) * SAH + kk + lm_k) * 2);
            }
            uint32_t bf[8][2];
#pragma unroll
            for (int jj = 0; jj < 4; jj++) {
                int nb2 = warp_n * 64 + jj * 16;
                uint32_t r0, r1, r2, r3;
                ldsm4(r0, r1, r2, r3, bbuf + ((nb2 + lm_row) * SAH + kk + lm_k) * 2);
                bf[2 * jj][0] = r0;     bf[2 * jj][1] = r2;
                bf[2 * jj + 1][0] = r1; bf[2 * jj + 1][1] = r3;
            }
#pragma unroll
            for (int i = 0; i < 2; i++)
#pragma unroll
                for (int j = 0; j < 8; j++)
                    mma_f16(acc[i][j], af[i], bf[j]);
        }
        __syncthreads();
    }

    // ---- epilogue ----
    if (ACT == 2) {
        __half* C = (__half*)Cv;
        float bebv[8];
        int cqv[8];
#pragma unroll
        for (int j = 0; j < 8; j++) {
            int cq = (n0 >> 1) + warp_n * 32 + j * 4 + t;
            cqv[j] = cq;
            bebv[j] = bias[cq];
        }
#pragma unroll
        for (int i = 0; i < 2; i++) {
#pragma unroll
            for (int half_ = 0; half_ < 2; half_++) {
                int r = m0 + warp_m * 32 + i * 16 + half_ * 8 + g;
                if (r >= M) continue;
                int dn = dst[r], sn = src[r];
                const __half* qrow = QKV + (size_t)dn * 768;
                const __half* krow = QKV + (size_t)sn * 768 + 256;
#pragma unroll
                for (int j = 0; j < 8; j++) {
                    float ew = acc[i][j][half_ * 2 + 0];
                    float eb = acc[i][j][half_ * 2 + 1] + bebv[j];
                    float aqk = __half2float(qrow[cqv[j]]) + __half2float(krow[cqv[j]]);
                    float c1 = aqk * ew;
                    float c2 = copysignf(sqrtf(fabsf(c1)), c1);
                    C[(size_t)r * 256 + cqv[j]] = __float2half(fmaxf(c2 + eb, 0.f));
                }
            }
        }
    } else if (SCORE) {
        __half* C = (__half*)Cv;
        const int h0 = (n0 + warp_n * 64) >> 5;
        float aw0[8], aw1[8];
#pragma unroll
        for (int j4 = 0; j4 < 4; j4++) {
            int d = j4 * 8 + 2 * t;
            aw0[2 * j4]     = __ldg(&Aw[d * 8 + h0]);
            aw0[2 * j4 + 1] = __ldg(&Aw[(d + 1) * 8 + h0]);
            aw1[2 * j4]     = __ldg(&Aw[d * 8 + h0 + 1]);
            aw1[2 * j4 + 1] = __ldg(&Aw[(d + 1) * 8 + h0 + 1]);
        }
        float2 bvj[8];
#pragma unroll
        for (int j = 0; j < 8; j++)
            bvj[j] = *(const float2*)&bias[n0 + warp_n * 64 + j * 8 + 2 * t];
#pragma unroll
        for (int i = 0; i < 2; i++) {
#pragma unroll
            for (int half_ = 0; half_ < 2; half_++) {
                int r = m0 + warp_m * 32 + i * 16 + half_ * 8 + g;
                float s0 = 0.f, s1 = 0.f;
                if (r < M) {
#pragma unroll
                    for (int j = 0; j < 8; j++) {
                        float ox = acc[i][j][half_ * 2 + 0] + bvj[j].x;
                        float oy = acc[i][j][half_ * 2 + 1] + bvj[j].y;
                        __half2 h2v = __float22half2_rn(make_float2(ox, oy));
                        ox = __half2float(__low2half(h2v));
                        oy = __half2float(__high2half(h2v));
                        int c = n0 + warp_n * 64 + j * 8 + 2 * t;
                        *(__half2*)&C[(size_t)r * Ncol + c] = h2v;
                        if (j < 4) {
                            s0 += ox * aw0[2 * j] + oy * aw0[2 * j + 1];
                        } else {
                            s1 += ox * aw1[2 * (j - 4)] + oy * aw1[2 * (j - 4) + 1];
                        }
                    }
                }
                s0 += __shfl_xor_sync(0xffffffffu, s0, 1);
                s0 += __shfl_xor_sync(0xffffffffu, s0, 2);
                s1 += __shfl_xor_sync(0xffffffffu, s1, 1);
                s1 += __shfl_xor_sync(0xffffffffu, s1, 2);
                if (r < M && t == 0) {
                    s0 = fminf(fmaxf(s0, -CLAMP_V), CLAMP_V);
                    s1 = fminf(fmaxf(s1, -CLAMP_V), CLAMP_V);
                    scb[(size_t)r * 8 + h0] = s0;
                    scb[(size_t)r * 8 + h0 + 1] = s1;
                    int dn = dst[r];
                    atomicMaxF(&smax[dn * 8 + h0], s0);
                    atomicMaxF(&smax[dn * 8 + h0 + 1], s1);
                }
            }
        }
    } else {
#pragma unroll
        for (int j = 0; j < 8; j++) {
            int c = n0 + warp_n * 64 + j * 8 + 2 * t;
            float2 bv = make_float2(0.f, 0.f);
            if (bias) bv = *(const float2*)&bias[c];
#pragma unroll
            for (int i = 0; i < 2; i++) {
                int rbase = m0 + warp_m * 32 + i * 16 + g;
#pragma unroll
                for (int half_ = 0; half_ < 2; half_++) {
                    int r = rbase + half_ * 8;
                    if (r >= M) continue;
                    float ox = acc[i][j][half_ * 2 + 0] + bv.x;
                    float oy = acc[i][j][half_ * 2 + 1] + bv.y;
                    if (resid) {
                        float2 rv = *(const float2*)&resid[(size_t)r * Ncol + c];
                        ox += rv.x; oy += rv.y;
                    }
                    if (ACT == 1) { ox = fmaxf(ox, 0.f); oy = fmaxf(oy, 0.f); }
                    if (OUTH) {
                        *(__half2*)&((__half*)Cv)[(size_t)r * Ncol + c] =
                            __float22half2_rn(make_float2(ox, oy));
                    } else {
                        *(float2*)&((float*)Cv)[(size_t)r * Ncol + c] = make_float2(ox, oy);
                    }
                }
            }
        }
    }
}

// ---------------- fp16 GEMM + fused residual + LayerNorm ----------------
// BM=64, BN=256 (full row), 256 thr = 8 warps (2m x 4n), warp tile 32x64.
// out = LN((A@B^T + bias + resid), gamma, beta) -> outF (f32), optional outH (half)
#define LNA_TILEH (64 * SAH)
#define LNA_TILEB (LNA_TILEH * 2)     // 9216
#define LNB_TILEH (256 * SAH)
#define LNB_TILEB (LNB_TILEH * 2)     // 36864
#define GLN_SMEM (2 * LNA_TILEB + 2 * LNB_TILEB)  // 92160

template <int OUT2, int KVAL>
__global__ __launch_bounds__(256, 2)
void gemm_ln(const __half* __restrict__ A, const __half* __restrict__ B,
             const float* __restrict__ bias, const float* __restrict__ resid,
             const float* __restrict__ lng, const float* __restrict__ lnb,
             float* __restrict__ outF, __half* __restrict__ outH, int M) {
    extern __shared__ __half smh[];
    constexpr int KT = KVAL / 64;

    const int tid = threadIdx.x;
    const int warp = tid >> 5;
    const int lane = tid & 31;
    const int g = lane >> 2;
    const int t = lane & 3;
    const int warp_m = warp & 1;   // 2 warps over M (32 rows each)
    const int warp_n = warp >> 1;  // 4 warps over N (64 cols each)
    const int m0 = blockIdx.x * 64;

    const uint32_t sbase = (uint32_t)__cvta_generic_to_shared(smh);
    const uint32_t bbase = sbase + 2 * LNA_TILEB;

    const int srow = tid >> 3;     // 0..31
    const int sseg = tid & 7;
    const bool apred[2] = { m0 + srow < M, m0 + srow + 32 < M };
    const __half* Aptr = A + (size_t)(m0 + srow) * KVAL + sseg * 8;
    const __half* Bptr = B + (size_t)srow * KVAL + sseg * 8;

    const int lm_row = lane & 15;
    const int lm_k   = (lane >> 4) << 3;

    float acc[2][8][4];
#pragma unroll
    for (int i = 0; i < 2; i++)
#pragma unroll
        for (int j = 0; j < 8; j++)
#pragma unroll
            for (int q = 0; q < 4; q++) acc[i][j][q] = 0.0f;

    // prologue: tile 0 -> buffer 0 (A: 2 rows/thread, B: 8 rows/thread)
#pragma unroll
    for (int u = 0; u < 2; u++) {
        int r = srow + u * 32;
        cp16(sbase + (r * SAH + sseg * 8) * 2, Aptr + (size_t)(u * 32) * KVAL, apred[u]);
    }
#pragma unroll
    for (int u = 0; u < 8; u++) {
        int r = srow + u * 32;
        cp16(bbase + (r * SAH + sseg * 8) * 2, Bptr + (size_t)(u * 32) * KVAL, true);
    }
    CP_COMMIT();

#pragma unroll
    for (int kt = 0; kt < KT; kt++) {
        const int buf = kt & 1;
        if (kt + 1 < KT) {
            const int k0 = (kt + 1) << 6;
            const int nb = buf ^ 1;
#pragma unroll
            for (int u = 0; u < 2; u++) {
                int r = srow + u * 32;
                cp16(sbase + (nb * LNA_TILEH + r * SAH + sseg * 8) * 2,
                     Aptr + (size_t)(u * 32) * KVAL + k0, apred[u]);
            }
#pragma unroll
            for (int u = 0; u < 8; u++) {
                int r = srow + u * 32;
                cp16(bbase + (nb * LNB_TILEH + r * SAH + sseg * 8) * 2,
                     Bptr + (size_t)(u * 32) * KVAL + k0, true);
            }
            CP_COMMIT();
            CP_WAIT(1);
        } else {
            CP_WAIT(0);
        }
        __syncthreads();

        const uint32_t abuf = sbase + buf * LNA_TILEB;
        const uint32_t bbuf = bbase + buf * LNB_TILEB;

#pragma unroll
        for (int ks = 0; ks < 4; ks++) {
            const int kk = ks * 16;
            uint32_t af[2][4];
#pragma unroll
            for (int i = 0; i < 2; i++) {
                int rm = warp_m * 32 + i * 16;
                ldsm4(af[i][0], af[i][1], af[i][2], af[i][3],
                      abuf + ((rm + lm_row) * SAH + kk + lm_k) * 2);
            }
            uint32_t bf[8][2];
#pragma unroll
            for (int jj = 0; jj < 4; jj++) {
                int nb2 = warp_n * 64 + jj * 16;
                uint32_t r0, r1, r2, r3;
                ldsm4(r0, r1, r2, r3, bbuf + ((nb2 + lm_row) * SAH + kk + lm_k) * 2);
                bf[2 * jj][0] = r0;     bf[2 * jj][1] = r2;
                bf[2 * jj + 1][0] = r1; bf[2 * jj + 1][1] = r3;
            }
#pragma unroll
            for (int i = 0; i < 2; i++)
#pragma unroll
                for (int j = 0; j < 8; j++)
                    mma_f16(acc[i][j], af[i], bf[j]);
        }
        __syncthreads();
    }

    // ---- fused bias + resid + LayerNorm epilogue ----
    float* red = (float*)smh;   // [64 rows][8]: s in [0..3], s2 in [4..7]

#pragma unroll
    for (int i = 0; i < 2; i++) {
#pragma unroll
        for (int half_ = 0; half_ < 2; half_++) {
            const int rl = warp_m * 32 + i * 16 + half_ * 8 + g;
            const int r = m0 + rl;
            float s = 0.f, s2 = 0.f;
            if (r < M) {
#pragma unroll
                for (int j = 0; j < 8; j++) {
                    int c = warp_n * 64 + j * 8 + 2 * t;
                    float2 bv = *(const float2*)&bias[c];
                    float2 rv = *(const float2*)&resid[(size_t)r * HIDC + c];
                    float ox = acc[i][j][half_ * 2 + 0] + bv.x + rv.x;
                    float oy = acc[i][j][half_ * 2 + 1] + bv.y + rv.y;
                    acc[i][j][half_ * 2 + 0] = ox;
                    acc[i][j][half_ * 2 + 1] = oy;
                    s += ox + oy;
                    s2 += ox * ox + oy * oy;
                }
            }
            s  += __shfl_xor_sync(0xffffffffu, s, 1);
            s  += __shfl_xor_sync(0xffffffffu, s, 2);
            s2 += __shfl_xor_sync(0xffffffffu, s2, 1);
            s2 += __shfl_xor_sync(0xffffffffu, s2, 2);
            if (t == 0) {
                red[rl * 8 + warp_n] = s;
                red[rl * 8 + 4 + warp_n] = s2;
            }
        }
    }
    __syncthreads();

#pragma unroll
    for (int i = 0; i < 2; i++) {
#pragma unroll
        for (int half_ = 0; half_ < 2; half_++) {
            const int rl = warp_m * 32 + i * 16 + half_ * 8 + g;
            const int r = m0 + rl;
            if (r >= M) continue;
            float S  = red[rl * 8 + 0] + red[rl * 8 + 1] + red[rl * 8 + 2] + red[rl * 8 + 3];
            float S2 = red[rl * 8 + 4] + red[rl * 8 + 5] + red[rl * 8 + 6] + red[rl * 8 + 7];
            float mean = S * (1.0f / HIDC);
            float var = S2 * (1.0f / HIDC) - mean * mean;
            float rstd = rsqrtf(var + 1e-5f);
#pragma unroll
            for (int j = 0; j < 8; j++) {
                int c = warp_n * 64 + j * 8 + 2 * t;
                float2 gv = *(const float2*)&lng[c];
                float2 bv = *(const float2*)&lnb[c];
                float vx = (acc[i][j][half_ * 2 + 0] - mean) * rstd * gv.x + bv.x;
                float vy = (acc[i][j][half_ * 2 + 1] - mean) * rstd * gv.y + bv.y;
                *(float2*)&outF[(size_t)r * HIDC + c] = make_float2(vx, vy);
                if (OUT2)
                    *(__half2*)&outH[(size_t)r * HIDC + c] =
                        __float22half2_rn(make_float2(vx, vy));
            }
        }
    }
}

// ---------------- weight pack: TRANSPOSED [N][K], half ----------------
__global__ void pack_kernel(const float* Wq, const float* Wk, const float* Wv,
                            const float* Wew, const float* Web, const float* Weo,
                            const float* Wo_h, const float* Wo_e,
                            const float* W1, const float* W2, float* S) {
    int i = blockIdx.x * 256 + threadIdx.x;
    if (i < 196608) {  // wqkvT [768][256]
        int n = i >> 8, k = i & 255;
        float v = (n < 256) ? Wq[k * 256 + n]
                : (n < 512) ? Wk[k * 256 + n - 256]
                            : Wv[k * 256 + n - 512];
        ((__half*)(S + O_WQKV))[i] = __float2half(v);
    }
    int i2 = i - 196608;
    if (i2 >= 0 && i2 < 131072) {  // wewbT [512][256], rows interleaved Ew/Eb
        int n = i2 >> 8, k = i2 & 255, c = n >> 1;
        float v = (n & 1) ? Web[k * 256 + c] : Wew[k * 256 + c];
        ((__half*)(S + O_WEWB))[i2] = __float2half(v);
    }
    int i3 = i - 327680;
    if (i3 >= 0 && i3 < 65536) {
        int n = i3 >> 8, k = i3 & 255;
        ((__half*)(S + O_WEO))[i3] = __float2half(Weo[k * 256 + n]);
    }
    int i4 = i - 393216;
    if (i4 >= 0 && i4 < 65536) {
        int n = i4 >> 8, k = i4 & 255;
        ((__half*)(S + O_WOH))[i4] = __float2half(Wo_h[k * 256 + n]);
    }
    int i5 = i - 458752;
    if (i5 >= 0 && i5 < 65536) {
        int n = i5 >> 8, k = i5 & 255;
        ((__half*)(S + O_WOE))[i5] = __float2half(Wo_e[k * 256 + n]);
    }
    int i6 = i - 524288;
    if (i6 >= 0 && i6 < 131072) {  // w1T [512][256]
        int n = i6 >> 8, k = i6 & 255;
        ((__half*)(S + O_W1))[i6] = __float2half(W1[k * 512 + n]);
    }
    int i7 = i - 655360;
    if (i7 >= 0 && i7 < 131072) {  // w2T [256][512]
        int n = i7 >> 9, k = i7 & 511;
        ((__half*)(S + O_W2))[i7] = __float2half(W2[k * 256 + n]);
    }
}

// ---------------- fp32 -> half copy ----------------
__global__ void cvt_kernel(const float* __restrict__ in, __half* __restrict__ out, long n4) {
    long i = (long)blockIdx.x * 256 + threadIdx.x;
    if (i >= n4) return;
    float4 v = ((const float4*)in)[i];
    __half2* o = (__half2*)out + 2 * i;
    o[0] = __float22half2_rn(make_float2(v.x, v.y));
    o[1] = __float22half2_rn(make_float2(v.z, v.w));
}

// ---------------- init ----------------
__global__ void init_kernel(float* agg, float* rowv, float* smax, float* ssum, int Nn) {
    int t = blockIdx.x * 256 + threadIdx.x;
    if (t < Nn * HIDC) { agg[t] = 0.f; rowv[t] = 0.f; }
    if (t < Nn * NHEAD) { smax[t] = -CLAMP_V; ssum[t] = 0.f; }
}

// ---------------- exp + segment sum ----------------
__global__ void ex_kernel(float* __restrict__ score, const float* __restrict__ smax,
                          float* __restrict__ ssum, const int* __restrict__ dst, int E) {
    int t = blockIdx.x * 256 + threadIdx.x;
    if (t >= E * NHEAD) return;
    int e = t >> 3, h = t & 7;
    int dn = dst[e];
    float ex = expf(score[t] - smax[dn * NHEAD + h]);
    score[t] = ex;
    atomicAdd(&ssum[dn * NHEAD + h], ex);
}

// ---------------- scatter (V in QKV half, col off 512, stride 768) ----------------
__global__ void scatter_kernel(const float* __restrict__ exv, const float* __restrict__ ssum,
                               const __half* __restrict__ QKV, const __half* __restrict__ Oe,
                               float* __restrict__ agg, float* __restrict__ rowv,
                               const int* __restrict__ dst, const int* __restrict__ src, int E) {
    long t = (long)blockIdx.x * 256 + threadIdx.x;
    if (t >= (long)E * 64) return;
    int e = (int)(t >> 6), q = (int)(t & 63);
    int h = q >> 3;
    int dn = dst[e], sn = src[e];
    float sc = exv[e * NHEAD + h] / (ssum[dn * NHEAD + h] + 1e-16f);
    const __half2* vp = (const __half2*)(QKV + (size_t)sn * 768 + 512 + q * 4);
    const __half2* op = (const __half2*)(Oe + (size_t)e * HIDC + q * 4);
    float2 v0 = __half22float2(vp[0]), v1 = __half22float2(vp[1]);
    float2 o0 = __half22float2(op[0]), o1 = __half22float2(op[1]);
    float* ap = &agg[(size_t)dn * HIDC + q * 4];
    atomicAdd(ap + 0, v0.x * sc); atomicAdd(ap + 1, v0.y * sc);
    atomicAdd(ap + 2, v1.x * sc); atomicAdd(ap + 3, v1.y * sc);
    float* rp = &rowv[(size_t)dn * HIDC + q * 4];
    atomicAdd(rp + 0, o0.x * sc); atomicAdd(rp + 1, o0.y * sc);
    atomicAdd(rp + 2, o1.x * sc); atomicAdd(rp + 3, o1.y * sc);
}

// ---------------- combine: On = half(agg + einsum(rowv, BW)) ----------------
__global__ void combine_kernel(const float* __restrict__ agg, const float* __restrict__ rowv,
                               const float* __restrict__ BW, __half* __restrict__ On, int Nn) {
    __shared__ float sBW[32 * 8 * 32];
    __shared__ float srv[HIDC];
    int tid = threadIdx.x;
    for (int i = tid; i < 32 * 8 * 32; i += 256) sBW[i] = BW[i];
    int h = tid >> 5, c = tid & 31;
    for (int r = 0; r < 4; r++) {
        int n = blockIdx.x * 4 + r;
        __syncthreads();
        if (n < Nn) srv[tid] = rowv[(size_t)n * HIDC + tid];
        __syncthreads();
        if (n < Nn) {
            float s = agg[(size_t)n * HIDC + tid];
#pragma unroll
            for (int d = 0; d < 32; d++)
                s += srv[h * 32 + d] * sBW[d * HIDC + h * 32 + c];
            On[(size_t)n * HIDC + tid] = __float2half(s);
        }
    }
}

// ---------------- launch ----------------
extern "C" void kernel_launch(void* const* d_in, const int* in_sizes, int n_in,
                              void* d_out, int out_size) {
    const float* x     = (const float*)d_in[0];
    const float* conn  = (const float*)d_in[1];
    const float* Wq    = (const float*)d_in[2];
    const float* Wk    = (const float*)d_in[3];
    const float* Wv    = (const float*)d_in[4];
    const float* Wew   = (const float*)d_in[5];
    const float* Web   = (const float*)d_in[6];
    const float* beb   = (const float*)d_in[7];
    const float* Weo   = (const float*)d_in[8];
    const float* beo   = (const float*)d_in[9];
    const float* Aw    = (const float*)d_in[10];
    const float* BW    = (const float*)d_in[11];
    const float* Wo_h  = (const float*)d_in[12];
    const float* bo_h  = (const float*)d_in[13];
    const float* Wo_e  = (const float*)d_in[14];
    const float* bo_e  = (const float*)d_in[15];
    const float* ln1hg = (const float*)d_in[16];
    const float* ln1hb = (const float*)d_in[17];
    const float* ln1eg = (const float*)d_in[18];
    const float* ln1eb = (const float*)d_in[19];
    const float* W1    = (const float*)d_in[20];
    const float* b1    = (const float*)d_in[21];
    const float* W2    = (const float*)d_in[22];
    const float* b2    = (const float*)d_in[23];
    const float* ln2hg = (const float*)d_in[24];
    const float* ln2hb = (const float*)d_in[25];
    const int*   ei    = (const int*)d_in[26];

    int Nn = in_sizes[0] / HIDC;
    int Ee = in_sizes[26] / 2;
    const int* dst = ei;
    const int* src = ei + Ee;

    float* S = nullptr;
    cudaGetSymbolAddress((void**)&S, g_scratch);

    __half* QKV  = (__half*)(S + O_QKV);
    __half* cA   = (__half*)(S + O_CA);
    __half* Oe   = (__half*)(S + O_OE);
    float*  scb  = S + O_SCB;
    float*  smax = S + O_SMAX;
    float*  ssum = S + O_SSUM;
    float*  agg  = S + O_AGG;
    float*  rowv = S + O_ROWV;
    __half* On   = (__half*)(S + O_ON);
    float*  hln  = S + O_HLN;
    __half* hlnt = (__half*)(S + O_HLNT);
    __half* ffn  = (__half*)(S + O_FFN);
    __half* xt   = (__half*)(S + O_XT);
    __half* ct   = (__half*)(S + O_CT);
    __half* wqkv = (__half*)(S + O_WQKV);
    __half* wewb = (__half*)(S + O_WEWB);
    __half* weo  = (__half*)(S + O_WEO);
    __half* woh  = (__half*)(S + O_WOH);
    __half* woe  = (__half*)(S + O_WOE);
    __half* w1   = (__half*)(S + O_W1);
    __half* w2   = (__half*)(S + O_W2);

    float* outH = (float*)d_out;
    float* outE = outH + (size_t)Nn * HIDC;

    cudaFuncSetAttribute(gemm_f16<0, 1, 0, 256>, cudaFuncAttributeMaxDynamicSharedMemorySize, G16_SMEM);
    cudaFuncSetAttribute(gemm_f16<0, 1, 1, 256>, cudaFuncAttributeMaxDynamicSharedMemorySize, G16_SMEM);
    cudaFuncSetAttribute(gemm_f16<1, 1, 0, 256>, cudaFuncAttributeMaxDynamicSharedMemorySize, G16_SMEM);
    cudaFuncSetAttribute(gemm_f16<2, 0, 0, 256>, cudaFuncAttributeMaxDynamicSharedMemorySize, G16_SMEM);
    cudaFuncSetAttribute(gemm_ln<1, 256>, cudaFuncAttributeMaxDynamicSharedMemorySize, GLN_SMEM);
    cudaFuncSetAttribute(gemm_ln<0, 256>, cudaFuncAttributeMaxDynamicSharedMemorySize, GLN_SMEM);
    cudaFuncSetAttribute(gemm_ln<0, 512>, cudaFuncAttributeMaxDynamicSharedMemorySize, GLN_SMEM);

    // prep
    pack_kernel<<<cdiv(786432, 256), 256>>>(Wq, Wk, Wv, Wew, Web, Weo, Wo_h, Wo_e, W1, W2, S);
    cvt_kernel<<<cdiv(Nn * 64, 256), 256>>>(x, xt, (long)Nn * 64);
    cvt_kernel<<<(int)cdiv((long)Ee * 64, 256), 256>>>(conn, ct, (long)Ee * 64);
    init_kernel<<<cdiv(Nn * HIDC, 256), 256>>>(agg, rowv, smax, ssum, Nn);

    int gmN = cdiv(Nn, 128);
    int gmE = cdiv(Ee, 128);

    // QKV = xt @ WqkvT  [N, 768] (half out)
    gemm_f16<0, 1, 0, 256><<<dim3(gmN, 6), 256, G16_SMEM>>>(
        xt, wqkv, nullptr, nullptr, QKV, Nn, 768,
        nullptr, nullptr, nullptr, nullptr, nullptr, nullptr);
    // fused EwEb GEMM + edge message -> cA (half)
    gemm_f16<2, 0, 0, 256><<<dim3(gmE, 4), 256, G16_SMEM>>>(
        ct, wewb, beb, nullptr, cA, Ee, 512,
        dst, src, QKV, nullptr, nullptr, nullptr);
    // Oe = cA @ WeoT + beo (half) + fused score/clamp/segment-max
    gemm_f16<0, 1, 1, 256><<<dim3(gmE, 2), 256, G16_SMEM>>>(
        cA, weo, beo, nullptr, Oe, Ee, 256,
        dst, nullptr, nullptr, Aw, scb, smax);

    ex_kernel<<<cdiv(Ee * NHEAD, 256), 256>>>(scb, smax, ssum, dst, Ee);
    scatter_kernel<<<(int)cdiv((long)Ee * 64, 256), 256>>>(scb, ssum, QKV, Oe, agg, rowv, dst, src, Ee);
    combine_kernel<<<cdiv(Nn, 4), 256>>>(agg, rowv, BW, On, Nn);

    // h path: hln = LN1h(x + On @ Wo_h + bo_h), + half copy hlnt
    gemm_ln<1, 256><<<cdiv(Nn, 64), 256, GLN_SMEM>>>(
        On, woh, bo_h, x, ln1hg, ln1hb, hln, hlnt, Nn);

    // e path: outE = LN1e(conn + Oe @ Wo_e + bo_e)   (fused)
    gemm_ln<0, 256><<<cdiv(Ee, 64), 256, GLN_SMEM>>>(
        Oe, woe, bo_e, conn, ln1eg, ln1eb, outE, nullptr, Ee);

    // FFN: ffn = relu(hlnt @ W1 + b1) (half)
    gemm_f16<1, 1, 0, 256><<<dim3(gmN, 4), 256, G16_SMEM>>>(
        hlnt, w1, b1, nullptr, ffn, Nn, 512,
        nullptr, nullptr, nullptr, nullptr, nullptr, nullptr);
    // outH = LN2h(hln + ffn @ W2 + b2)  (K=512, fused)
    gemm_ln<0, 512><<<cdiv(Nn, 64), 256, GLN_SMEM>>>(
        ffn, w2, b2, hln, ln2hg, ln2hb, outH, nullptr, Nn);
}

// round 10
// speedup vs baseline: 1.5618x; 1.1405x over previous
#include <cuda_runtime.h>
#include <cuda_fp16.h>
#include <math.h>
#include <stdint.h>

#define HIDC 256
#define NHEAD 8
#define CLAMP_V 5.0f

static const int NMAXC = 50000;
static const int EMAXC = 320000;

// ---------------- scratch layout (slots sized in floats; half arrays reuse) ----
#define O_QKV  ((size_t)0)                          // N*768 (half)
#define O_CA   (O_QKV  + (size_t)NMAXC*768)         // E*256 (half)
#define O_OE   (O_CA   + (size_t)EMAXC*256)         // E*256 (half)
#define O_SCB  (O_OE   + (size_t)EMAXC*256)         // E*8  (f32)
#define O_SMAX (O_SCB  + (size_t)EMAXC*8)           // N*8  (f32)
#define O_SSUM (O_SMAX + (size_t)NMAXC*8)           // N*8  (f32)
#define O_AGG  (O_SSUM + (size_t)NMAXC*8)           // N*256 (f32)
#define O_ROWV (O_AGG  + (size_t)NMAXC*256)         // N*256 (f32)
#define O_ON   (O_ROWV + (size_t)NMAXC*256)         // N*256 (half)
#define O_HLN  (O_ON   + (size_t)NMAXC*256)         // N*256 (f32)
#define O_HLNT (O_HLN  + (size_t)NMAXC*256)         // N*256 (half)
#define O_FFN  (O_HLNT + (size_t)NMAXC*256)         // N*512 (half)
#define O_XT   (O_FFN  + (size_t)NMAXC*512)         // N*256 (half)
#define O_CT   (O_XT   + (size_t)NMAXC*256)         // E*256 (half)
#define O_WQKV (O_CT   + (size_t)EMAXC*256)         // 768*256 (half, [N][K])
#define O_WEWB (O_WQKV + (size_t)768*256)           // 512*256 (half)
#define O_WEO  (O_WEWB + (size_t)512*256)           // 256*256 (half)
#define O_WOH  (O_WEO  + (size_t)256*256)           // 256*256 (half)
#define O_WOE  (O_WOH  + (size_t)256*256)           // 256*256 (half)
#define O_W1   (O_WOE  + (size_t)256*256)           // 512*256 (half)
#define O_W2   (O_W1   + (size_t)512*256)           // 256*512 (half)
#define O_TOTAL (O_W2  + (size_t)256*512)

__device__ float g_scratch[O_TOTAL];

static inline int cdiv(int a, int b) { return (a + b - 1) / b; }

// ---------------- helpers ----------------
__device__ __forceinline__ void mma_f16(float c[4], const uint32_t a[4], const uint32_t b[2]) {
    asm volatile(
        "mma.sync.aligned.m16n8k16.row.col.f32.f16.f16.f32 "
        "{%0,%1,%2,%3}, {%4,%5,%6,%7}, {%8,%9}, {%0,%1,%2,%3};"
        : "+f"(c[0]), "+f"(c[1]), "+f"(c[2]), "+f"(c[3])
        : "r"(a[0]), "r"(a[1]), "r"(a[2]), "r"(a[3]), "r"(b[0]), "r"(b[1]));
}

__device__ __forceinline__ void ldsm4(uint32_t& r0, uint32_t& r1, uint32_t& r2, uint32_t& r3,
                                      uint32_t addr) {
    asm volatile("ldmatrix.sync.aligned.m8n8.x4.shared.b16 {%0,%1,%2,%3}, [%4];"
                 : "=r"(r0), "=r"(r1), "=r"(r2), "=r"(r3) : "r"(addr));
}

__device__ __forceinline__ void cp16(uint32_t saddr, const void* g, bool pred) {
    int sz = pred ? 16 : 0;
    asm volatile("cp.async.cg.shared.global [%0], [%1], 16, %2;\n"
                 :: "r"(saddr), "l"(g), "r"(sz));
}
#define CP_COMMIT() asm volatile("cp.async.commit_group;\n" ::)
#define CP_WAIT(n)  asm volatile("cp.async.wait_group %0;\n" :: "n"(n))

__device__ __forceinline__ void atomicMaxF(float* addr, float val) {
    int* ai = (int*)addr;
    int old = *ai;
    while (__int_as_float(old) < val) {
        int assumed = old;
        old = atomicCAS(ai, assumed, __float_as_int(val));
        if (old == assumed) break;
    }
}

__device__ __forceinline__ void redv4(float* addr, float a, float b, float c, float d) {
    asm volatile("red.global.add.v4.f32 [%0], {%1, %2, %3, %4};"
                 :: "l"(addr), "f"(a), "f"(b), "f"(c), "f"(d) : "memory");
}

// ---------------- fp16 tensor-core GEMM (BM=128, BN=128) ----------------
// A row-major [M][KVAL] half; B = weights [Ntot][KVAL] half (K-major).
// 256 thr = 8 warps (4m x 2n), warp tile 32x64, BK=64 double buffer.
// ACT: 0 normal (bias?+resid? fp32), 1 bias+relu, 2 fused edge message
// OUTH: store half. SCORE: fused attention score (Oe GEMM, implies half out).
#define SAH 72                    // smem row stride in halves (144B)
#define TILEH (128 * SAH)
#define TILEB (TILEH * 2)
#define G16_SMEM (4 * TILEB)

template <int ACT, int OUTH, int SCORE, int KVAL>
__global__ __launch_bounds__(256, 2)
void gemm_f16(const __half* __restrict__ A, const __half* __restrict__ B,
              const float* __restrict__ bias, const float* __restrict__ resid,
              void* __restrict__ Cv, int M, int Ncol,
              const int* __restrict__ dst, const int* __restrict__ src,
              const __half* __restrict__ QKV, const float* __restrict__ Aw,
              float* __restrict__ scb, float* __restrict__ smax) {
    extern __shared__ __half smh[];
    constexpr int KT = KVAL / 64;

    const int tid = threadIdx.x;
    const int warp = tid >> 5;
    const int lane = tid & 31;
    const int g = lane >> 2;
    const int t = lane & 3;
    const int warp_m = warp & 3;
    const int warp_n = warp >> 2;
    const int m0 = blockIdx.x * 128;
    const int n0 = blockIdx.y * 128;

    const uint32_t sbase = (uint32_t)__cvta_generic_to_shared(smh);
    const uint32_t bbase = sbase + 2 * TILEB;

    const int srow = tid >> 3;
    const int sseg = tid & 7;
    const bool apred[4] = { m0 + srow + 0 * 32 < M, m0 + srow + 1 * 32 < M,
                            m0 + srow + 2 * 32 < M, m0 + srow + 3 * 32 < M };
    const __half* Aptr = A + (size_t)(m0 + srow) * KVAL + sseg * 8;
    const __half* Bptr = B + (size_t)(n0 + srow) * KVAL + sseg * 8;

    const int lm_row = lane & 15;
    const int lm_k   = (lane >> 4) << 3;

    float acc[2][8][4];
#pragma unroll
    for (int i = 0; i < 2; i++)
#pragma unroll
        for (int j = 0; j < 8; j++)
#pragma unroll
            for (int q = 0; q < 4; q++) acc[i][j][q] = 0.0f;

#pragma unroll
    for (int u = 0; u < 4; u++) {
        int r = srow + u * 32;
        cp16(sbase + (r * SAH + sseg * 8) * 2, Aptr + (size_t)(u * 32) * KVAL, apred[u]);
        cp16(bbase + (r * SAH + sseg * 8) * 2, Bptr + (size_t)(u * 32) * KVAL, true);
    }
    CP_COMMIT();

#pragma unroll
    for (int kt = 0; kt < KT; kt++) {
        const int buf = kt & 1;
        if (kt + 1 < KT) {
            const int k0 = (kt + 1) << 6;
            const int nb = buf ^ 1;
#pragma unroll
            for (int u = 0; u < 4; u++) {
                int r = srow + u * 32;
                cp16(sbase + (nb * TILEH + r * SAH + sseg * 8) * 2,
                     Aptr + (size_t)(u * 32) * KVAL + k0, apred[u]);
                cp16(bbase + (nb * TILEH + r * SAH + sseg * 8) * 2,
                     Bptr + (size_t)(u * 32) * KVAL + k0, true);
            }
            CP_COMMIT();
            CP_WAIT(1);
        } else {
            CP_WAIT(0);
        }
        __syncthreads();

        const uint32_t abuf = sbase + buf * TILEB;
        const uint32_t bbuf = bbase + buf * TILEB;

#pragma unroll
        for (int ks = 0; ks < 4; ks++) {
            const int kk = ks * 16;
            uint32_t af[2][4];
#pragma unroll
            for (int i = 0; i < 2; i++) {
                int rm = warp_m * 32 + i * 16;
                ldsm4(af[i][0], af[i][1], af[i][2], af[i][3],
                      abuf + ((rm + lm_row) * SAH + kk + lm_k) * 2);
            }
            uint32_t bf[8][2];
#pragma unroll
            for (int jj = 0; jj < 4; jj++) {
                int nb2 = warp_n * 64 + jj * 16;
                uint32_t r0, r1, r2, r3;
                ldsm4(r0, r1, r2, r3, bbuf + ((nb2 + lm_row) * SAH + kk + lm_k) * 2);
                bf[2 * jj][0] = r0;     bf[2 * jj][1] = r2;
                bf[2 * jj + 1][0] = r1; bf[2 * jj + 1][1] = r3;
            }
#pragma unroll
            for (int i = 0; i < 2; i++)
#pragma unroll
                for (int j = 0; j < 8; j++)
                    mma_f16(acc[i][j], af[i], bf[j]);
        }
        __syncthreads();
    }

    // ---- epilogue ----
    if (ACT == 2) {
        __half* C = (__half*)Cv;
        float bebv[8];
        int cqv[8];
#pragma unroll
        for (int j = 0; j < 8; j++) {
            int cq = (n0 >> 1) + warp_n * 32 + j * 4 + t;
            cqv[j] = cq;
            bebv[j] = bias[cq];
        }
#pragma unroll
        for (int i = 0; i < 2; i++) {
#pragma unroll
            for (int half_ = 0; half_ < 2; half_++) {
                int r = m0 + warp_m * 32 + i * 16 + half_ * 8 + g;
                if (r >= M) continue;
                int dn = dst[r], sn = src[r];
                const __half* qrow = QKV + (size_t)dn * 768;
                const __half* krow = QKV + (size_t)sn * 768 + 256;
#pragma unroll
                for (int j = 0; j < 8; j++) {
                    float ew = acc[i][j][half_ * 2 + 0];
                    float eb = acc[i][j][half_ * 2 + 1] + bebv[j];
                    float aqk = __half2float(qrow[cqv[j]]) + __half2float(krow[cqv[j]]);
                    float c1 = aqk * ew;
                    float c2 = copysignf(sqrtf(fabsf(c1)), c1);
                    C[(size_t)r * 256 + cqv[j]] = __float2half(fmaxf(c2 + eb, 0.f));
                }
            }
        }
    } else if (SCORE) {
        __half* C = (__half*)Cv;
        const int h0 = (n0 + warp_n * 64) >> 5;
        float aw0[8], aw1[8];
#pragma unroll
        for (int j4 = 0; j4 < 4; j4++) {
            int d = j4 * 8 + 2 * t;
            aw0[2 * j4]     = __ldg(&Aw[d * 8 + h0]);
            aw0[2 * j4 + 1] = __ldg(&Aw[(d + 1) * 8 + h0]);
            aw1[2 * j4]     = __ldg(&Aw[d * 8 + h0 + 1]);
            aw1[2 * j4 + 1] = __ldg(&Aw[(d + 1) * 8 + h0 + 1]);
        }
        float2 bvj[8];
#pragma unroll
        for (int j = 0; j < 8; j++)
            bvj[j] = *(const float2*)&bias[n0 + warp_n * 64 + j * 8 + 2 * t];
#pragma unroll
        for (int i = 0; i < 2; i++) {
#pragma unroll
            for (int half_ = 0; half_ < 2; half_++) {
                int r = m0 + warp_m * 32 + i * 16 + half_ * 8 + g;
                float s0 = 0.f, s1 = 0.f;
                if (r < M) {
#pragma unroll
                    for (int j = 0; j < 8; j++) {
                        float ox = acc[i][j][half_ * 2 + 0] + bvj[j].x;
                        float oy = acc[i][j][half_ * 2 + 1] + bvj[j].y;
                        __half2 h2v = __float22half2_rn(make_float2(ox, oy));
                        ox = __half2float(__low2half(h2v));
                        oy = __half2float(__high2half(h2v));
                        int c = n0 + warp_n * 64 + j * 8 + 2 * t;
                        *(__half2*)&C[(size_t)r * Ncol + c] = h2v;
                        if (j < 4) {
                            s0 += ox * aw0[2 * j] + oy * aw0[2 * j + 1];
                        } else {
                            s1 += ox * aw1[2 * (j - 4)] + oy * aw1[2 * (j - 4) + 1];
                        }
                    }
                }
                s0 += __shfl_xor_sync(0xffffffffu, s0, 1);
                s0 += __shfl_xor_sync(0xffffffffu, s0, 2);
                s1 += __shfl_xor_sync(0xffffffffu, s1, 1);
                s1 += __shfl_xor_sync(0xffffffffu, s1, 2);
                if (r < M && t == 0) {
                    s0 = fminf(fmaxf(s0, -CLAMP_V), CLAMP_V);
                    s1 = fminf(fmaxf(s1, -CLAMP_V), CLAMP_V);
                    scb[(size_t)r * 8 + h0] = s0;
                    scb[(size_t)r * 8 + h0 + 1] = s1;
                    int dn = dst[r];
                    atomicMaxF(&smax[dn * 8 + h0], s0);
                    atomicMaxF(&smax[dn * 8 + h0 + 1], s1);
                }
            }
        }
    } else {
#pragma unroll
        for (int j = 0; j < 8; j++) {
            int c = n0 + warp_n * 64 + j * 8 + 2 * t;
            float2 bv = make_float2(0.f, 0.f);
            if (bias) bv = *(const float2*)&bias[c];
#pragma unroll
            for (int i = 0; i < 2; i++) {
                int rbase = m0 + warp_m * 32 + i * 16 + g;
#pragma unroll
                for (int half_ = 0; half_ < 2; half_++) {
                    int r = rbase + half_ * 8;
                    if (r >= M) continue;
                    float ox = acc[i][j][half_ * 2 + 0] + bv.x;
                    float oy = acc[i][j][half_ * 2 + 1] + bv.y;
                    if (resid) {
                        float2 rv = *(const float2*)&resid[(size_t)r * Ncol + c];
                        ox += rv.x; oy += rv.y;
                    }
                    if (ACT == 1) { ox = fmaxf(ox, 0.f); oy = fmaxf(oy, 0.f); }
                    if (OUTH) {
                        *(__half2*)&((__half*)Cv)[(size_t)r * Ncol + c] =
                            __float22half2_rn(make_float2(ox, oy));
                    } else {
                        *(float2*)&((float*)Cv)[(size_t)r * Ncol + c] = make_float2(ox, oy);
                    }
                }
            }
        }
    }
}

// ---------------- fp16 GEMM + fused residual + LayerNorm ----------------
// BM=64, BN=256 (full row), 256 thr = 8 warps (2m x 4n), warp tile 32x64.
#define LNA_TILEH (64 * SAH)
#define LNA_TILEB (LNA_TILEH * 2)
#define LNB_TILEH (256 * SAH)
#define LNB_TILEB (LNB_TILEH * 2)
#define GLN_SMEM (2 * LNA_TILEB + 2 * LNB_TILEB)

template <int OUT2, int KVAL>
__global__ __launch_bounds__(256, 2)
void gemm_ln(const __half* __restrict__ A, const __half* __restrict__ B,
             const float* __restrict__ bias, const float* __restrict__ resid,
             const float* __restrict__ lng, const float* __restrict__ lnb,
             float* __restrict__ outF, __half* __restrict__ outH, int M) {
    extern __shared__ __half smh[];
    constexpr int KT = KVAL / 64;

    const int tid = threadIdx.x;
    const int warp = tid >> 5;
    const int lane = tid & 31;
    const int g = lane >> 2;
    const int t = lane & 3;
    const int warp_m = warp & 1;
    const int warp_n = warp >> 1;
    const int m0 = blockIdx.x * 64;

    const uint32_t sbase = (uint32_t)__cvta_generic_to_shared(smh);
    const uint32_t bbase = sbase + 2 * LNA_TILEB;

    const int srow = tid >> 3;
    const int sseg = tid & 7;
    const bool apred[2] = { m0 + srow < M, m0 + srow + 32 < M };
    const __half* Aptr = A + (size_t)(m0 + srow) * KVAL + sseg * 8;
    const __half* Bptr = B + (size_t)srow * KVAL + sseg * 8;

    const int lm_row = lane & 15;
    const int lm_k   = (lane >> 4) << 3;

    float acc[2][8][4];
#pragma unroll
    for (int i = 0; i < 2; i++)
#pragma unroll
        for (int j = 0; j < 8; j++)
#pragma unroll
            for (int q = 0; q < 4; q++) acc[i][j][q] = 0.0f;

#pragma unroll
    for (int u = 0; u < 2; u++) {
        int r = srow + u * 32;
        cp16(sbase + (r * SAH + sseg * 8) * 2, Aptr + (size_t)(u * 32) * KVAL, apred[u]);
    }
#pragma unroll
    for (int u = 0; u < 8; u++) {
        int r = srow + u * 32;
        cp16(bbase + (r * SAH + sseg * 8) * 2, Bptr + (size_t)(u * 32) * KVAL, true);
    }
    CP_COMMIT();

#pragma unroll
    for (int kt = 0; kt < KT; kt++) {
        const int buf = kt & 1;
        if (kt + 1 < KT) {
            const int k0 = (kt + 1) << 6;
            const int nb = buf ^ 1;
#pragma unroll
            for (int u = 0; u < 2; u++) {
                int r = srow + u * 32;
                cp16(sbase + (nb * LNA_TILEH + r * SAH + sseg * 8) * 2,
                     Aptr + (size_t)(u * 32) * KVAL + k0, apred[u]);
            }
#pragma unroll
            for (int u = 0; u < 8; u++) {
                int r = srow + u * 32;
                cp16(bbase + (nb * LNB_TILEH + r * SAH + sseg * 8) * 2,
                     Bptr + (size_t)(u * 32) * KVAL + k0, true);
            }
            CP_COMMIT();
            CP_WAIT(1);
        } else {
            CP_WAIT(0);
        }
        __syncthreads();

        const uint32_t abuf = sbase + buf * LNA_TILEB;
        const uint32_t bbuf = bbase + buf * LNB_TILEB;

#pragma unroll
        for (int ks = 0; ks < 4; ks++) {
            const int kk = ks * 16;
            uint32_t af[2][4];
#pragma unroll
            for (int i = 0; i < 2; i++) {
                int rm = warp_m * 32 + i * 16;
                ldsm4(af[i][0], af[i][1], af[i][2], af[i][3],
                      abuf + ((rm + lm_row) * SAH + kk + lm_k) * 2);
            }
            uint32_t bf[8][2];
#pragma unroll
            for (int jj = 0; jj < 4; jj++) {
                int nb2 = warp_n * 64 + jj * 16;
                uint32_t r0, r1, r2, r3;
                ldsm4(r0, r1, r2, r3, bbuf + ((nb2 + lm_row) * SAH + kk + lm_k) * 2);
                bf[2 * jj][0] = r0;     bf[2 * jj][1] = r2;
                bf[2 * jj + 1][0] = r1; bf[2 * jj + 1][1] = r3;
            }
#pragma unroll
            for (int i = 0; i < 2; i++)
#pragma unroll
                for (int j = 0; j < 8; j++)
                    mma_f16(acc[i][j], af[i], bf[j]);
        }
        __syncthreads();
    }

    float* red = (float*)smh;

#pragma unroll
    for (int i = 0; i < 2; i++) {
#pragma unroll
        for (int half_ = 0; half_ < 2; half_++) {
            const int rl = warp_m * 32 + i * 16 + half_ * 8 + g;
            const int r = m0 + rl;
            float s = 0.f, s2 = 0.f;
            if (r < M) {
#pragma unroll
                for (int j = 0; j < 8; j++) {
                    int c = warp_n * 64 + j * 8 + 2 * t;
                    float2 bv = *(const float2*)&bias[c];
                    float2 rv = *(const float2*)&resid[(size_t)r * HIDC + c];
                    float ox = acc[i][j][half_ * 2 + 0] + bv.x + rv.x;
                    float oy = acc[i][j][half_ * 2 + 1] + bv.y + rv.y;
                    acc[i][j][half_ * 2 + 0] = ox;
                    acc[i][j][half_ * 2 + 1] = oy;
                    s += ox + oy;
                    s2 += ox * ox + oy * oy;
                }
            }
            s  += __shfl_xor_sync(0xffffffffu, s, 1);
            s  += __shfl_xor_sync(0xffffffffu, s, 2);
            s2 += __shfl_xor_sync(0xffffffffu, s2, 1);
            s2 += __shfl_xor_sync(0xffffffffu, s2, 2);
            if (t == 0) {
                red[rl * 8 + warp_n] = s;
                red[rl * 8 + 4 + warp_n] = s2;
            }
        }
    }
    __syncthreads();

#pragma unroll
    for (int i = 0; i < 2; i++) {
#pragma unroll
        for (int half_ = 0; half_ < 2; half_++) {
            const int rl = warp_m * 32 + i * 16 + half_ * 8 + g;
            const int r = m0 + rl;
            if (r >= M) continue;
            float S  = red[rl * 8 + 0] + red[rl * 8 + 1] + red[rl * 8 + 2] + red[rl * 8 + 3];
            float S2 = red[rl * 8 + 4] + red[rl * 8 + 5] + red[rl * 8 + 6] + red[rl * 8 + 7];
            float mean = S * (1.0f / HIDC);
            float var = S2 * (1.0f / HIDC) - mean * mean;
            float rstd = rsqrtf(var + 1e-5f);
#pragma unroll
            for (int j = 0; j < 8; j++) {
                int c = warp_n * 64 + j * 8 + 2 * t;
                float2 gv = *(const float2*)&lng[c];
                float2 bv = *(const float2*)&lnb[c];
                float vx = (acc[i][j][half_ * 2 + 0] - mean) * rstd * gv.x + bv.x;
                float vy = (acc[i][j][half_ * 2 + 1] - mean) * rstd * gv.y + bv.y;
                *(float2*)&outF[(size_t)r * HIDC + c] = make_float2(vx, vy);
                if (OUT2)
                    *(__half2*)&outH[(size_t)r * HIDC + c] =
                        __float22half2_rn(make_float2(vx, vy));
            }
        }
    }
}

// ---------------- weight pack: TRANSPOSED [N][K], half ----------------
__global__ void pack_kernel(const float* Wq, const float* Wk, const float* Wv,
                            const float* Wew, const float* Web, const float* Weo,
                            const float* Wo_h, const float* Wo_e,
                            const float* W1, const float* W2, float* S) {
    int i = blockIdx.x * 256 + threadIdx.x;
    if (i < 196608) {
        int n = i >> 8, k = i & 255;
        float v = (n < 256) ? Wq[k * 256 + n]
                : (n < 512) ? Wk[k * 256 + n - 256]
                            : Wv[k * 256 + n - 512];
        ((__half*)(S + O_WQKV))[i] = __float2half(v);
    }
    int i2 = i - 196608;
    if (i2 >= 0 && i2 < 131072) {
        int n = i2 >> 8, k = i2 & 255, c = n >> 1;
        float v = (n & 1) ? Web[k * 256 + c] : Wew[k * 256 + c];
        ((__half*)(S + O_WEWB))[i2] = __float2half(v);
    }
    int i3 = i - 327680;
    if (i3 >= 0 && i3 < 65536) {
        int n = i3 >> 8, k = i3 & 255;
        ((__half*)(S + O_WEO))[i3] = __float2half(Weo[k * 256 + n]);
    }
    int i4 = i - 393216;
    if (i4 >= 0 && i4 < 65536) {
        int n = i4 >> 8, k = i4 & 255;
        ((__half*)(S + O_WOH))[i4] = __float2half(Wo_h[k * 256 + n]);
    }
    int i5 = i - 458752;
    if (i5 >= 0 && i5 < 65536) {
        int n = i5 >> 8, k = i5 & 255;
        ((__half*)(S + O_WOE))[i5] = __float2half(Wo_e[k * 256 + n]);
    }
    int i6 = i - 524288;
    if (i6 >= 0 && i6 < 131072) {
        int n = i6 >> 8, k = i6 & 255;
        ((__half*)(S + O_W1))[i6] = __float2half(W1[k * 512 + n]);
    }
    int i7 = i - 655360;
    if (i7 >= 0 && i7 < 131072) {
        int n = i7 >> 9, k = i7 & 511;
        ((__half*)(S + O_W2))[i7] = __float2half(W2[k * 256 + n]);
    }
}

// ---------------- fp32 -> half copy ----------------
__global__ void cvt_kernel(const float* __restrict__ in, __half* __restrict__ out, long n4) {
    long i = (long)blockIdx.x * 256 + threadIdx.x;
    if (i >= n4) return;
    float4 v = ((const float4*)in)[i];
    __half2* o = (__half2*)out + 2 * i;
    o[0] = __float22half2_rn(make_float2(v.x, v.y));
    o[1] = __float22half2_rn(make_float2(v.z, v.w));
}

// ---------------- init ----------------
__global__ void init_kernel(float* agg, float* rowv, float* smax, float* ssum, int Nn) {
    int t = blockIdx.x * 256 + threadIdx.x;
    if (t < Nn * HIDC) { agg[t] = 0.f; rowv[t] = 0.f; }
    if (t < Nn * NHEAD) { smax[t] = -CLAMP_V; ssum[t] = 0.f; }
}

// ---------------- exp + segment sum ----------------
__global__ void ex_kernel(float* __restrict__ score, const float* __restrict__ smax,
                          float* __restrict__ ssum, const int* __restrict__ dst, int E) {
    int t = blockIdx.x * 256 + threadIdx.x;
    if (t >= E * NHEAD) return;
    int e = t >> 3, h = t & 7;
    int dn = dst[e];
    float ex = expf(score[t] - smax[dn * NHEAD + h]);
    score[t] = ex;
    atomicAdd(&ssum[dn * NHEAD + h], ex);
}

// ---------------- scatter: vector RED (red.global.add.v4.f32) ----------------
__global__ void scatter_kernel(const float* __restrict__ exv, const float* __restrict__ ssum,
                               const __half* __restrict__ QKV, const __half* __restrict__ Oe,
                               float* __restrict__ agg, float* __restrict__ rowv,
                               const int* __restrict__ dst, const int* __restrict__ src, int E) {
    long t = (long)blockIdx.x * 256 + threadIdx.x;
    if (t >= (long)E * 64) return;
    int e = (int)(t >> 6), q = (int)(t & 63);
    int h = q >> 3;
    int dn = dst[e], sn = src[e];
    float sc = exv[e * NHEAD + h] / (ssum[dn * NHEAD + h] + 1e-16f);
    const __half2* vp = (const __half2*)(QKV + (size_t)sn * 768 + 512 + q * 4);
    const __half2* op = (const __half2*)(Oe + (size_t)e * HIDC + q * 4);
    float2 v0 = __half22float2(vp[0]), v1 = __half22float2(vp[1]);
    float2 o0 = __half22float2(op[0]), o1 = __half22float2(op[1]);
    redv4(&agg[(size_t)dn * HIDC + q * 4], v0.x * sc, v0.y * sc, v1.x * sc, v1.y * sc);
    redv4(&rowv[(size_t)dn * HIDC + q * 4], o0.x * sc, o0.y * sc, o1.x * sc, o1.y * sc);
}

// ---------------- combine: On = half(agg + einsum(rowv, BW)) ----------------
__global__ void combine_kernel(const float* __restrict__ agg, const float* __restrict__ rowv,
                               const float* __restrict__ BW, __half* __restrict__ On, int Nn) {
    __shared__ float sBW[32 * 8 * 32];
    __shared__ float srv[HIDC];
    int tid = threadIdx.x;
    for (int i = tid; i < 32 * 8 * 32; i += 256) sBW[i] = BW[i];
    int h = tid >> 5, c = tid & 31;
    for (int r = 0; r < 4; r++) {
        int n = blockIdx.x * 4 + r;
        __syncthreads();
        if (n < Nn) srv[tid] = rowv[(size_t)n * HIDC + tid];
        __syncthreads();
        if (n < Nn) {
            float s = agg[(size_t)n * HIDC + tid];
#pragma unroll
            for (int d = 0; d < 32; d++)
                s += srv[h * 32 + d] * sBW[d * HIDC + h * 32 + c];
            On[(size_t)n * HIDC + tid] = __float2half(s);
        }
    }
}

// ---------------- launch ----------------
extern "C" void kernel_launch(void* const* d_in, const int* in_sizes, int n_in,
                              void* d_out, int out_size) {
    const float* x     = (const float*)d_in[0];
    const float* conn  = (const float*)d_in[1];
    const float* Wq    = (const float*)d_in[2];
    const float* Wk    = (const float*)d_in[3];
    const float* Wv    = (const float*)d_in[4];
    const float* Wew   = (const float*)d_in[5];
    const float* Web   = (const float*)d_in[6];
    const float* beb   = (const float*)d_in[7];
    const float* Weo   = (const float*)d_in[8];
    const float* beo   = (const float*)d_in[9];
    const float* Aw    = (const float*)d_in[10];
    const float* BW    = (const float*)d_in[11];
    const float* Wo_h  = (const float*)d_in[12];
    const float* bo_h  = (const float*)d_in[13];
    const float* Wo_e  = (const float*)d_in[14];
    const float* bo_e  = (const float*)d_in[15];
    const float* ln1hg = (const float*)d_in[16];
    const float* ln1hb = (const float*)d_in[17];
    const float* ln1eg = (const float*)d_in[18];
    const float* ln1eb = (const float*)d_in[19];
    const float* W1    = (const float*)d_in[20];
    const float* b1    = (const float*)d_in[21];
    const float* W2    = (const float*)d_in[22];
    const float* b2    = (const float*)d_in[23];
    const float* ln2hg = (const float*)d_in[24];
    const float* ln2hb = (const float*)d_in[25];
    const int*   ei    = (const int*)d_in[26];

    int Nn = in_sizes[0] / HIDC;
    int Ee = in_sizes[26] / 2;
    const int* dst = ei;
    const int* src = ei + Ee;

    float* S = nullptr;
    cudaGetSymbolAddress((void**)&S, g_scratch);

    __half* QKV  = (__half*)(S + O_QKV);
    __half* cA   = (__half*)(S + O_CA);
    __half* Oe   = (__half*)(S + O_OE);
    float*  scb  = S + O_SCB;
    float*  smax = S + O_SMAX;
    float*  ssum = S + O_SSUM;
    float*  agg  = S + O_AGG;
    float*  rowv = S + O_ROWV;
    __half* On   = (__half*)(S + O_ON);
    float*  hln  = S + O_HLN;
    __half* hlnt = (__half*)(S + O_HLNT);
    __half* ffn  = (__half*)(S + O_FFN);
    __half* xt   = (__half*)(S + O_XT);
    __half* ct   = (__half*)(S + O_CT);
    __half* wqkv = (__half*)(S + O_WQKV);
    __half* wewb = (__half*)(S + O_WEWB);
    __half* weo  = (__half*)(S + O_WEO);
    __half* woh  = (__half*)(S + O_WOH);
    __half* woe  = (__half*)(S + O_WOE);
    __half* w1   = (__half*)(S + O_W1);
    __half* w2   = (__half*)(S + O_W2);

    float* outH = (float*)d_out;
    float* outE = outH + (size_t)Nn * HIDC;

    cudaFuncSetAttribute(gemm_f16<0, 1, 0, 256>, cudaFuncAttributeMaxDynamicSharedMemorySize, G16_SMEM);
    cudaFuncSetAttribute(gemm_f16<0, 1, 1, 256>, cudaFuncAttributeMaxDynamicSharedMemorySize, G16_SMEM);
    cudaFuncSetAttribute(gemm_f16<1, 1, 0, 256>, cudaFuncAttributeMaxDynamicSharedMemorySize, G16_SMEM);
    cudaFuncSetAttribute(gemm_f16<2, 0, 0, 256>, cudaFuncAttributeMaxDynamicSharedMemorySize, G16_SMEM);
    cudaFuncSetAttribute(gemm_ln<1, 256>, cudaFuncAttributeMaxDynamicSharedMemorySize, GLN_SMEM);
    cudaFuncSetAttribute(gemm_ln<0, 256>, cudaFuncAttributeMaxDynamicSharedMemorySize, GLN_SMEM);
    cudaFuncSetAttribute(gemm_ln<0, 512>, cudaFuncAttributeMaxDynamicSharedMemorySize, GLN_SMEM);

    // prep
    pack_kernel<<<cdiv(786432, 256), 256>>>(Wq, Wk, Wv, Wew, Web, Weo, Wo_h, Wo_e, W1, W2, S);
    cvt_kernel<<<cdiv(Nn * 64, 256), 256>>>(x, xt, (long)Nn * 64);
    cvt_kernel<<<(int)cdiv((long)Ee * 64, 256), 256>>>(conn, ct, (long)Ee * 64);
    init_kernel<<<cdiv(Nn * HIDC, 256), 256>>>(agg, rowv, smax, ssum, Nn);

    int gmN = cdiv(Nn, 128);
    int gmE = cdiv(Ee, 128);

    // QKV = xt @ WqkvT  [N, 768] (half out)
    gemm_f16<0, 1, 0, 256><<<dim3(gmN, 6), 256, G16_SMEM>>>(
        xt, wqkv, nullptr, nullptr, QKV, Nn, 768,
        nullptr, nullptr, nullptr, nullptr, nullptr, nullptr);
    // fused EwEb GEMM + edge message -> cA (half)
    gemm_f16<2, 0, 0, 256><<<dim3(gmE, 4), 256, G16_SMEM>>>(
        ct, wewb, beb, nullptr, cA, Ee, 512,
        dst, src, QKV, nullptr, nullptr, nullptr);
    // Oe = cA @ WeoT + beo (half) + fused score/clamp/segment-max
    gemm_f16<0, 1, 1, 256><<<dim3(gmE, 2), 256, G16_SMEM>>>(
        cA, weo, beo, nullptr, Oe, Ee, 256,
        dst, nullptr, nullptr, Aw, scb, smax);

    ex_kernel<<<cdiv(Ee * NHEAD, 256), 256>>>(scb, smax, ssum, dst, Ee);
    scatter_kernel<<<(int)cdiv((long)Ee * 64, 256), 256>>>(scb, ssum, QKV, Oe, agg, rowv, dst, src, Ee);
    combine_kernel<<<cdiv(Nn, 4), 256>>>(agg, rowv, BW, On, Nn);

    // h path: hln = LN1h(x + On @ Wo_h + bo_h), + half copy hlnt
    gemm_ln<1, 256><<<cdiv(Nn, 64), 256, GLN_SMEM>>>(
        On, woh, bo_h, x, ln1hg, ln1hb, hln, hlnt, Nn);

    // e path: outE = LN1e(conn + Oe @ Wo_e + bo_e)
    gemm_ln<0, 256><<<cdiv(Ee, 64), 256, GLN_SMEM>>>(
        Oe, woe, bo_e, conn, ln1eg, ln1eb, outE, nullptr, Ee);

    // FFN: ffn = relu(hlnt @ W1 + b1) (half)
    gemm_f16<1, 1, 0, 256><<<dim3(gmN, 4), 256, G16_SMEM>>>(
        hlnt, w1, b1, nullptr, ffn, Nn, 512,
        nullptr, nullptr, nullptr, nullptr, nullptr, nullptr);
    // outH = LN2h(hln + ffn @ W2 + b2)  (K=512, fused)
    gemm_ln<0, 512><<<cdiv(Nn, 64), 256, GLN_SMEM>>>(
        ffn, w2, b2, hln, ln2hg, ln2hb, outH, nullptr, Nn);
}

// round 11
// speedup vs baseline: 1.5968x; 1.0225x over previous
#include <cuda_runtime.h>
#include <cuda_fp16.h>
#include <math.h>
#include <stdint.h>

#define HIDC 256
#define NHEAD 8
#define CLAMP_V 5.0f

static const int NMAXC = 50000;
static const int EMAXC = 320000;

// ---------------- scratch layout (slots sized in floats; half arrays reuse) ----
#define O_QKV  ((size_t)0)                          // N*768 (half)
#define O_CA   (O_QKV  + (size_t)NMAXC*768)         // E*256 (half)
#define O_OE   (O_CA   + (size_t)EMAXC*256)         // E*256 (half)
#define O_SCB  (O_OE   + (size_t)EMAXC*256)         // E*8  (f32)
#define O_SMAX (O_SCB  + (size_t)EMAXC*8)           // N*8  (f32)
#define O_SSUM (O_SMAX + (size_t)NMAXC*8)           // N*8  (f32)
#define O_AGG  (O_SSUM + (size_t)NMAXC*8)           // N*256 (f32)
#define O_ROWV (O_AGG  + (size_t)NMAXC*256)         // N*256 (f32)  [contiguous w/ AGG]
#define O_ON   (O_ROWV + (size_t)NMAXC*256)         // N*256 (half)
#define O_HLN  (O_ON   + (size_t)NMAXC*256)         // N*256 (f32)
#define O_HLNT (O_HLN  + (size_t)NMAXC*256)         // N*256 (half)
#define O_FFN  (O_HLNT + (size_t)NMAXC*256)         // N*512 (half)
#define O_WQKV (O_FFN  + (size_t)NMAXC*512)         // 768*256 (half, [N][K])
#define O_WEWB (O_WQKV + (size_t)768*256)           // 512*256 (half)
#define O_WEO  (O_WEWB + (size_t)512*256)           // 256*256 (half)
#define O_WOH  (O_WEO  + (size_t)256*256)           // 256*256 (half)
#define O_WOE  (O_WOH  + (size_t)256*256)           // 256*256 (half)
#define O_W1   (O_WOE  + (size_t)256*256)           // 512*256 (half)
#define O_W2   (O_W1   + (size_t)512*256)           // 256*512 (half)
#define O_TOTAL (O_W2  + (size_t)256*512)

__device__ float g_scratch[O_TOTAL];

static inline int cdiv(int a, int b) { return (a + b - 1) / b; }

// ---------------- helpers ----------------
__device__ __forceinline__ void mma_f16(float c[4], const uint32_t a[4], const uint32_t b[2]) {
    asm volatile(
        "mma.sync.aligned.m16n8k16.row.col.f32.f16.f16.f32 "
        "{%0,%1,%2,%3}, {%4,%5,%6,%7}, {%8,%9}, {%0,%1,%2,%3};"
        : "+f"(c[0]), "+f"(c[1]), "+f"(c[2]), "+f"(c[3])
        : "r"(a[0]), "r"(a[1]), "r"(a[2]), "r"(a[3]), "r"(b[0]), "r"(b[1]));
}

__device__ __forceinline__ void ldsm4(uint32_t& r0, uint32_t& r1, uint32_t& r2, uint32_t& r3,
                                      uint32_t addr) {
    asm volatile("ldmatrix.sync.aligned.m8n8.x4.shared.b16 {%0,%1,%2,%3}, [%4];"
                 : "=r"(r0), "=r"(r1), "=r"(r2), "=r"(r3) : "r"(addr));
}

__device__ __forceinline__ void cp16(uint32_t saddr, const void* g, bool pred) {
    int sz = pred ? 16 : 0;
    asm volatile("cp.async.cg.shared.global [%0], [%1], 16, %2;\n"
                 :: "r"(saddr), "l"(g), "r"(sz));
}
#define CP_COMMIT() asm volatile("cp.async.commit_group;\n" ::)
#define CP_WAIT(n)  asm volatile("cp.async.wait_group %0;\n" :: "n"(n))

__device__ __forceinline__ void atomicMaxF(float* addr, float val) {
    int* ai = (int*)addr;
    int old = *ai;
    while (__int_as_float(old) < val) {
        int assumed = old;
        old = atomicCAS(ai, assumed, __float_as_int(val));
        if (old == assumed) break;
    }
}

__device__ __forceinline__ void redv4(float* addr, float a, float b, float c, float d) {
    asm volatile("red.global.add.v4.f32 [%0], {%1, %2, %3, %4};"
                 :: "l"(addr), "f"(a), "f"(b), "f"(c), "f"(d) : "memory");
}

// ---------------- gemm_nt: K=256-resident-A fp16 GEMM ----------------
// A: [M][256] (fp32 if CVTA, else half), loaded ONCE per block into resident smem.
// B: weights [NT*128][256] half, K-major. Block loops over NT column tiles of 128.
// 256 thr = 8 warps (4m x 2n), warp tile 32x64, B double-buffered (BK=64).
// ACT: 0 plain (bias?), 1 bias+relu, 2 fused edge message
// OUTH: half out. SCORE: fused attention score (Oe GEMM).
#define SAR 264                        // A resident row stride (halves)
#define NTA_BYTES (128 * SAR * 2)      // 67584
#define SAH 72                         // B tile row stride (halves)
#define NTB_TILEH (128 * SAH)
#define NTB_BYTES (NTB_TILEH * 2)      // 18432
#define GNT_SMEM (NTA_BYTES + 2 * NTB_BYTES)  // 104448

template <int ACT, int OUTH, int SCORE, int CVTA, int NT>
__global__ __launch_bounds__(256, 2)
void gemm_nt(const void* __restrict__ Av, const __half* __restrict__ B,
             const float* __restrict__ bias,
             void* __restrict__ Cv, int M,
             const int* __restrict__ dst, const int* __restrict__ src,
             const __half* __restrict__ QKV, const float* __restrict__ Aw,
             float* __restrict__ scb, float* __restrict__ smax) {
    extern __shared__ __half smh[];
    constexpr int Ncol = NT * 128;
    constexpr int NS = 4 * NT;

    const int tid = threadIdx.x;
    const int warp = tid >> 5;
    const int lane = tid & 31;
    const int g = lane >> 2;
    const int t = lane & 3;
    const int warp_m = warp & 3;
    const int warp_n = warp >> 2;
    const int m0 = blockIdx.x * 128;

    const uint32_t sbase = (uint32_t)__cvta_generic_to_shared(smh);
    const uint32_t bbase = sbase + NTA_BYTES;

    const int srow = tid >> 3;   // 0..31
    const int sseg = tid & 7;

    const int lm_row = lane & 15;
    const int lm_k   = (lane >> 4) << 3;

    // ---- prologue ----
    if (!CVTA) {
        const __half* A = (const __half*)Av;
#pragma unroll
        for (int i = 0; i < 16; i++) {
            int idx = tid + i * 256;
            int row = idx >> 5, seg = idx & 31;
            cp16(sbase + (row * SAR + seg * 8) * 2,
                 A + (size_t)(m0 + row) * 256 + seg * 8, (m0 + row) < M);
        }
    }
    // B tile s=0 (n0=0, k-cols 0..63)
#pragma unroll
    for (int u = 0; u < 4; u++) {
        int r = srow + u * 32;
        cp16(bbase + (r * SAH + sseg * 8) * 2, B + (size_t)r * 256 + sseg * 8, true);
    }
    CP_COMMIT();
    if (CVTA) {
        // fp32 A -> registers -> half resident smem (overlaps with B DMA)
        const float* A32 = (const float*)Av;
#pragma unroll
        for (int i = 0; i < 32; i++) {
            int idx = tid + i * 256;
            int row = idx >> 6, c4 = idx & 63;
            float4 v = make_float4(0.f, 0.f, 0.f, 0.f);
            if (m0 + row < M) v = *(const float4*)&A32[(size_t)(m0 + row) * 256 + c4 * 4];
            __half2 h0 = __float22half2_rn(make_float2(v.x, v.y));
            __half2 h1 = __float22half2_rn(make_float2(v.z, v.w));
            *(__half2*)&smh[row * SAR + c4 * 4] = h0;
            *(__half2*)&smh[row * SAR + c4 * 4 + 2] = h1;
        }
    }

    float acc[2][8][4];
#pragma unroll
    for (int i = 0; i < 2; i++)
#pragma unroll
        for (int j = 0; j < 8; j++)
#pragma unroll
            for (int q = 0; q < 4; q++) acc[i][j][q] = 0.0f;

#pragma unroll
    for (int s = 0; s < NS; s++) {
        if (s + 1 < NS) {
            const int nn0 = ((s + 1) >> 2) * 128;
            const int nc0 = ((s + 1) & 3) * 64;
            const int nb = (s + 1) & 1;
#pragma unroll
            for (int u = 0; u < 4; u++) {
                int r = srow + u * 32;
                cp16(bbase + (nb * NTB_TILEH + r * SAH + sseg * 8) * 2,
                     B + (size_t)(nn0 + r) * 256 + nc0 + sseg * 8, true);
            }
            CP_COMMIT();
            CP_WAIT(1);
        } else {
            CP_WAIT(0);
        }
        __syncthreads();

        const uint32_t bbuf = bbase + (s & 1) * NTB_BYTES;
        const int kk_base = (s & 3) * 64;

#pragma unroll
        for (int ks = 0; ks < 4; ks++) {
            const int kk = kk_base + ks * 16;
            const int kkb = ks * 16;
            uint32_t af[2][4];
#pragma unroll
            for (int i = 0; i < 2; i++) {
                int rm = warp_m * 32 + i * 16;
                ldsm4(af[i][0], af[i][1], af[i][2], af[i][3],
                      sbase + ((rm + lm_row) * SAR + kk + lm_k) * 2);
            }
            uint32_t bf[8][2];
#pragma unroll
            for (int jj = 0; jj < 4; jj++) {
                int nb2 = warp_n * 64 + jj * 16;
                uint32_t r0, r1, r2, r3;
                ldsm4(r0, r1, r2, r3, bbuf + ((nb2 + lm_row) * SAH + kkb + lm_k) * 2);
                bf[2 * jj][0] = r0;     bf[2 * jj][1] = r2;
                bf[2 * jj + 1][0] = r1; bf[2 * jj + 1][1] = r3;
            }
#pragma unroll
            for (int i = 0; i < 2; i++)
#pragma unroll
                for (int j = 0; j < 8; j++)
                    mma_f16(acc[i][j], af[i], bf[j]);
        }

        if ((s & 3) == 3) {
            const int n0 = (s >> 2) * 128;
            // ---- epilogue for this column tile ----
            if (ACT == 2) {
                __half* C = (__half*)Cv;
                float bebv[8];
                int cqv[8];
#pragma unroll
                for (int j = 0; j < 8; j++) {
                    int cq = (n0 >> 1) + warp_n * 32 + j * 4 + t;
                    cqv[j] = cq;
                    bebv[j] = bias[cq];
                }
#pragma unroll
                for (int i = 0; i < 2; i++) {
#pragma unroll
                    for (int half_ = 0; half_ < 2; half_++) {
                        int r = m0 + warp_m * 32 + i * 16 + half_ * 8 + g;
                        if (r >= M) continue;
                        int dn = dst[r], sn = src[r];
                        const __half* qrow = QKV + (size_t)dn * 768;
                        const __half* krow = QKV + (size_t)sn * 768 + 256;
#pragma unroll
                        for (int j = 0; j < 8; j++) {
                            float ew = acc[i][j][half_ * 2 + 0];
                            float eb = acc[i][j][half_ * 2 + 1] + bebv[j];
                            float aqk = __half2float(qrow[cqv[j]]) + __half2float(krow[cqv[j]]);
                            float c1 = aqk * ew;
                            float c2 = copysignf(sqrtf(fabsf(c1)), c1);
                            C[(size_t)r * 256 + cqv[j]] = __float2half(fmaxf(c2 + eb, 0.f));
                        }
                    }
                }
            } else if (SCORE) {
                __half* C = (__half*)Cv;
                const int h0 = (n0 + warp_n * 64) >> 5;
                float aw0[8], aw1[8];
#pragma unroll
                for (int j4 = 0; j4 < 4; j4++) {
                    int d = j4 * 8 + 2 * t;
                    aw0[2 * j4]     = __ldg(&Aw[d * 8 + h0]);
                    aw0[2 * j4 + 1] = __ldg(&Aw[(d + 1) * 8 + h0]);
                    aw1[2 * j4]     = __ldg(&Aw[d * 8 + h0 + 1]);
                    aw1[2 * j4 + 1] = __ldg(&Aw[(d + 1) * 8 + h0 + 1]);
                }
                float2 bvj[8];
#pragma unroll
                for (int j = 0; j < 8; j++)
                    bvj[j] = *(const float2*)&bias[n0 + warp_n * 64 + j * 8 + 2 * t];
#pragma unroll
                for (int i = 0; i < 2; i++) {
#pragma unroll
                    for (int half_ = 0; half_ < 2; half_++) {
                        int r = m0 + warp_m * 32 + i * 16 + half_ * 8 + g;
                        float s0 = 0.f, s1 = 0.f;
                        if (r < M) {
#pragma unroll
                            for (int j = 0; j < 8; j++) {
                                float ox = acc[i][j][half_ * 2 + 0] + bvj[j].x;
                                float oy = acc[i][j][half_ * 2 + 1] + bvj[j].y;
                                __half2 h2v = __float22half2_rn(make_float2(ox, oy));
                                ox = __half2float(__low2half(h2v));
                                oy = __half2float(__high2half(h2v));
                                int c = n0 + warp_n * 64 + j * 8 + 2 * t;
                                *(__half2*)&C[(size_t)r * Ncol + c] = h2v;
                                if (j < 4) {
                                    s0 += ox * aw0[2 * j] + oy * aw0[2 * j + 1];
                                } else {
                                    s1 += ox * aw1[2 * (j - 4)] + oy * aw1[2 * (j - 4) + 1];
                                }
                            }
                        }
                        s0 += __shfl_xor_sync(0xffffffffu, s0, 1);
                        s0 += __shfl_xor_sync(0xffffffffu, s0, 2);
                        s1 += __shfl_xor_sync(0xffffffffu, s1, 1);
                        s1 += __shfl_xor_sync(0xffffffffu, s1, 2);
                        if (r < M && t == 0) {
                            s0 = fminf(fmaxf(s0, -CLAMP_V), CLAMP_V);
                            s1 = fminf(fmaxf(s1, -CLAMP_V), CLAMP_V);
                            scb[(size_t)r * 8 + h0] = s0;
                            scb[(size_t)r * 8 + h0 + 1] = s1;
                            int dn = dst[r];
                            atomicMaxF(&smax[dn * 8 + h0], s0);
                            atomicMaxF(&smax[dn * 8 + h0 + 1], s1);
                        }
                    }
                }
            } else {
#pragma unroll
                for (int j = 0; j < 8; j++) {
                    int c = n0 + warp_n * 64 + j * 8 + 2 * t;
                    float2 bv = make_float2(0.f, 0.f);
                    if (bias) bv = *(const float2*)&bias[c];
#pragma unroll
                    for (int i = 0; i < 2; i++) {
                        int rbase = m0 + warp_m * 32 + i * 16 + g;
#pragma unroll
                        for (int half_ = 0; half_ < 2; half_++) {
                            int r = rbase + half_ * 8;
                            if (r >= M) continue;
                            float ox = acc[i][j][half_ * 2 + 0] + bv.x;
                            float oy = acc[i][j][half_ * 2 + 1] + bv.y;
                            if (ACT == 1) { ox = fmaxf(ox, 0.f); oy = fmaxf(oy, 0.f); }
                            if (OUTH) {
                                *(__half2*)&((__half*)Cv)[(size_t)r * Ncol + c] =
                                    __float22half2_rn(make_float2(ox, oy));
                            } else {
                                *(float2*)&((float*)Cv)[(size_t)r * Ncol + c] =
                                    make_float2(ox, oy);
                            }
                        }
                    }
                }
            }
            // reset accumulators for next column tile
#pragma unroll
            for (int i = 0; i < 2; i++)
#pragma unroll
                for (int j = 0; j < 8; j++)
#pragma unroll
                    for (int q = 0; q < 4; q++) acc[i][j][q] = 0.0f;
        }
        __syncthreads();
    }
}

// ---------------- fp16 GEMM + fused residual + LayerNorm ----------------
// BM=64, BN=256 (full row), 256 thr = 8 warps (2m x 4n), warp tile 32x64.
#define LNA_TILEH (64 * SAH)
#define LNA_TILEB (LNA_TILEH * 2)
#define LNB_TILEH (256 * SAH)
#define LNB_TILEB (LNB_TILEH * 2)
#define GLN_SMEM (2 * LNA_TILEB + 2 * LNB_TILEB)

template <int OUT2, int KVAL>
__global__ __launch_bounds__(256, 2)
void gemm_ln(const __half* __restrict__ A, const __half* __restrict__ B,
             const float* __restrict__ bias, const float* __restrict__ resid,
             const float* __restrict__ lng, const float* __restrict__ lnb,
             float* __restrict__ outF, __half* __restrict__ outH, int M) {
    extern __shared__ __half smh[];
    constexpr int KT = KVAL / 64;

    const int tid = threadIdx.x;
    const int warp = tid >> 5;
    const int lane = tid & 31;
    const int g = lane >> 2;
    const int t = lane & 3;
    const int warp_m = warp & 1;
    const int warp_n = warp >> 1;
    const int m0 = blockIdx.x * 64;

    const uint32_t sbase = (uint32_t)__cvta_generic_to_shared(smh);
    const uint32_t bbase = sbase + 2 * LNA_TILEB;

    const int srow = tid >> 3;
    const int sseg = tid & 7;
    const bool apred[2] = { m0 + srow < M, m0 + srow + 32 < M };
    const __half* Aptr = A + (size_t)(m0 + srow) * KVAL + sseg * 8;
    const __half* Bptr = B + (size_t)srow * KVAL + sseg * 8;

    const int lm_row = lane & 15;
    const int lm_k   = (lane >> 4) << 3;

    float acc[2][8][4];
#pragma unroll
    for (int i = 0; i < 2; i++)
#pragma unroll
        for (int j = 0; j < 8; j++)
#pragma unroll
            for (int q = 0; q < 4; q++) acc[i][j][q] = 0.0f;

#pragma unroll
    for (int u = 0; u < 2; u++) {
        int r = srow + u * 32;
        cp16(sbase + (r * SAH + sseg * 8) * 2, Aptr + (size_t)(u * 32) * KVAL, apred[u]);
    }
#pragma unroll
    for (int u = 0; u < 8; u++) {
        int r = srow + u * 32;
        cp16(bbase + (r * SAH + sseg * 8) * 2, Bptr + (size_t)(u * 32) * KVAL, true);
    }
    CP_COMMIT();

#pragma unroll
    for (int kt = 0; kt < KT; kt++) {
        const int buf = kt & 1;
        if (kt + 1 < KT) {
            const int k0 = (kt + 1) << 6;
            const int nb = buf ^ 1;
#pragma unroll
            for (int u = 0; u < 2; u++) {
                int r = srow + u * 32;
                cp16(sbase + (nb * LNA_TILEH + r * SAH + sseg * 8) * 2,
                     Aptr + (size_t)(u * 32) * KVAL + k0, apred[u]);
            }
#pragma unroll
            for (int u = 0; u < 8; u++) {
                int r = srow + u * 32;
                cp16(bbase + (nb * LNB_TILEH + r * SAH + sseg * 8) * 2,
                     Bptr + (size_t)(u * 32) * KVAL + k0, true);
            }
            CP_COMMIT();
            CP_WAIT(1);
        } else {
            CP_WAIT(0);
        }
        __syncthreads();

        const uint32_t abuf = sbase + buf * LNA_TILEB;
        const uint32_t bbuf = bbase + buf * LNB_TILEB;

#pragma unroll
        for (int ks = 0; ks < 4; ks++) {
            const int kk = ks * 16;
            uint32_t af[2][4];
#pragma unroll
            for (int i = 0; i < 2; i++) {
                int rm = warp_m * 32 + i * 16;
                ldsm4(af[i][0], af[i][1], af[i][2], af[i][3],
                      abuf + ((rm + lm_row) * SAH + kk + lm_k) * 2);
            }
            uint32_t bf[8][2];
#pragma unroll
            for (int jj = 0; jj < 4; jj++) {
                int nb2 = warp_n * 64 + jj * 16;
                uint32_t r0, r1, r2, r3;
                ldsm4(r0, r1, r2, r3, bbuf + ((nb2 + lm_row) * SAH + kk + lm_k) * 2);
                bf[2 * jj][0] = r0;     bf[2 * jj][1] = r2;
                bf[2 * jj + 1][0] = r1; bf[2 * jj + 1][1] = r3;
            }
#pragma unroll
            for (int i = 0; i < 2; i++)
#pragma unroll
                for (int j = 0; j < 8; j++)
                    mma_f16(acc[i][j], af[i], bf[j]);
        }
        __syncthreads();
    }

    float* red = (float*)smh;

#pragma unroll
    for (int i = 0; i < 2; i++) {
#pragma unroll
        for (int half_ = 0; half_ < 2; half_++) {
            const int rl = warp_m * 32 + i * 16 + half_ * 8 + g;
            const int r = m0 + rl;
            float s = 0.f, s2 = 0.f;
            if (r < M) {
#pragma unroll
                for (int j = 0; j < 8; j++) {
                    int c = warp_n * 64 + j * 8 + 2 * t;
                    float2 bv = *(const float2*)&bias[c];
                    float2 rv = *(const float2*)&resid[(size_t)r * HIDC + c];
                    float ox = acc[i][j][half_ * 2 + 0] + bv.x + rv.x;
                    float oy = acc[i][j][half_ * 2 + 1] + bv.y + rv.y;
                    acc[i][j][half_ * 2 + 0] = ox;
                    acc[i][j][half_ * 2 + 1] = oy;
                    s += ox + oy;
                    s2 += ox * ox + oy * oy;
                }
            }
            s  += __shfl_xor_sync(0xffffffffu, s, 1);
            s  += __shfl_xor_sync(0xffffffffu, s, 2);
            s2 += __shfl_xor_sync(0xffffffffu, s2, 1);
            s2 += __shfl_xor_sync(0xffffffffu, s2, 2);
            if (t == 0) {
                red[rl * 8 + warp_n] = s;
                red[rl * 8 + 4 + warp_n] = s2;
            }
        }
    }
    __syncthreads();

#pragma unroll
    for (int i = 0; i < 2; i++) {
#pragma unroll
        for (int half_ = 0; half_ < 2; half_++) {
            const int rl = warp_m * 32 + i * 16 + half_ * 8 + g;
            const int r = m0 + rl;
            if (r >= M) continue;
            float S  = red[rl * 8 + 0] + red[rl * 8 + 1] + red[rl * 8 + 2] + red[rl * 8 + 3];
            float S2 = red[rl * 8 + 4] + red[rl * 8 + 5] + red[rl * 8 + 6] + red[rl * 8 + 7];
            float mean = S * (1.0f / HIDC);
            float var = S2 * (1.0f / HIDC) - mean * mean;
            float rstd = rsqrtf(var + 1e-5f);
#pragma unroll
            for (int j = 0; j < 8; j++) {
                int c = warp_n * 64 + j * 8 + 2 * t;
                float2 gv = *(const float2*)&lng[c];
                float2 bv = *(const float2*)&lnb[c];
                float vx = (acc[i][j][half_ * 2 + 0] - mean) * rstd * gv.x + bv.x;
                float vy = (acc[i][j][half_ * 2 + 1] - mean) * rstd * gv.y + bv.y;
                *(float2*)&outF[(size_t)r * HIDC + c] = make_float2(vx, vy);
                if (OUT2)
                    *(__half2*)&outH[(size_t)r * HIDC + c] =
                        __float22half2_rn(make_float2(vx, vy));
            }
        }
    }
}

// ---------------- weight pack: TRANSPOSED [N][K], half ----------------
__global__ void pack_kernel(const float* Wq, const float* Wk, const float* Wv,
                            const float* Wew, const float* Web, const float* Weo,
                            const float* Wo_h, const float* Wo_e,
                            const float* W1, const float* W2, float* S) {
    int i = blockIdx.x * 256 + threadIdx.x;
    if (i < 196608) {
        int n = i >> 8, k = i & 255;
        float v = (n < 256) ? Wq[k * 256 + n]
                : (n < 512) ? Wk[k * 256 + n - 256]
                            : Wv[k * 256 + n - 512];
        ((__half*)(S + O_WQKV))[i] = __float2half(v);
    }
    int i2 = i - 196608;
    if (i2 >= 0 && i2 < 131072) {
        int n = i2 >> 8, k = i2 & 255, c = n >> 1;
        float v = (n & 1) ? Web[k * 256 + c] : Wew[k * 256 + c];
        ((__half*)(S + O_WEWB))[i2] = __float2half(v);
    }
    int i3 = i - 327680;
    if (i3 >= 0 && i3 < 65536) {
        int n = i3 >> 8, k = i3 & 255;
        ((__half*)(S + O_WEO))[i3] = __float2half(Weo[k * 256 + n]);
    }
    int i4 = i - 393216;
    if (i4 >= 0 && i4 < 65536) {
        int n = i4 >> 8, k = i4 & 255;
        ((__half*)(S + O_WOH))[i4] = __float2half(Wo_h[k * 256 + n]);
    }
    int i5 = i - 458752;
    if (i5 >= 0 && i5 < 65536) {
        int n = i5 >> 8, k = i5 & 255;
        ((__half*)(S + O_WOE))[i5] = __float2half(Wo_e[k * 256 + n]);
    }
    int i6 = i - 524288;
    if (i6 >= 0 && i6 < 131072) {
        int n = i6 >> 8, k = i6 & 255;
        ((__half*)(S + O_W1))[i6] = __float2half(W1[k * 512 + n]);
    }
    int i7 = i - 655360;
    if (i7 >= 0 && i7 < 131072) {
        int n = i7 >> 9, k = i7 & 511;
        ((__half*)(S + O_W2))[i7] = __float2half(W2[k * 256 + n]);
    }
}

// ---------------- init for smax/ssum only (agg/rowv via memset) ----------------
__global__ void init2_kernel(float* smax, float* ssum, int Nn) {
    int t = blockIdx.x * 256 + threadIdx.x;
    if (t < Nn * NHEAD) { smax[t] = -CLAMP_V; ssum[t] = 0.f; }
}

// ---------------- exp + segment sum ----------------
__global__ void ex_kernel(float* __restrict__ score, const float* __restrict__ smax,
                          float* __restrict__ ssum, const int* __restrict__ dst, int E) {
    int t = blockIdx.x * 256 + threadIdx.x;
    if (t >= E * NHEAD) return;
    int e = t >> 3, h = t & 7;
    int dn = dst[e];
    float ex = expf(score[t] - smax[dn * NHEAD + h]);
    score[t] = ex;
    atomicAdd(&ssum[dn * NHEAD + h], ex);
}

// ---------------- scatter: vector RED ----------------
__global__ void scatter_kernel(const float* __restrict__ exv, const float* __restrict__ ssum,
                               const __half* __restrict__ QKV, const __half* __restrict__ Oe,
                               float* __restrict__ agg, float* __restrict__ rowv,
                               const int* __restrict__ dst, const int* __restrict__ src, int E) {
    long t = (long)blockIdx.x * 256 + threadIdx.x;
    if (t >= (long)E * 64) return;
    int e = (int)(t >> 6), q = (int)(t & 63);
    int h = q >> 3;
    int dn = dst[e], sn = src[e];
    float sc = exv[e * NHEAD + h] / (ssum[dn * NHEAD + h] + 1e-16f);
    const __half2* vp = (const __half2*)(QKV + (size_t)sn * 768 + 512 + q * 4);
    const __half2* op = (const __half2*)(Oe + (size_t)e * HIDC + q * 4);
    float2 v0 = __half22float2(vp[0]), v1 = __half22float2(vp[1]);
    float2 o0 = __half22float2(op[0]), o1 = __half22float2(op[1]);
    redv4(&agg[(size_t)dn * HIDC + q * 4], v0.x * sc, v0.y * sc, v1.x * sc, v1.y * sc);
    redv4(&rowv[(size_t)dn * HIDC + q * 4], o0.x * sc, o0.y * sc, o1.x * sc, o1.y * sc);
}

// ---------------- combine: On = half(agg + einsum(rowv, BW)), 16 rows/block ----
__global__ void combine_kernel(const float* __restrict__ agg, const float* __restrict__ rowv,
                               const float* __restrict__ BW, __half* __restrict__ On, int Nn) {
    __shared__ float sBW[32 * 8 * 32];
    __shared__ float srv[HIDC];
    int tid = threadIdx.x;
    for (int i = tid; i < 32 * 8 * 32; i += 256) sBW[i] = BW[i];
    int h = tid >> 5, c = tid & 31;
    for (int r = 0; r < 16; r++) {
        int n = blockIdx.x * 16 + r;
        __syncthreads();
        if (n < Nn) srv[tid] = rowv[(size_t)n * HIDC + tid];
        __syncthreads();
        if (n < Nn) {
            float s = agg[(size_t)n * HIDC + tid];
#pragma unroll
            for (int d = 0; d < 32; d++)
                s += srv[h * 32 + d] * sBW[d * HIDC + h * 32 + c];
            On[(size_t)n * HIDC + tid] = __float2half(s);
        }
    }
}

// ---------------- launch ----------------
extern "C" void kernel_launch(void* const* d_in, const int* in_sizes, int n_in,
                              void* d_out, int out_size) {
    const float* x     = (const float*)d_in[0];
    const float* conn  = (const float*)d_in[1];
    const float* Wq    = (const float*)d_in[2];
    const float* Wk    = (const float*)d_in[3];
    const float* Wv    = (const float*)d_in[4];
    const float* Wew   = (const float*)d_in[5];
    const float* Web   = (const float*)d_in[6];
    const float* beb   = (const float*)d_in[7];
    const float* Weo   = (const float*)d_in[8];
    const float* beo   = (const float*)d_in[9];
    const float* Aw    = (const float*)d_in[10];
    const float* BW    = (const float*)d_in[11];
    const float* Wo_h  = (const float*)d_in[12];
    const float* bo_h  = (const float*)d_in[13];
    const float* Wo_e  = (const float*)d_in[14];
    const float* bo_e  = (const float*)d_in[15];
    const float* ln1hg = (const float*)d_in[16];
    const float* ln1hb = (const float*)d_in[17];
    const float* ln1eg = (const float*)d_in[18];
    const float* ln1eb = (const float*)d_in[19];
    const float* W1    = (const float*)d_in[20];
    const float* b1    = (const float*)d_in[21];
    const float* W2    = (const float*)d_in[22];
    const float* b2    = (const float*)d_in[23];
    const float* ln2hg = (const float*)d_in[24];
    const float* ln2hb = (const float*)d_in[25];
    const int*   ei    = (const int*)d_in[26];

    int Nn = in_sizes[0] / HIDC;
    int Ee = in_sizes[26] / 2;
    const int* dst = ei;
    const int* src = ei + Ee;

    float* S = nullptr;
    cudaGetSymbolAddress((void**)&S, g_scratch);

    __half* QKV  = (__half*)(S + O_QKV);
    __half* cA   = (__half*)(S + O_CA);
    __half* Oe   = (__half*)(S + O_OE);
    float*  scb  = S + O_SCB;
    float*  smax = S + O_SMAX;
    float*  ssum = S + O_SSUM;
    float*  agg  = S + O_AGG;
    float*  rowv = S + O_ROWV;
    __half* On   = (__half*)(S + O_ON);
    float*  hln  = S + O_HLN;
    __half* hlnt = (__half*)(S + O_HLNT);
    __half* ffn  = (__half*)(S + O_FFN);
    __half* wqkv = (__half*)(S + O_WQKV);
    __half* wewb = (__half*)(S + O_WEWB);
    __half* weo  = (__half*)(S + O_WEO);
    __half* woh  = (__half*)(S + O_WOH);
    __half* woe  = (__half*)(S + O_WOE);
    __half* w1   = (__half*)(S + O_W1);
    __half* w2   = (__half*)(S + O_W2);

    float* outH = (float*)d_out;
    float* outE = outH + (size_t)Nn * HIDC;

    cudaFuncSetAttribute(gemm_nt<0, 1, 0, 1, 6>, cudaFuncAttributeMaxDynamicSharedMemorySize, GNT_SMEM);
    cudaFuncSetAttribute(gemm_nt<2, 0, 0, 1, 4>, cudaFuncAttributeMaxDynamicSharedMemorySize, GNT_SMEM);
    cudaFuncSetAttribute(gemm_nt<0, 1, 1, 0, 2>, cudaFuncAttributeMaxDynamicSharedMemorySize, GNT_SMEM);
    cudaFuncSetAttribute(gemm_nt<1, 1, 0, 0, 4>, cudaFuncAttributeMaxDynamicSharedMemorySize, GNT_SMEM);
    cudaFuncSetAttribute(gemm_ln<1, 256>, cudaFuncAttributeMaxDynamicSharedMemorySize, GLN_SMEM);
    cudaFuncSetAttribute(gemm_ln<0, 256>, cudaFuncAttributeMaxDynamicSharedMemorySize, GLN_SMEM);
    cudaFuncSetAttribute(gemm_ln<0, 512>, cudaFuncAttributeMaxDynamicSharedMemorySize, GLN_SMEM);

    // prep: pack weights, zero scatter buffers (agg+rowv contiguous), init smax/ssum
    pack_kernel<<<cdiv(786432, 256), 256>>>(Wq, Wk, Wv, Wew, Web, Weo, Wo_h, Wo_e, W1, W2, S);
    cudaMemsetAsync(agg, 0, (size_t)Nn * 512 * sizeof(float));
    init2_kernel<<<cdiv(Nn * NHEAD, 256), 256>>>(smax, ssum, Nn);

    int gmN = cdiv(Nn, 128);
    int gmE = cdiv(Ee, 128);

    // QKV = x(fp32) @ WqkvT  [N, 768] (half out)
    gemm_nt<0, 1, 0, 1, 6><<<gmN, 256, GNT_SMEM>>>(
        x, wqkv, nullptr, QKV, Nn,
        nullptr, nullptr, nullptr, nullptr, nullptr, nullptr);
    // fused EwEb GEMM + edge message: conn(fp32) -> cA (half)
    gemm_nt<2, 0, 0, 1, 4><<<gmE, 256, GNT_SMEM>>>(
        conn, wewb, beb, cA, Ee,
        dst, src, QKV, nullptr, nullptr, nullptr);
    // Oe = cA @ WeoT + beo (half) + fused score/clamp/segment-max
    gemm_nt<0, 1, 1, 0, 2><<<gmE, 256, GNT_SMEM>>>(
        cA, weo, beo, Oe, Ee,
        dst, nullptr, nullptr, Aw, scb, smax);

    ex_kernel<<<cdiv(Ee * NHEAD, 256), 256>>>(scb, smax, ssum, dst, Ee);
    scatter_kernel<<<(int)cdiv((long)Ee * 64, 256), 256>>>(scb, ssum, QKV, Oe, agg, rowv, dst, src, Ee);
    combine_kernel<<<cdiv(Nn, 16), 256>>>(agg, rowv, BW, On, Nn);

    // h path: hln = LN1h(x + On @ Wo_h + bo_h), + half copy hlnt
    gemm_ln<1, 256><<<cdiv(Nn, 64), 256, GLN_SMEM>>>(
        On, woh, bo_h, x, ln1hg, ln1hb, hln, hlnt, Nn);

    // e path: outE = LN1e(conn + Oe @ Wo_e + bo_e)
    gemm_ln<0, 256><<<cdiv(Ee, 64), 256, GLN_SMEM>>>(
        Oe, woe, bo_e, conn, ln1eg, ln1eb, outE, nullptr, Ee);

    // FFN: ffn = relu(hlnt @ W1 + b1) (half)
    gemm_nt<1, 1, 0, 0, 4><<<gmN, 256, GNT_SMEM>>>(
        hlnt, w1, b1, ffn, Nn,
        nullptr, nullptr, nullptr, nullptr, nullptr, nullptr);
    // outH = LN2h(hln + ffn @ W2 + b2)  (K=512, fused)
    gemm_ln<0, 512><<<cdiv(Nn, 64), 256, GLN_SMEM>>>(
        ffn, w2, b2, hln, ln2hg, ln2hb, outH, nullptr, Nn);
}

// round 12
// speedup vs baseline: 1.6537x; 1.0356x over previous
#include <cuda_runtime.h>
#include <cuda_fp16.h>
#include <math.h>
#include <stdint.h>

#define HIDC 256
#define NHEAD 8
#define CLAMP_V 5.0f

static const int NMAXC = 50000;
static const int EMAXC = 320000;

// ---------------- scratch layout (slots sized in floats; half arrays reuse) ----
#define O_QKV  ((size_t)0)                          // N*768 (half)
#define O_CA   (O_QKV  + (size_t)NMAXC*768)         // E*256 (half)
#define O_AQK  (O_CA   + (size_t)EMAXC*256)         // E*256 (half) -> E*128 floats used
#define O_OE   (O_AQK  + (size_t)EMAXC*128)         // E*256 (half)
#define O_SCB  (O_OE   + (size_t)EMAXC*256)         // E*8  (f32)
#define O_SMAX (O_SCB  + (size_t)EMAXC*8)           // N*8  (f32)
#define O_SSUM (O_SMAX + (size_t)NMAXC*8)           // N*8  (f32)
#define O_AGG  (O_SSUM + (size_t)NMAXC*8)           // N*256 (f32)
#define O_ROWV (O_AGG  + (size_t)NMAXC*256)         // N*256 (f32)  [contiguous w/ AGG]
#define O_ON   (O_ROWV + (size_t)NMAXC*256)         // N*256 (half)
#define O_HLN  (O_ON   + (size_t)NMAXC*256)         // N*256 (f32)
#define O_HLNT (O_HLN  + (size_t)NMAXC*256)         // N*256 (half)
#define O_FFN  (O_HLNT + (size_t)NMAXC*256)         // N*512 (half)
#define O_WQKV (O_FFN  + (size_t)NMAXC*512)         // 768*256 (half, [N][K])
#define O_WEWB (O_WQKV + (size_t)768*256)           // 512*256 (half)
#define O_WEO  (O_WEWB + (size_t)512*256)           // 256*256 (half)
#define O_WOH  (O_WEO  + (size_t)256*256)           // 256*256 (half)
#define O_WOE  (O_WOH  + (size_t)256*256)           // 256*256 (half)
#define O_W1   (O_WOE  + (size_t)256*256)           // 512*256 (half)
#define O_W2   (O_W1   + (size_t)512*256)           // 256*512 (half)
#define O_TOTAL (O_W2  + (size_t)256*512)

__device__ float g_scratch[O_TOTAL];

static inline int cdiv(int a, int b) { return (a + b - 1) / b; }

// ---------------- helpers ----------------
__device__ __forceinline__ void mma_f16(float c[4], const uint32_t a[4], const uint32_t b[2]) {
    asm volatile(
        "mma.sync.aligned.m16n8k16.row.col.f32.f16.f16.f32 "
        "{%0,%1,%2,%3}, {%4,%5,%6,%7}, {%8,%9}, {%0,%1,%2,%3};"
        : "+f"(c[0]), "+f"(c[1]), "+f"(c[2]), "+f"(c[3])
        : "r"(a[0]), "r"(a[1]), "r"(a[2]), "r"(a[3]), "r"(b[0]), "r"(b[1]));
}

__device__ __forceinline__ void ldsm4(uint32_t& r0, uint32_t& r1, uint32_t& r2, uint32_t& r3,
                                      uint32_t addr) {
    asm volatile("ldmatrix.sync.aligned.m8n8.x4.shared.b16 {%0,%1,%2,%3}, [%4];"
                 : "=r"(r0), "=r"(r1), "=r"(r2), "=r"(r3) : "r"(addr));
}

__device__ __forceinline__ void cp16(uint32_t saddr, const void* g, bool pred) {
    int sz = pred ? 16 : 0;
    asm volatile("cp.async.cg.shared.global [%0], [%1], 16, %2;\n"
                 :: "r"(saddr), "l"(g), "r"(sz));
}
#define CP_COMMIT() asm volatile("cp.async.commit_group;\n" ::)
#define CP_WAIT(n)  asm volatile("cp.async.wait_group %0;\n" :: "n"(n))

__device__ __forceinline__ void atomicMaxF(float* addr, float val) {
    int* ai = (int*)addr;
    int old = *ai;
    while (__int_as_float(old) < val) {
        int assumed = old;
        old = atomicCAS(ai, assumed, __float_as_int(val));
        if (old == assumed) break;
    }
}

__device__ __forceinline__ void redv4(float* addr, float a, float b, float c, float d) {
    asm volatile("red.global.add.v4.f32 [%0], {%1, %2, %3, %4};"
                 :: "l"(addr), "f"(a), "f"(b), "f"(c), "f"(d) : "memory");
}

// ---------------- aqk: per-edge coalesced gather  aqk[e] = Q[dst[e]] + K[src[e]] ----
__global__ void aqk_kernel(const __half* __restrict__ QKV, __half* __restrict__ aqk,
                           const int* __restrict__ dst, const int* __restrict__ src, int E) {
    int w = (blockIdx.x * 256 + threadIdx.x) >> 5;
    int lane = threadIdx.x & 31;
    if (w >= E) return;
    int dn = dst[w], sn = src[w];
    int4 qv = ((const int4*)(QKV + (size_t)dn * 768))[lane];
    int4 kv = ((const int4*)(QKV + (size_t)sn * 768 + 256))[lane];
    __half2* qh = (__half2*)&qv;
    __half2* kh = (__half2*)&kv;
    int4 out;
    __half2* oh = (__half2*)&out;
#pragma unroll
    for (int i = 0; i < 4; i++) oh[i] = __hadd2(qh[i], kh[i]);
    ((int4*)(aqk + (size_t)w * 256))[lane] = out;
}

// ---------------- gemm_nt: K=256-resident-A fp16 GEMM ----------------
// A: [M][256] (fp32 if CVTA, else half), loaded ONCE per block into resident smem.
// B: weights [NT*128][256] half, K-major. Block loops over NT column tiles of 128.
// 256 thr = 8 warps (4m x 2n), warp tile 32x64, B double-buffered (BK=64).
// ACT: 0 plain (bias?), 1 bias+relu, 2 fused edge message (AQK = dense edge-major)
// OUTH: half out. SCORE: fused attention score (Oe GEMM).
#define SAR 264                        // A resident row stride (halves)
#define NTA_BYTES (128 * SAR * 2)      // 67584
#define SAH 72                         // B tile row stride (halves)
#define NTB_TILEH (128 * SAH)
#define NTB_BYTES (NTB_TILEH * 2)      // 18432
#define GNT_SMEM (NTA_BYTES + 2 * NTB_BYTES)  // 104448

template <int ACT, int OUTH, int SCORE, int CVTA, int NT>
__global__ __launch_bounds__(256, 2)
void gemm_nt(const void* __restrict__ Av, const __half* __restrict__ B,
             const float* __restrict__ bias,
             void* __restrict__ Cv, int M,
             const int* __restrict__ dst, const int* __restrict__ src,
             const __half* __restrict__ AQK, const float* __restrict__ Aw,
             float* __restrict__ scb, float* __restrict__ smax) {
    extern __shared__ __half smh[];
    constexpr int Ncol = NT * 128;
    constexpr int NS = 4 * NT;

    const int tid = threadIdx.x;
    const int warp = tid >> 5;
    const int lane = tid & 31;
    const int g = lane >> 2;
    const int t = lane & 3;
    const int warp_m = warp & 3;
    const int warp_n = warp >> 2;
    const int m0 = blockIdx.x * 128;

    const uint32_t sbase = (uint32_t)__cvta_generic_to_shared(smh);
    const uint32_t bbase = sbase + NTA_BYTES;

    const int srow = tid >> 3;   // 0..31
    const int sseg = tid & 7;

    const int lm_row = lane & 15;
    const int lm_k   = (lane >> 4) << 3;

    // ---- prologue ----
    if (!CVTA) {
        const __half* A = (const __half*)Av;
#pragma unroll
        for (int i = 0; i < 16; i++) {
            int idx = tid + i * 256;
            int row = idx >> 5, seg = idx & 31;
            cp16(sbase + (row * SAR + seg * 8) * 2,
                 A + (size_t)(m0 + row) * 256 + seg * 8, (m0 + row) < M);
        }
    }
    // B tile s=0 (n0=0, k-cols 0..63)
#pragma unroll
    for (int u = 0; u < 4; u++) {
        int r = srow + u * 32;
        cp16(bbase + (r * SAH + sseg * 8) * 2, B + (size_t)r * 256 + sseg * 8, true);
    }
    CP_COMMIT();
    if (CVTA) {
        const float* A32 = (const float*)Av;
#pragma unroll
        for (int i = 0; i < 32; i++) {
            int idx = tid + i * 256;
            int row = idx >> 6, c4 = idx & 63;
            float4 v = make_float4(0.f, 0.f, 0.f, 0.f);
            if (m0 + row < M) v = *(const float4*)&A32[(size_t)(m0 + row) * 256 + c4 * 4];
            __half2 h0 = __float22half2_rn(make_float2(v.x, v.y));
            __half2 h1 = __float22half2_rn(make_float2(v.z, v.w));
            *(__half2*)&smh[row * SAR + c4 * 4] = h0;
            *(__half2*)&smh[row * SAR + c4 * 4 + 2] = h1;
        }
    }

    float acc[2][8][4];
#pragma unroll
    for (int i = 0; i < 2; i++)
#pragma unroll
        for (int j = 0; j < 8; j++)
#pragma unroll
            for (int q = 0; q < 4; q++) acc[i][j][q] = 0.0f;

#pragma unroll
    for (int s = 0; s < NS; s++) {
        if (s + 1 < NS) {
            const int nn0 = ((s + 1) >> 2) * 128;
            const int nc0 = ((s + 1) & 3) * 64;
            const int nb = (s + 1) & 1;
#pragma unroll
            for (int u = 0; u < 4; u++) {
                int r = srow + u * 32;
                cp16(bbase + (nb * NTB_TILEH + r * SAH + sseg * 8) * 2,
                     B + (size_t)(nn0 + r) * 256 + nc0 + sseg * 8, true);
            }
            CP_COMMIT();
            CP_WAIT(1);
        } else {
            CP_WAIT(0);
        }
        __syncthreads();

        const uint32_t bbuf = bbase + (s & 1) * NTB_BYTES;
        const int kk_base = (s & 3) * 64;

#pragma unroll
        for (int ks = 0; ks < 4; ks++) {
            const int kk = kk_base + ks * 16;
            const int kkb = ks * 16;
            uint32_t af[2][4];
#pragma unroll
            for (int i = 0; i < 2; i++) {
                int rm = warp_m * 32 + i * 16;
                ldsm4(af[i][0], af[i][1], af[i][2], af[i][3],
                      sbase + ((rm + lm_row) * SAR + kk + lm_k) * 2);
            }
            uint32_t bf[8][2];
#pragma unroll
            for (int jj = 0; jj < 4; jj++) {
                int nb2 = warp_n * 64 + jj * 16;
                uint32_t r0, r1, r2, r3;
                ldsm4(r0, r1, r2, r3, bbuf + ((nb2 + lm_row) * SAH + kkb + lm_k) * 2);
                bf[2 * jj][0] = r0;     bf[2 * jj][1] = r2;
                bf[2 * jj + 1][0] = r1; bf[2 * jj + 1][1] = r3;
            }
#pragma unroll
            for (int i = 0; i < 2; i++)
#pragma unroll
                for (int j = 0; j < 8; j++)
                    mma_f16(acc[i][j], af[i], bf[j]);
        }

        if ((s & 3) == 3) {
            const int n0 = (s >> 2) * 128;
            // ---- epilogue for this column tile ----
            if (ACT == 2) {
                __half* C = (__half*)Cv;
                float bebv[8];
                int cqv[8];
#pragma unroll
                for (int j = 0; j < 8; j++) {
                    int cq = (n0 >> 1) + warp_n * 32 + j * 4 + t;
                    cqv[j] = cq;
                    bebv[j] = bias[cq];
                }
#pragma unroll
                for (int i = 0; i < 2; i++) {
#pragma unroll
                    for (int half_ = 0; half_ < 2; half_++) {
                        int r = m0 + warp_m * 32 + i * 16 + half_ * 8 + g;
                        if (r >= M) continue;
                        const __half* arow = AQK + (size_t)r * 256;
#pragma unroll
                        for (int j = 0; j < 8; j++) {
                            float ew = acc[i][j][half_ * 2 + 0];
                            float eb = acc[i][j][half_ * 2 + 1] + bebv[j];
                            float aqk = __half2float(arow[cqv[j]]);
                            float c1 = aqk * ew;
                            float c2 = copysignf(sqrtf(fabsf(c1)), c1);
                            C[(size_t)r * 256 + cqv[j]] = __float2half(fmaxf(c2 + eb, 0.f));
                        }
                    }
                }
            } else if (SCORE) {
                __half* C = (__half*)Cv;
                const int h0 = (n0 + warp_n * 64) >> 5;
                float aw0[8], aw1[8];
#pragma unroll
                for (int j4 = 0; j4 < 4; j4++) {
                    int d = j4 * 8 + 2 * t;
                    aw0[2 * j4]     = __ldg(&Aw[d * 8 + h0]);
                    aw0[2 * j4 + 1] = __ldg(&Aw[(d + 1) * 8 + h0]);
                    aw1[2 * j4]     = __ldg(&Aw[d * 8 + h0 + 1]);
                    aw1[2 * j4 + 1] = __ldg(&Aw[(d + 1) * 8 + h0 + 1]);
                }
                float2 bvj[8];
#pragma unroll
                for (int j = 0; j < 8; j++)
                    bvj[j] = *(const float2*)&bias[n0 + warp_n * 64 + j * 8 + 2 * t];
#pragma unroll
                for (int i = 0; i < 2; i++) {
#pragma unroll
                    for (int half_ = 0; half_ < 2; half_++) {
                        int r = m0 + warp_m * 32 + i * 16 + half_ * 8 + g;
                        float s0 = 0.f, s1 = 0.f;
                        if (r < M) {
#pragma unroll
                            for (int j = 0; j < 8; j++) {
                                float ox = acc[i][j][half_ * 2 + 0] + bvj[j].x;
                                float oy = acc[i][j][half_ * 2 + 1] + bvj[j].y;
                                __half2 h2v = __float22half2_rn(make_float2(ox, oy));
                                ox = __half2float(__low2half(h2v));
                                oy = __half2float(__high2half(h2v));
                                int c = n0 + warp_n * 64 + j * 8 + 2 * t;
                                *(__half2*)&C[(size_t)r * Ncol + c] = h2v;
                                if (j < 4) {
                                    s0 += ox * aw0[2 * j] + oy * aw0[2 * j + 1];
                                } else {
                                    s1 += ox * aw1[2 * (j - 4)] + oy * aw1[2 * (j - 4) + 1];
                                }
                            }
                        }
                        s0 += __shfl_xor_sync(0xffffffffu, s0, 1);
                        s0 += __shfl_xor_sync(0xffffffffu, s0, 2);
                        s1 += __shfl_xor_sync(0xffffffffu, s1, 1);
                        s1 += __shfl_xor_sync(0xffffffffu, s1, 2);
                        if (r < M && t == 0) {
                            s0 = fminf(fmaxf(s0, -CLAMP_V), CLAMP_V);
                            s1 = fminf(fmaxf(s1, -CLAMP_V), CLAMP_V);
                            scb[(size_t)r * 8 + h0] = s0;
                            scb[(size_t)r * 8 + h0 + 1] = s1;
                            int dn = dst[r];
                            atomicMaxF(&smax[dn * 8 + h0], s0);
                            atomicMaxF(&smax[dn * 8 + h0 + 1], s1);
                        }
                    }
                }
            } else {
#pragma unroll
                for (int j = 0; j < 8; j++) {
                    int c = n0 + warp_n * 64 + j * 8 + 2 * t;
                    float2 bv = make_float2(0.f, 0.f);
                    if (bias) bv = *(const float2*)&bias[c];
#pragma unroll
                    for (int i = 0; i < 2; i++) {
                        int rbase = m0 + warp_m * 32 + i * 16 + g;
#pragma unroll
                        for (int half_ = 0; half_ < 2; half_++) {
                            int r = rbase + half_ * 8;
                            if (r >= M) continue;
                            float ox = acc[i][j][half_ * 2 + 0] + bv.x;
                            float oy = acc[i][j][half_ * 2 + 1] + bv.y;
                            if (ACT == 1) { ox = fmaxf(ox, 0.f); oy = fmaxf(oy, 0.f); }
                            if (OUTH) {
                                *(__half2*)&((__half*)Cv)[(size_t)r * Ncol + c] =
                                    __float22half2_rn(make_float2(ox, oy));
                            } else {
                                *(float2*)&((float*)Cv)[(size_t)r * Ncol + c] =
                                    make_float2(ox, oy);
                            }
                        }
                    }
                }
            }
            // reset accumulators for next column tile
#pragma unroll
            for (int i = 0; i < 2; i++)
#pragma unroll
                for (int j = 0; j < 8; j++)
#pragma unroll
                    for (int q = 0; q < 4; q++) acc[i][j][q] = 0.0f;
        }
        __syncthreads();
    }
}

// ---------------- fp16 GEMM + fused residual + LayerNorm ----------------
// BM=64, BN=256 (full row), 256 thr = 8 warps (2m x 4n), warp tile 32x64.
#define LNA_TILEH (64 * SAH)
#define LNA_TILEB (LNA_TILEH * 2)
#define LNB_TILEH (256 * SAH)
#define LNB_TILEB (LNB_TILEH * 2)
#define GLN_SMEM (2 * LNA_TILEB + 2 * LNB_TILEB)

template <int OUT2, int KVAL>
__global__ __launch_bounds__(256, 2)
void gemm_ln(const __half* __restrict__ A, const __half* __restrict__ B,
             const float* __restrict__ bias, const float* __restrict__ resid,
             const float* __restrict__ lng, const float* __restrict__ lnb,
             float* __restrict__ outF, __half* __restrict__ outH, int M) {
    extern __shared__ __half smh[];
    constexpr int KT = KVAL / 64;

    const int tid = threadIdx.x;
    const int warp = tid >> 5;
    const int lane = tid & 31;
    const int g = lane >> 2;
    const int t = lane & 3;
    const int warp_m = warp & 1;
    const int warp_n = warp >> 1;
    const int m0 = blockIdx.x * 64;

    const uint32_t sbase = (uint32_t)__cvta_generic_to_shared(smh);
    const uint32_t bbase = sbase + 2 * LNA_TILEB;

    const int srow = tid >> 3;
    const int sseg = tid & 7;
    const bool apred[2] = { m0 + srow < M, m0 + srow + 32 < M };
    const __half* Aptr = A + (size_t)(m0 + srow) * KVAL + sseg * 8;
    const __half* Bptr = B + (size_t)srow * KVAL + sseg * 8;

    const int lm_row = lane & 15;
    const int lm_k   = (lane >> 4) << 3;

    float acc[2][8][4];
#pragma unroll
    for (int i = 0; i < 2; i++)
#pragma unroll
        for (int j = 0; j < 8; j++)
#pragma unroll
            for (int q = 0; q < 4; q++) acc[i][j][q] = 0.0f;

#pragma unroll
    for (int u = 0; u < 2; u++) {
        int r = srow + u * 32;
        cp16(sbase + (r * SAH + sseg * 8) * 2, Aptr + (size_t)(u * 32) * KVAL, apred[u]);
    }
#pragma unroll
    for (int u = 0; u < 8; u++) {
        int r = srow + u * 32;
        cp16(bbase + (r * SAH + sseg * 8) * 2, Bptr + (size_t)(u * 32) * KVAL, true);
    }
    CP_COMMIT();

#pragma unroll
    for (int kt = 0; kt < KT; kt++) {
        const int buf = kt & 1;
        if (kt + 1 < KT) {
            const int k0 = (kt + 1) << 6;
            const int nb = buf ^ 1;
#pragma unroll
            for (int u = 0; u < 2; u++) {
                int r = srow + u * 32;
                cp16(sbase + (nb * LNA_TILEH + r * SAH + sseg * 8) * 2,
                     Aptr + (size_t)(u * 32) * KVAL + k0, apred[u]);
            }
#pragma unroll
            for (int u = 0; u < 8; u++) {
                int r = srow + u * 32;
                cp16(bbase + (nb * LNB_TILEH + r * SAH + sseg * 8) * 2,
                     Bptr + (size_t)(u * 32) * KVAL + k0, true);
            }
            CP_COMMIT();
            CP_WAIT(1);
        } else {
            CP_WAIT(0);
        }
        __syncthreads();

        const uint32_t abuf = sbase + buf * LNA_TILEB;
        const uint32_t bbuf = bbase + buf * LNB_TILEB;

#pragma unroll
        for (int ks = 0; ks < 4; ks++) {
            const int kk = ks * 16;
            uint32_t af[2][4];
#pragma unroll
            for (int i = 0; i < 2; i++) {
                int rm = warp_m * 32 + i * 16;
                ldsm4(af[i][0], af[i][1], af[i][2], af[i][3],
                      abuf + ((rm + lm_row) * SAH + kk + lm_k) * 2);
            }
            uint32_t bf[8][2];
#pragma unroll
            for (int jj = 0; jj < 4; jj++) {
                int nb2 = warp_n * 64 + jj * 16;
                uint32_t r0, r1, r2, r3;
                ldsm4(r0, r1, r2, r3, bbuf + ((nb2 + lm_row) * SAH + kk + lm_k) * 2);
                bf[2 * jj][0] = r0;     bf[2 * jj][1] = r2;
                bf[2 * jj + 1][0] = r1; bf[2 * jj + 1][1] = r3;
            }
#pragma unroll
            for (int i = 0; i < 2; i++)
#pragma unroll
                for (int j = 0; j < 8; j++)
                    mma_f16(acc[i][j], af[i], bf[j]);
        }
        __syncthreads();
    }

    float* red = (float*)smh;

#pragma unroll
    for (int i = 0; i < 2; i++) {
#pragma unroll
        for (int half_ = 0; half_ < 2; half_++) {
            const int rl = warp_m * 32 + i * 16 + half_ * 8 + g;
            const int r = m0 + rl;
            float s = 0.f, s2 = 0.f;
            if (r < M) {
#pragma unroll
                for (int j = 0; j < 8; j++) {
                    int c = warp_n * 64 + j * 8 + 2 * t;
                    float2 bv = *(const float2*)&bias[c];
                    float2 rv = *(const float2*)&resid[(size_t)r * HIDC + c];
                    float ox = acc[i][j][half_ * 2 + 0] + bv.x + rv.x;
                    float oy = acc[i][j][half_ * 2 + 1] + bv.y + rv.y;
                    acc[i][j][half_ * 2 + 0] = ox;
                    acc[i][j][half_ * 2 + 1] = oy;
                    s += ox + oy;
                    s2 += ox * ox + oy * oy;
                }
            }
            s  += __shfl_xor_sync(0xffffffffu, s, 1);
            s  += __shfl_xor_sync(0xffffffffu, s, 2);
            s2 += __shfl_xor_sync(0xffffffffu, s2, 1);
            s2 += __shfl_xor_sync(0xffffffffu, s2, 2);
            if (t == 0) {
                red[rl * 8 + warp_n] = s;
                red[rl * 8 + 4 + warp_n] = s2;
            }
        }
    }
    __syncthreads();

#pragma unroll
    for (int i = 0; i < 2; i++) {
#pragma unroll
        for (int half_ = 0; half_ < 2; half_++) {
            const int rl = warp_m * 32 + i * 16 + half_ * 8 + g;
            const int r = m0 + rl;
            if (r >= M) continue;
            float S  = red[rl * 8 + 0] + red[rl * 8 + 1] + red[rl * 8 + 2] + red[rl * 8 + 3];
            float S2 = red[rl * 8 + 4] + red[rl * 8 + 5] + red[rl * 8 + 6] + red[rl * 8 + 7];
            float mean = S * (1.0f / HIDC);
            float var = S2 * (1.0f / HIDC) - mean * mean;
            float rstd = rsqrtf(var + 1e-5f);
#pragma unroll
            for (int j = 0; j < 8; j++) {
                int c = warp_n * 64 + j * 8 + 2 * t;
                float2 gv = *(const float2*)&lng[c];
                float2 bv = *(const float2*)&lnb[c];
                float vx = (acc[i][j][half_ * 2 + 0] - mean) * rstd * gv.x + bv.x;
                float vy = (acc[i][j][half_ * 2 + 1] - mean) * rstd * gv.y + bv.y;
                *(float2*)&outF[(size_t)r * HIDC + c] = make_float2(vx, vy);
                if (OUT2)
                    *(__half2*)&outH[(size_t)r * HIDC + c] =
                        __float22half2_rn(make_float2(vx, vy));
            }
        }
    }
}

// ---------------- weight pack: TRANSPOSED [N][K], half ----------------
__global__ void pack_kernel(const float* Wq, const float* Wk, const float* Wv,
                            const float* Wew, const float* Web, const float* Weo,
                            const float* Wo_h, const float* Wo_e,
                            const float* W1, const float* W2, float* S) {
    int i = blockIdx.x * 256 + threadIdx.x;
    if (i < 196608) {
        int n = i >> 8, k = i & 255;
        float v = (n < 256) ? Wq[k * 256 + n]
                : (n < 512) ? Wk[k * 256 + n - 256]
                            : Wv[k * 256 + n - 512];
        ((__half*)(S + O_WQKV))[i] = __float2half(v);
    }
    int i2 = i - 196608;
    if (i2 >= 0 && i2 < 131072) {
        int n = i2 >> 8, k = i2 & 255, c = n >> 1;
        float v = (n & 1) ? Web[k * 256 + c] : Wew[k * 256 + c];
        ((__half*)(S + O_WEWB))[i2] = __float2half(v);
    }
    int i3 = i - 327680;
    if (i3 >= 0 && i3 < 65536) {
        int n = i3 >> 8, k = i3 & 255;
        ((__half*)(S + O_WEO))[i3] = __float2half(Weo[k * 256 + n]);
    }
    int i4 = i - 393216;
    if (i4 >= 0 && i4 < 65536) {
        int n = i4 >> 8, k = i4 & 255;
        ((__half*)(S + O_WOH))[i4] = __float2half(Wo_h[k * 256 + n]);
    }
    int i5 = i - 458752;
    if (i5 >= 0 && i5 < 65536) {
        int n = i5 >> 8, k = i5 & 255;
        ((__half*)(S + O_WOE))[i5] = __float2half(Wo_e[k * 256 + n]);
    }
    int i6 = i - 524288;
    if (i6 >= 0 && i6 < 131072) {
        int n = i6 >> 8, k = i6 & 255;
        ((__half*)(S + O_W1))[i6] = __float2half(W1[k * 512 + n]);
    }
    int i7 = i - 655360;
    if (i7 >= 0 && i7 < 131072) {
        int n = i7 >> 9, k = i7 & 511;
        ((__half*)(S + O_W2))[i7] = __float2half(W2[k * 256 + n]);
    }
}

// ---------------- init for smax/ssum only (agg/rowv via memset) ----------------
__global__ void init2_kernel(float* smax, float* ssum, int Nn) {
    int t = blockIdx.x * 256 + threadIdx.x;
    if (t < Nn * NHEAD) { smax[t] = -CLAMP_V; ssum[t] = 0.f; }
}

// ---------------- exp + segment sum ----------------
__global__ void ex_kernel(float* __restrict__ score, const float* __restrict__ smax,
                          float* __restrict__ ssum, const int* __restrict__ dst, int E) {
    int t = blockIdx.x * 256 + threadIdx.x;
    if (t >= E * NHEAD) return;
    int e = t >> 3, h = t & 7;
    int dn = dst[e];
    float ex = expf(score[t] - smax[dn * NHEAD + h]);
    score[t] = ex;
    atomicAdd(&ssum[dn * NHEAD + h], ex);
}

// ---------------- scatter: vector RED ----------------
__global__ void scatter_kernel(const float* __restrict__ exv, const float* __restrict__ ssum,
                               const __half* __restrict__ QKV, const __half* __restrict__ Oe,
                               float* __restrict__ agg, float* __restrict__ rowv,
                               const int* __restrict__ dst, const int* __restrict__ src, int E) {
    long t = (long)blockIdx.x * 256 + threadIdx.x;
    if (t >= (long)E * 64) return;
    int e = (int)(t >> 6), q = (int)(t & 63);
    int h = q >> 3;
    int dn = dst[e], sn = src[e];
    float sc = exv[e * NHEAD + h] / (ssum[dn * NHEAD + h] + 1e-16f);
    const __half2* vp = (const __half2*)(QKV + (size_t)sn * 768 + 512 + q * 4);
    const __half2* op = (const __half2*)(Oe + (size_t)e * HIDC + q * 4);
    float2 v0 = __half22float2(vp[0]), v1 = __half22float2(vp[1]);
    float2 o0 = __half22float2(op[0]), o1 = __half22float2(op[1]);
    redv4(&agg[(size_t)dn * HIDC + q * 4], v0.x * sc, v0.y * sc, v1.x * sc, v1.y * sc);
    redv4(&rowv[(size_t)dn * HIDC + q * 4], o0.x * sc, o0.y * sc, o1.x * sc, o1.y * sc);
}

// ---------------- combine: On = half(agg + einsum(rowv, BW)), 16 rows/block ----
__global__ void combine_kernel(const float* __restrict__ agg, const float* __restrict__ rowv,
                               const float* __restrict__ BW, __half* __restrict__ On, int Nn) {
    __shared__ float sBW[32 * 8 * 32];
    __shared__ float srv[HIDC];
    int tid = threadIdx.x;
    for (int i = tid; i < 32 * 8 * 32; i += 256) sBW[i] = BW[i];
    int h = tid >> 5, c = tid & 31;
    for (int r = 0; r < 16; r++) {
        int n = blockIdx.x * 16 + r;
        __syncthreads();
        if (n < Nn) srv[tid] = rowv[(size_t)n * HIDC + tid];
        __syncthreads();
        if (n < Nn) {
            float s = agg[(size_t)n * HIDC + tid];
#pragma unroll
            for (int d = 0; d < 32; d++)
                s += srv[h * 32 + d] * sBW[d * HIDC + h * 32 + c];
            On[(size_t)n * HIDC + tid] = __float2half(s);
        }
    }
}

// ---------------- launch ----------------
extern "C" void kernel_launch(void* const* d_in, const int* in_sizes, int n_in,
                              void* d_out, int out_size) {
    const float* x     = (const float*)d_in[0];
    const float* conn  = (const float*)d_in[1];
    const float* Wq    = (const float*)d_in[2];
    const float* Wk    = (const float*)d_in[3];
    const float* Wv    = (const float*)d_in[4];
    const float* Wew   = (const float*)d_in[5];
    const float* Web   = (const float*)d_in[6];
    const float* beb   = (const float*)d_in[7];
    const float* Weo   = (const float*)d_in[8];
    const float* beo   = (const float*)d_in[9];
    const float* Aw    = (const float*)d_in[10];
    const float* BW    = (const float*)d_in[11];
    const float* Wo_h  = (const float*)d_in[12];
    const float* bo_h  = (const float*)d_in[13];
    const float* Wo_e  = (const float*)d_in[14];
    const float* bo_e  = (const float*)d_in[15];
    const float* ln1hg = (const float*)d_in[16];
    const float* ln1hb = (const float*)d_in[17];
    const float* ln1eg = (const float*)d_in[18];
    const float* ln1eb = (const float*)d_in[19];
    const float* W1    = (const float*)d_in[20];
    const float* b1    = (const float*)d_in[21];
    const float* W2    = (const float*)d_in[22];
    const float* b2    = (const float*)d_in[23];
    const float* ln2hg = (const float*)d_in[24];
    const float* ln2hb = (const float*)d_in[25];
    const int*   ei    = (const int*)d_in[26];

    int Nn = in_sizes[0] / HIDC;
    int Ee = in_sizes[26] / 2;
    const int* dst = ei;
    const int* src = ei + Ee;

    float* S = nullptr;
    cudaGetSymbolAddress((void**)&S, g_scratch);

    __half* QKV  = (__half*)(S + O_QKV);
    __half* cA   = (__half*)(S + O_CA);
    __half* aqk  = (__half*)(S + O_AQK);
    __half* Oe   = (__half*)(S + O_OE);
    float*  scb  = S + O_SCB;
    float*  smax = S + O_SMAX;
    float*  ssum = S + O_SSUM;
    float*  agg  = S + O_AGG;
    float*  rowv = S + O_ROWV;
    __half* On   = (__half*)(S + O_ON);
    float*  hln  = S + O_HLN;
    __half* hlnt = (__half*)(S + O_HLNT);
    __half* ffn  = (__half*)(S + O_FFN);
    __half* wqkv = (__half*)(S + O_WQKV);
    __half* wewb = (__half*)(S + O_WEWB);
    __half* weo  = (__half*)(S + O_WEO);
    __half* woh  = (__half*)(S + O_WOH);
    __half* woe  = (__half*)(S + O_WOE);
    __half* w1   = (__half*)(S + O_W1);
    __half* w2   = (__half*)(S + O_W2);

    float* outH = (float*)d_out;
    float* outE = outH + (size_t)Nn * HIDC;

    cudaFuncSetAttribute(gemm_nt<0, 1, 0, 1, 6>, cudaFuncAttributeMaxDynamicSharedMemorySize, GNT_SMEM);
    cudaFuncSetAttribute(gemm_nt<2, 0, 0, 1, 4>, cudaFuncAttributeMaxDynamicSharedMemorySize, GNT_SMEM);
    cudaFuncSetAttribute(gemm_nt<0, 1, 1, 0, 2>, cudaFuncAttributeMaxDynamicSharedMemorySize, GNT_SMEM);
    cudaFuncSetAttribute(gemm_nt<1, 1, 0, 0, 4>, cudaFuncAttributeMaxDynamicSharedMemorySize, GNT_SMEM);
    cudaFuncSetAttribute(gemm_ln<1, 256>, cudaFuncAttributeMaxDynamicSharedMemorySize, GLN_SMEM);
    cudaFuncSetAttribute(gemm_ln<0, 256>, cudaFuncAttributeMaxDynamicSharedMemorySize, GLN_SMEM);
    cudaFuncSetAttribute(gemm_ln<0, 512>, cudaFuncAttributeMaxDynamicSharedMemorySize, GLN_SMEM);

    // prep: pack weights, zero scatter buffers (agg+rowv contiguous), init smax/ssum
    pack_kernel<<<cdiv(786432, 256), 256>>>(Wq, Wk, Wv, Wew, Web, Weo, Wo_h, Wo_e, W1, W2, S);
    cudaMemsetAsync(agg, 0, (size_t)Nn * 512 * sizeof(float));
    init2_kernel<<<cdiv(Nn * NHEAD, 256), 256>>>(smax, ssum, Nn);

    int gmN = cdiv(Nn, 128);
    int gmE = cdiv(Ee, 128);

    // QKV = x(fp32) @ WqkvT  [N, 768] (half out)
    gemm_nt<0, 1, 0, 1, 6><<<gmN, 256, GNT_SMEM>>>(
        x, wqkv, nullptr, QKV, Nn,
        nullptr, nullptr, nullptr, nullptr, nullptr, nullptr);
    // aqk[e] = Q[dst[e]] + K[src[e]]  (coalesced per-edge gather, half)
    aqk_kernel<<<cdiv(Ee, 8), 256>>>(QKV, aqk, dst, src, Ee);
    // fused EwEb GEMM + edge message (reads dense aqk): conn(fp32) -> cA (half)
    gemm_nt<2, 0, 0, 1, 4><<<gmE, 256, GNT_SMEM>>>(
        conn, wewb, beb, cA, Ee,
        dst, src, aqk, nullptr, nullptr, nullptr);
    // Oe = cA @ WeoT + beo (half) + fused score/clamp/segment-max
    gemm_nt<0, 1, 1, 0, 2><<<gmE, 256, GNT_SMEM>>>(
        cA, weo, beo, Oe, Ee,
        dst, nullptr, nullptr, Aw, scb, smax);

    ex_kernel<<<cdiv(Ee * NHEAD, 256), 256>>>(scb, smax, ssum, dst, Ee);
    scatter_kernel<<<(int)cdiv((long)Ee * 64, 256), 256>>>(scb, ssum, QKV, Oe, agg, rowv, dst, src, Ee);
    combine_kernel<<<cdiv(Nn, 16), 256>>>(agg, rowv, BW, On, Nn);

    // h path: hln = LN1h(x + On @ Wo_h + bo_h), + half copy hlnt
    gemm_ln<1, 256><<<cdiv(Nn, 64), 256, GLN_SMEM>>>(
        On, woh, bo_h, x, ln1hg, ln1hb, hln, hlnt, Nn);

    // e path: outE = LN1e(conn + Oe @ Wo_e + bo_e)
    gemm_ln<0, 256><<<cdiv(Ee, 64), 256, GLN_SMEM>>>(
        Oe, woe, bo_e, conn, ln1eg, ln1eb, outE, nullptr, Ee);

    // FFN: ffn = relu(hlnt @ W1 + b1) (half)
    gemm_nt<1, 1, 0, 0, 4><<<gmN, 256, GNT_SMEM>>>(
        hlnt, w1, b1, ffn, Nn,
        nullptr, nullptr, nullptr, nullptr, nullptr, nullptr);
    // outH = LN2h(hln + ffn @ W2 + b2)  (K=512, fused)
    gemm_ln<0, 512><<<cdiv(Nn, 64), 256, GLN_SMEM>>>(
        ffn, w2, b2, hln, ln2hg, ln2hb, outH, nullptr, Nn);
}

// round 13
// speedup vs baseline: 1.6730x; 1.0117x over previous
#include <cuda_runtime.h>
#include <cuda_fp16.h>
#include <math.h>
#include <stdint.h>

#define HIDC 256
#define NHEAD 8
#define CLAMP_V 5.0f

static const int NMAXC = 50000;
static const int EMAXC = 320000;

// ---------------- scratch layout (slots sized in floats; half arrays reuse) ----
#define O_QKV  ((size_t)0)                          // N*768 (half)
#define O_CA   (O_QKV  + (size_t)NMAXC*768)         // E*256 (half)
#define O_AQK  (O_CA   + (size_t)EMAXC*256)         // E*256 (half) -> E*128 floats used
#define O_OE   (O_AQK  + (size_t)EMAXC*128)         // E*256 (half)
#define O_SCB  (O_OE   + (size_t)EMAXC*256)         // E*8  (f32)
#define O_SMAX (O_SCB  + (size_t)EMAXC*8)           // N*8  (f32)
#define O_SSUM (O_SMAX + (size_t)NMAXC*8)           // N*8  (f32)
#define O_AGG  (O_SSUM + (size_t)NMAXC*8)           // N*256 (f32)
#define O_ROWV (O_AGG  + (size_t)NMAXC*256)         // N*256 (f32)  [contiguous w/ AGG]
#define O_ON   (O_ROWV + (size_t)NMAXC*256)         // N*256 (half)
#define O_HLN  (O_ON   + (size_t)NMAXC*256)         // N*256 (f32)
#define O_HLNT (O_HLN  + (size_t)NMAXC*256)         // N*256 (half)
#define O_FFN  (O_HLNT + (size_t)NMAXC*256)         // N*512 (half)
#define O_WQKV (O_FFN  + (size_t)NMAXC*512)         // 768*256 (half, [N][K])
#define O_WEWB (O_WQKV + (size_t)768*256)           // 512*256 (half)
#define O_WEO  (O_WEWB + (size_t)512*256)           // 256*256 (half)
#define O_WOH  (O_WEO  + (size_t)256*256)           // 256*256 (half)
#define O_WOE  (O_WOH  + (size_t)256*256)           // 256*256 (half)
#define O_W1   (O_WOE  + (size_t)256*256)           // 512*256 (half)
#define O_W2   (O_W1   + (size_t)512*256)           // 256*512 (half)
#define O_TOTAL (O_W2  + (size_t)256*512)

__device__ float g_scratch[O_TOTAL];

static inline int cdiv(int a, int b) { return (a + b - 1) / b; }

// ---------------- helpers ----------------
__device__ __forceinline__ void mma_f16(float c[4], const uint32_t a[4], const uint32_t b[2]) {
    asm volatile(
        "mma.sync.aligned.m16n8k16.row.col.f32.f16.f16.f32 "
        "{%0,%1,%2,%3}, {%4,%5,%6,%7}, {%8,%9}, {%0,%1,%2,%3};"
        : "+f"(c[0]), "+f"(c[1]), "+f"(c[2]), "+f"(c[3])
        : "r"(a[0]), "r"(a[1]), "r"(a[2]), "r"(a[3]), "r"(b[0]), "r"(b[1]));
}

__device__ __forceinline__ void ldsm4(uint32_t& r0, uint32_t& r1, uint32_t& r2, uint32_t& r3,
                                      uint32_t addr) {
    asm volatile("ldmatrix.sync.aligned.m8n8.x4.shared.b16 {%0,%1,%2,%3}, [%4];"
                 : "=r"(r0), "=r"(r1), "=r"(r2), "=r"(r3) : "r"(addr));
}

__device__ __forceinline__ void cp16(uint32_t saddr, const void* g, bool pred) {
    int sz = pred ? 16 : 0;
    asm volatile("cp.async.cg.shared.global [%0], [%1], 16, %2;\n"
                 :: "r"(saddr), "l"(g), "r"(sz));
}
#define CP_COMMIT() asm volatile("cp.async.commit_group;\n" ::)
#define CP_WAIT(n)  asm volatile("cp.async.wait_group %0;\n" :: "n"(n))

__device__ __forceinline__ void atomicMaxF(float* addr, float val) {
    int* ai = (int*)addr;
    int old = *ai;
    while (__int_as_float(old) < val) {
        int assumed = old;
        old = atomicCAS(ai, assumed, __float_as_int(val));
        if (old == assumed) break;
    }
}

__device__ __forceinline__ void redv4(float* addr, float a, float b, float c, float d) {
    asm volatile("red.global.add.v4.f32 [%0], {%1, %2, %3, %4};"
                 :: "l"(addr), "f"(a), "f"(b), "f"(c), "f"(d) : "memory");
}

// ---------------- aqk: per-edge coalesced gather  aqk[e] = Q[dst[e]] + K[src[e]] ----
__global__ void aqk_kernel(const __half* __restrict__ QKV, __half* __restrict__ aqk,
                           const int* __restrict__ dst, const int* __restrict__ src, int E) {
    int w = (blockIdx.x * 256 + threadIdx.x) >> 5;
    int lane = threadIdx.x & 31;
    if (w >= E) return;
    int dn = dst[w], sn = src[w];
    int4 qv = ((const int4*)(QKV + (size_t)dn * 768))[lane];
    int4 kv = ((const int4*)(QKV + (size_t)sn * 768 + 256))[lane];
    __half2* qh = (__half2*)&qv;
    __half2* kh = (__half2*)&kv;
    int4 out;
    __half2* oh = (__half2*)&out;
#pragma unroll
    for (int i = 0; i < 4; i++) oh[i] = __hadd2(qh[i], kh[i]);
    ((int4*)(aqk + (size_t)w * 256))[lane] = out;
}

// ---------------- gemm_nt: K=256-resident-A fp16 GEMM ----------------
#define SAR 264
#define NTA_BYTES (128 * SAR * 2)
#define SAH 72
#define NTB_TILEH (128 * SAH)
#define NTB_BYTES (NTB_TILEH * 2)
#define GNT_SMEM (NTA_BYTES + 2 * NTB_BYTES)

template <int ACT, int OUTH, int SCORE, int CVTA, int NT>
__global__ __launch_bounds__(256, 2)
void gemm_nt(const void* __restrict__ Av, const __half* __restrict__ B,
             const float* __restrict__ bias,
             void* __restrict__ Cv, int M,
             const int* __restrict__ dst, const int* __restrict__ src,
             const __half* __restrict__ AQK, const float* __restrict__ Aw,
             float* __restrict__ scb, float* __restrict__ smax) {
    extern __shared__ __half smh[];
    constexpr int Ncol = NT * 128;
    constexpr int NS = 4 * NT;

    const int tid = threadIdx.x;
    const int warp = tid >> 5;
    const int lane = tid & 31;
    const int g = lane >> 2;
    const int t = lane & 3;
    const int warp_m = warp & 3;
    const int warp_n = warp >> 2;
    const int m0 = blockIdx.x * 128;

    const uint32_t sbase = (uint32_t)__cvta_generic_to_shared(smh);
    const uint32_t bbase = sbase + NTA_BYTES;

    const int srow = tid >> 3;
    const int sseg = tid & 7;

    const int lm_row = lane & 15;
    const int lm_k   = (lane >> 4) << 3;

    if (!CVTA) {
        const __half* A = (const __half*)Av;
#pragma unroll
        for (int i = 0; i < 16; i++) {
            int idx = tid + i * 256;
            int row = idx >> 5, seg = idx & 31;
            cp16(sbase + (row * SAR + seg * 8) * 2,
                 A + (size_t)(m0 + row) * 256 + seg * 8, (m0 + row) < M);
        }
    }
#pragma unroll
    for (int u = 0; u < 4; u++) {
        int r = srow + u * 32;
        cp16(bbase + (r * SAH + sseg * 8) * 2, B + (size_t)r * 256 + sseg * 8, true);
    }
    CP_COMMIT();
    if (CVTA) {
        const float* A32 = (const float*)Av;
#pragma unroll
        for (int i = 0; i < 32; i++) {
            int idx = tid + i * 256;
            int row = idx >> 6, c4 = idx & 63;
            float4 v = make_float4(0.f, 0.f, 0.f, 0.f);
            if (m0 + row < M) v = *(const float4*)&A32[(size_t)(m0 + row) * 256 + c4 * 4];
            __half2 h0 = __float22half2_rn(make_float2(v.x, v.y));
            __half2 h1 = __float22half2_rn(make_float2(v.z, v.w));
            *(__half2*)&smh[row * SAR + c4 * 4] = h0;
            *(__half2*)&smh[row * SAR + c4 * 4 + 2] = h1;
        }
    }

    float acc[2][8][4];
#pragma unroll
    for (int i = 0; i < 2; i++)
#pragma unroll
        for (int j = 0; j < 8; j++)
#pragma unroll
            for (int q = 0; q < 4; q++) acc[i][j][q] = 0.0f;

#pragma unroll
    for (int s = 0; s < NS; s++) {
        if (s + 1 < NS) {
            const int nn0 = ((s + 1) >> 2) * 128;
            const int nc0 = ((s + 1) & 3) * 64;
            const int nb = (s + 1) & 1;
#pragma unroll
            for (int u = 0; u < 4; u++) {
                int r = srow + u * 32;
                cp16(bbase + (nb * NTB_TILEH + r * SAH + sseg * 8) * 2,
                     B + (size_t)(nn0 + r) * 256 + nc0 + sseg * 8, true);
            }
            CP_COMMIT();
            CP_WAIT(1);
        } else {
            CP_WAIT(0);
        }
        __syncthreads();

        const uint32_t bbuf = bbase + (s & 1) * NTB_BYTES;
        const int kk_base = (s & 3) * 64;

#pragma unroll
        for (int ks = 0; ks < 4; ks++) {
            const int kk = kk_base + ks * 16;
            const int kkb = ks * 16;
            uint32_t af[2][4];
#pragma unroll
            for (int i = 0; i < 2; i++) {
                int rm = warp_m * 32 + i * 16;
                ldsm4(af[i][0], af[i][1], af[i][2], af[i][3],
                      sbase + ((rm + lm_row) * SAR + kk + lm_k) * 2);
            }
            uint32_t bf[8][2];
#pragma unroll
            for (int jj = 0; jj < 4; jj++) {
                int nb2 = warp_n * 64 + jj * 16;
                uint32_t r0, r1, r2, r3;
                ldsm4(r0, r1, r2, r3, bbuf + ((nb2 + lm_row) * SAH + kkb + lm_k) * 2);
                bf[2 * jj][0] = r0;     bf[2 * jj][1] = r2;
                bf[2 * jj + 1][0] = r1; bf[2 * jj + 1][1] = r3;
            }
#pragma unroll
            for (int i = 0; i < 2; i++)
#pragma unroll
                for (int j = 0; j < 8; j++)
                    mma_f16(acc[i][j], af[i], bf[j]);
        }

        if ((s & 3) == 3) {
            const int n0 = (s >> 2) * 128;
            if (ACT == 2) {
                __half* C = (__half*)Cv;
                float bebv[8];
                int cqv[8];
#pragma unroll
                for (int j = 0; j < 8; j++) {
                    int cq = (n0 >> 1) + warp_n * 32 + j * 4 + t;
                    cqv[j] = cq;
                    bebv[j] = bias[cq];
                }
#pragma unroll
                for (int i = 0; i < 2; i++) {
#pragma unroll
                    for (int half_ = 0; half_ < 2; half_++) {
                        int r = m0 + warp_m * 32 + i * 16 + half_ * 8 + g;
                        if (r >= M) continue;
                        const __half* arow = AQK + (size_t)r * 256;
#pragma unroll
                        for (int j = 0; j < 8; j++) {
                            float ew = acc[i][j][half_ * 2 + 0];
                            float eb = acc[i][j][half_ * 2 + 1] + bebv[j];
                            float aqk = __half2float(arow[cqv[j]]);
                            float c1 = aqk * ew;
                            float c2 = copysignf(sqrtf(fabsf(c1)), c1);
                            C[(size_t)r * 256 + cqv[j]] = __float2half(fmaxf(c2 + eb, 0.f));
                        }
                    }
                }
            } else if (SCORE) {
                __half* C = (__half*)Cv;
                const int h0 = (n0 + warp_n * 64) >> 5;
                float aw0[8], aw1[8];
#pragma unroll
                for (int j4 = 0; j4 < 4; j4++) {
                    int d = j4 * 8 + 2 * t;
                    aw0[2 * j4]     = __ldg(&Aw[d * 8 + h0]);
                    aw0[2 * j4 + 1] = __ldg(&Aw[(d + 1) * 8 + h0]);
                    aw1[2 * j4]     = __ldg(&Aw[d * 8 + h0 + 1]);
                    aw1[2 * j4 + 1] = __ldg(&Aw[(d + 1) * 8 + h0 + 1]);
                }
                float2 bvj[8];
#pragma unroll
                for (int j = 0; j < 8; j++)
                    bvj[j] = *(const float2*)&bias[n0 + warp_n * 64 + j * 8 + 2 * t];
#pragma unroll
                for (int i = 0; i < 2; i++) {
#pragma unroll
                    for (int half_ = 0; half_ < 2; half_++) {
                        int r = m0 + warp_m * 32 + i * 16 + half_ * 8 + g;
                        float s0 = 0.f, s1 = 0.f;
                        if (r < M) {
#pragma unroll
                            for (int j = 0; j < 8; j++) {
                                float ox = acc[i][j][half_ * 2 + 0] + bvj[j].x;
                                float oy = acc[i][j][half_ * 2 + 1] + bvj[j].y;
                                __half2 h2v = __float22half2_rn(make_float2(ox, oy));
                                ox = __half2float(__low2half(h2v));
                                oy = __half2float(__high2half(h2v));
                                int c = n0 + warp_n * 64 + j * 8 + 2 * t;
                                *(__half2*)&C[(size_t)r * Ncol + c] = h2v;
                                if (j < 4) {
                                    s0 += ox * aw0[2 * j] + oy * aw0[2 * j + 1];
                                } else {
                                    s1 += ox * aw1[2 * (j - 4)] + oy * aw1[2 * (j - 4) + 1];
                                }
                            }
                        }
                        s0 += __shfl_xor_sync(0xffffffffu, s0, 1);
                        s0 += __shfl_xor_sync(0xffffffffu, s0, 2);
                        s1 += __shfl_xor_sync(0xffffffffu, s1, 1);
                        s1 += __shfl_xor_sync(0xffffffffu, s1, 2);
                        if (r < M && t == 0) {
                            s0 = fminf(fmaxf(s0, -CLAMP_V), CLAMP_V);
                            s1 = fminf(fmaxf(s1, -CLAMP_V), CLAMP_V);
                            scb[(size_t)r * 8 + h0] = s0;
                            scb[(size_t)r * 8 + h0 + 1] = s1;
                            int dn = dst[r];
                            atomicMaxF(&smax[dn * 8 + h0], s0);
                            atomicMaxF(&smax[dn * 8 + h0 + 1], s1);
                        }
                    }
                }
            } else {
#pragma unroll
                for (int j = 0; j < 8; j++) {
                    int c = n0 + warp_n * 64 + j * 8 + 2 * t;
                    float2 bv = make_float2(0.f, 0.f);
                    if (bias) bv = *(const float2*)&bias[c];
#pragma unroll
                    for (int i = 0; i < 2; i++) {
                        int rbase = m0 + warp_m * 32 + i * 16 + g;
#pragma unroll
                        for (int half_ = 0; half_ < 2; half_++) {
                            int r = rbase + half_ * 8;
                            if (r >= M) continue;
                            float ox = acc[i][j][half_ * 2 + 0] + bv.x;
                            float oy = acc[i][j][half_ * 2 + 1] + bv.y;
                            if (ACT == 1) { ox = fmaxf(ox, 0.f); oy = fmaxf(oy, 0.f); }
                            if (OUTH) {
                                *(__half2*)&((__half*)Cv)[(size_t)r * Ncol + c] =
                                    __float22half2_rn(make_float2(ox, oy));
                            } else {
                                *(float2*)&((float*)Cv)[(size_t)r * Ncol + c] =
                                    make_float2(ox, oy);
                            }
                        }
                    }
                }
            }
#pragma unroll
            for (int i = 0; i < 2; i++)
#pragma unroll
                for (int j = 0; j < 8; j++)
#pragma unroll
                    for (int q = 0; q < 4; q++) acc[i][j][q] = 0.0f;
        }
        __syncthreads();
    }
}

// ---------------- fp16 GEMM + fused residual + LayerNorm ----------------
#define LNA_TILEH (64 * SAH)
#define LNA_TILEB (LNA_TILEH * 2)
#define LNB_TILEH (256 * SAH)
#define LNB_TILEB (LNB_TILEH * 2)
#define GLN_SMEM (2 * LNA_TILEB + 2 * LNB_TILEB)

template <int OUT2, int KVAL>
__global__ __launch_bounds__(256, 2)
void gemm_ln(const __half* __restrict__ A, const __half* __restrict__ B,
             const float* __restrict__ bias, const float* __restrict__ resid,
             const float* __restrict__ lng, const float* __restrict__ lnb,
             float* __restrict__ outF, __half* __restrict__ outH, int M) {
    extern __shared__ __half smh[];
    constexpr int KT = KVAL / 64;

    const int tid = threadIdx.x;
    const int warp = tid >> 5;
    const int lane = tid & 31;
    const int g = lane >> 2;
    const int t = lane & 3;
    const int warp_m = warp & 1;
    const int warp_n = warp >> 1;
    const int m0 = blockIdx.x * 64;

    const uint32_t sbase = (uint32_t)__cvta_generic_to_shared(smh);
    const uint32_t bbase = sbase + 2 * LNA_TILEB;

    const int srow = tid >> 3;
    const int sseg = tid & 7;
    const bool apred[2] = { m0 + srow < M, m0 + srow + 32 < M };
    const __half* Aptr = A + (size_t)(m0 + srow) * KVAL + sseg * 8;
    const __half* Bptr = B + (size_t)srow * KVAL + sseg * 8;

    const int lm_row = lane & 15;
    const int lm_k   = (lane >> 4) << 3;

    float acc[2][8][4];
#pragma unroll
    for (int i = 0; i < 2; i++)
#pragma unroll
        for (int j = 0; j < 8; j++)
#pragma unroll
            for (int q = 0; q < 4; q++) acc[i][j][q] = 0.0f;

#pragma unroll
    for (int u = 0; u < 2; u++) {
        int r = srow + u * 32;
        cp16(sbase + (r * SAH + sseg * 8) * 2, Aptr + (size_t)(u * 32) * KVAL, apred[u]);
    }
#pragma unroll
    for (int u = 0; u < 8; u++) {
        int r = srow + u * 32;
        cp16(bbase + (r * SAH + sseg * 8) * 2, Bptr + (size_t)(u * 32) * KVAL, true);
    }
    CP_COMMIT();

#pragma unroll
    for (int kt = 0; kt < KT; kt++) {
        const int buf = kt & 1;
        if (kt + 1 < KT) {
            const int k0 = (kt + 1) << 6;
            const int nb = buf ^ 1;
#pragma unroll
            for (int u = 0; u < 2; u++) {
                int r = srow + u * 32;
                cp16(sbase + (nb * LNA_TILEH + r * SAH + sseg * 8) * 2,
                     Aptr + (size_t)(u * 32) * KVAL + k0, apred[u]);
            }
#pragma unroll
            for (int u = 0; u < 8; u++) {
                int r = srow + u * 32;
                cp16(bbase + (nb * LNB_TILEH + r * SAH + sseg * 8) * 2,
                     Bptr + (size_t)(u * 32) * KVAL + k0, true);
            }
            CP_COMMIT();
            CP_WAIT(1);
        } else {
            CP_WAIT(0);
        }
        __syncthreads();

        const uint32_t abuf = sbase + buf * LNA_TILEB;
        const uint32_t bbuf = bbase + buf * LNB_TILEB;

#pragma unroll
        for (int ks = 0; ks < 4; ks++) {
            const int kk = ks * 16;
            uint32_t af[2][4];
#pragma unroll
            for (int i = 0; i < 2; i++) {
                int rm = warp_m * 32 + i * 16;
                ldsm4(af[i][0], af[i][1], af[i][2], af[i][3],
                      abuf + ((rm + lm_row) * SAH + kk + lm_k) * 2);
            }
            uint32_t bf[8][2];
#pragma unroll
            for (int jj = 0; jj < 4; jj++) {
                int nb2 = warp_n * 64 + jj * 16;
                uint32_t r0, r1, r2, r3;
                ldsm4(r0, r1, r2, r3, bbuf + ((nb2 + lm_row) * SAH + kk + lm_k) * 2);
                bf[2 * jj][0] = r0;     bf[2 * jj][1] = r2;
                bf[2 * jj + 1][0] = r1; bf[2 * jj + 1][1] = r3;
            }
#pragma unroll
            for (int i = 0; i < 2; i++)
#pragma unroll
                for (int j = 0; j < 8; j++)
                    mma_f16(acc[i][j], af[i], bf[j]);
        }
        __syncthreads();
    }

    float* red = (float*)smh;

#pragma unroll
    for (int i = 0; i < 2; i++) {
#pragma unroll
        for (int half_ = 0; half_ < 2; half_++) {
            const int rl = warp_m * 32 + i * 16 + half_ * 8 + g;
            const int r = m0 + rl;
            float s = 0.f, s2 = 0.f;
            if (r < M) {
#pragma unroll
                for (int j = 0; j < 8; j++) {
                    int c = warp_n * 64 + j * 8 + 2 * t;
                    float2 bv = *(const float2*)&bias[c];
                    float2 rv = *(const float2*)&resid[(size_t)r * HIDC + c];
                    float ox = acc[i][j][half_ * 2 + 0] + bv.x + rv.x;
                    float oy = acc[i][j][half_ * 2 + 1] + bv.y + rv.y;
                    acc[i][j][half_ * 2 + 0] = ox;
                    acc[i][j][half_ * 2 + 1] = oy;
                    s += ox + oy;
                    s2 += ox * ox + oy * oy;
                }
            }
            s  += __shfl_xor_sync(0xffffffffu, s, 1);
            s  += __shfl_xor_sync(0xffffffffu, s, 2);
            s2 += __shfl_xor_sync(0xffffffffu, s2, 1);
            s2 += __shfl_xor_sync(0xffffffffu, s2, 2);
            if (t == 0) {
                red[rl * 8 + warp_n] = s;
                red[rl * 8 + 4 + warp_n] = s2;
            }
        }
    }
    __syncthreads();

#pragma unroll
    for (int i = 0; i < 2; i++) {
#pragma unroll
        for (int half_ = 0; half_ < 2; half_++) {
            const int rl = warp_m * 32 + i * 16 + half_ * 8 + g;
            const int r = m0 + rl;
            if (r >= M) continue;
            float S  = red[rl * 8 + 0] + red[rl * 8 + 1] + red[rl * 8 + 2] + red[rl * 8 + 3];
            float S2 = red[rl * 8 + 4] + red[rl * 8 + 5] + red[rl * 8 + 6] + red[rl * 8 + 7];
            float mean = S * (1.0f / HIDC);
            float var = S2 * (1.0f / HIDC) - mean * mean;
            float rstd = rsqrtf(var + 1e-5f);
#pragma unroll
            for (int j = 0; j < 8; j++) {
                int c = warp_n * 64 + j * 8 + 2 * t;
                float2 gv = *(const float2*)&lng[c];
                float2 bv = *(const float2*)&lnb[c];
                float vx = (acc[i][j][half_ * 2 + 0] - mean) * rstd * gv.x + bv.x;
                float vy = (acc[i][j][half_ * 2 + 1] - mean) * rstd * gv.y + bv.y;
                *(float2*)&outF[(size_t)r * HIDC + c] = make_float2(vx, vy);
                if (OUT2)
                    *(__half2*)&outH[(size_t)r * HIDC + c] =
                        __float22half2_rn(make_float2(vx, vy));
            }
        }
    }
}

// ---------------- weight pack: TRANSPOSED [N][K], half ----------------
__global__ void pack_kernel(const float* Wq, const float* Wk, const float* Wv,
                            const float* Wew, const float* Web, const float* Weo,
                            const float* Wo_h, const float* Wo_e,
                            const float* W1, const float* W2, float* S) {
    int i = blockIdx.x * 256 + threadIdx.x;
    if (i < 196608) {
        int n = i >> 8, k = i & 255;
        float v = (n < 256) ? Wq[k * 256 + n]
                : (n < 512) ? Wk[k * 256 + n - 256]
                            : Wv[k * 256 + n - 512];
        ((__half*)(S + O_WQKV))[i] = __float2half(v);
    }
    int i2 = i - 196608;
    if (i2 >= 0 && i2 < 131072) {
        int n = i2 >> 8, k = i2 & 255, c = n >> 1;
        float v = (n & 1) ? Web[k * 256 + c] : Wew[k * 256 + c];
        ((__half*)(S + O_WEWB))[i2] = __float2half(v);
    }
    int i3 = i - 327680;
    if (i3 >= 0 && i3 < 65536) {
        int n = i3 >> 8, k = i3 & 255;
        ((__half*)(S + O_WEO))[i3] = __float2half(Weo[k * 256 + n]);
    }
    int i4 = i - 393216;
    if (i4 >= 0 && i4 < 65536) {
        int n = i4 >> 8, k = i4 & 255;
        ((__half*)(S + O_WOH))[i4] = __float2half(Wo_h[k * 256 + n]);
    }
    int i5 = i - 458752;
    if (i5 >= 0 && i5 < 65536) {
        int n = i5 >> 8, k = i5 & 255;
        ((__half*)(S + O_WOE))[i5] = __float2half(Wo_e[k * 256 + n]);
    }
    int i6 = i - 524288;
    if (i6 >= 0 && i6 < 131072) {
        int n = i6 >> 8, k = i6 & 255;
        ((__half*)(S + O_W1))[i6] = __float2half(W1[k * 512 + n]);
    }
    int i7 = i - 655360;
    if (i7 >= 0 && i7 < 131072) {
        int n = i7 >> 9, k = i7 & 511;
        ((__half*)(S + O_W2))[i7] = __float2half(W2[k * 256 + n]);
    }
}

// ---------------- init for smax/ssum only ----------------
__global__ void init2_kernel(float* smax, float* ssum, int Nn) {
    int t = blockIdx.x * 256 + threadIdx.x;
    if (t < Nn * NHEAD) { smax[t] = -CLAMP_V; ssum[t] = 0.f; }
}

// ---------------- exp + segment sum ----------------
__global__ void ex_kernel(float* __restrict__ score, const float* __restrict__ smax,
                          float* __restrict__ ssum, const int* __restrict__ dst, int E) {
    int t = blockIdx.x * 256 + threadIdx.x;
    if (t >= E * NHEAD) return;
    int e = t >> 3, h = t & 7;
    int dn = dst[e];
    float ex = expf(score[t] - smax[dn * NHEAD + h]);
    score[t] = ex;
    atomicAdd(&ssum[dn * NHEAD + h], ex);
}

// ---------------- scatter: vector RED ----------------
__global__ void scatter_kernel(const float* __restrict__ exv, const float* __restrict__ ssum,
                               const __half* __restrict__ QKV, const __half* __restrict__ Oe,
                               float* __restrict__ agg, float* __restrict__ rowv,
                               const int* __restrict__ dst, const int* __restrict__ src, int E) {
    long t = (long)blockIdx.x * 256 + threadIdx.x;
    if (t >= (long)E * 64) return;
    int e = (int)(t >> 6), q = (int)(t & 63);
    int h = q >> 3;
    int dn = dst[e], sn = src[e];
    float sc = exv[e * NHEAD + h] / (ssum[dn * NHEAD + h] + 1e-16f);
    const __half2* vp = (const __half2*)(QKV + (size_t)sn * 768 + 512 + q * 4);
    const __half2* op = (const __half2*)(Oe + (size_t)e * HIDC + q * 4);
    float2 v0 = __half22float2(vp[0]), v1 = __half22float2(vp[1]);
    float2 o0 = __half22float2(op[0]), o1 = __half22float2(op[1]);
    redv4(&agg[(size_t)dn * HIDC + q * 4], v0.x * sc, v0.y * sc, v1.x * sc, v1.y * sc);
    redv4(&rowv[(size_t)dn * HIDC + q * 4], o0.x * sc, o0.y * sc, o1.x * sc, o1.y * sc);
}

// ---------------- combine: On = half(agg + einsum(rowv, BW)), 16 rows/block ----
__global__ void combine_kernel(const float* __restrict__ agg, const float* __restrict__ rowv,
                               const float* __restrict__ BW, __half* __restrict__ On, int Nn) {
    __shared__ float sBW[32 * 8 * 32];
    __shared__ float srv[HIDC];
    int tid = threadIdx.x;
    for (int i = tid; i < 32 * 8 * 32; i += 256) sBW[i] = BW[i];
    int h = tid >> 5, c = tid & 31;
    for (int r = 0; r < 16; r++) {
        int n = blockIdx.x * 16 + r;
        __syncthreads();
        if (n < Nn) srv[tid] = rowv[(size_t)n * HIDC + tid];
        __syncthreads();
        if (n < Nn) {
            float s = agg[(size_t)n * HIDC + tid];
#pragma unroll
            for (int d = 0; d < 32; d++)
                s += srv[h * 32 + d] * sBW[d * HIDC + h * 32 + c];
            On[(size_t)n * HIDC + tid] = __float2half(s);
        }
    }
}

// ---------------- launch ----------------
extern "C" void kernel_launch(void* const* d_in, const int* in_sizes, int n_in,
                              void* d_out, int out_size) {
    const float* x     = (const float*)d_in[0];
    const float* conn  = (const float*)d_in[1];
    const float* Wq    = (const float*)d_in[2];
    const float* Wk    = (const float*)d_in[3];
    const float* Wv    = (const float*)d_in[4];
    const float* Wew   = (const float*)d_in[5];
    const float* Web   = (const float*)d_in[6];
    const float* beb   = (const float*)d_in[7];
    const float* Weo   = (const float*)d_in[8];
    const float* beo   = (const float*)d_in[9];
    const float* Aw    = (const float*)d_in[10];
    const float* BW    = (const float*)d_in[11];
    const float* Wo_h  = (const float*)d_in[12];
    const float* bo_h  = (const float*)d_in[13];
    const float* Wo_e  = (const float*)d_in[14];
    const float* bo_e  = (const float*)d_in[15];
    const float* ln1hg = (const float*)d_in[16];
    const float* ln1hb = (const float*)d_in[17];
    const float* ln1eg = (const float*)d_in[18];
    const float* ln1eb = (const float*)d_in[19];
    const float* W1    = (const float*)d_in[20];
    const float* b1    = (const float*)d_in[21];
    const float* W2    = (const float*)d_in[22];
    const float* b2    = (const float*)d_in[23];
    const float* ln2hg = (const float*)d_in[24];
    const float* ln2hb = (const float*)d_in[25];
    const int*   ei    = (const int*)d_in[26];

    int Nn = in_sizes[0] / HIDC;
    int Ee = in_sizes[26] / 2;
    const int* dst = ei;
    const int* src = ei + Ee;

    float* S = nullptr;
    cudaGetSymbolAddress((void**)&S, g_scratch);

    __half* QKV  = (__half*)(S + O_QKV);
    __half* cA   = (__half*)(S + O_CA);
    __half* aqk  = (__half*)(S + O_AQK);
    __half* Oe   = (__half*)(S + O_OE);
    float*  scb  = S + O_SCB;
    float*  smax = S + O_SMAX;
    float*  ssum = S + O_SSUM;
    float*  agg  = S + O_AGG;
    float*  rowv = S + O_ROWV;
    __half* On   = (__half*)(S + O_ON);
    float*  hln  = S + O_HLN;
    __half* hlnt = (__half*)(S + O_HLNT);
    __half* ffn  = (__half*)(S + O_FFN);
    __half* wqkv = (__half*)(S + O_WQKV);
    __half* wewb = (__half*)(S + O_WEWB);
    __half* weo  = (__half*)(S + O_WEO);
    __half* woh  = (__half*)(S + O_WOH);
    __half* woe  = (__half*)(S + O_WOE);
    __half* w1   = (__half*)(S + O_W1);
    __half* w2   = (__half*)(S + O_W2);

    float* outH = (float*)d_out;
    float* outE = outH + (size_t)Nn * HIDC;

    cudaFuncSetAttribute(gemm_nt<0, 1, 0, 1, 6>, cudaFuncAttributeMaxDynamicSharedMemorySize, GNT_SMEM);
    cudaFuncSetAttribute(gemm_nt<2, 0, 0, 1, 4>, cudaFuncAttributeMaxDynamicSharedMemorySize, GNT_SMEM);
    cudaFuncSetAttribute(gemm_nt<0, 1, 1, 0, 2>, cudaFuncAttributeMaxDynamicSharedMemorySize, GNT_SMEM);
    cudaFuncSetAttribute(gemm_nt<1, 1, 0, 0, 4>, cudaFuncAttributeMaxDynamicSharedMemorySize, GNT_SMEM);
    cudaFuncSetAttribute(gemm_ln<1, 256>, cudaFuncAttributeMaxDynamicSharedMemorySize, GLN_SMEM);
    cudaFuncSetAttribute(gemm_ln<0, 256>, cudaFuncAttributeMaxDynamicSharedMemorySize, GLN_SMEM);
    cudaFuncSetAttribute(gemm_ln<0, 512>, cudaFuncAttributeMaxDynamicSharedMemorySize, GLN_SMEM);

    // side stream + events for forked capture (created once; fallback to serial)
    static cudaStream_t s1 = nullptr;
    static cudaEvent_t evFork = nullptr, evJoin = nullptr;
    static bool streams_ok = false;
    static bool tried = false;
    if (!tried) {
        tried = true;
        streams_ok =
            (cudaStreamCreateWithFlags(&s1, cudaStreamNonBlocking) == cudaSuccess) &&
            (cudaEventCreateWithFlags(&evFork, cudaEventDisableTiming) == cudaSuccess) &&
            (cudaEventCreateWithFlags(&evJoin, cudaEventDisableTiming) == cudaSuccess);
    }

    // prep
    pack_kernel<<<cdiv(786432, 256), 256>>>(Wq, Wk, Wv, Wew, Web, Weo, Wo_h, Wo_e, W1, W2, S);
    cudaMemsetAsync(agg, 0, (size_t)Nn * 512 * sizeof(float));
    init2_kernel<<<cdiv(Nn * NHEAD, 256), 256>>>(smax, ssum, Nn);

    int gmN = cdiv(Nn, 128);
    int gmE = cdiv(Ee, 128);

    // QKV = x(fp32) @ WqkvT  [N, 768] (half out)
    gemm_nt<0, 1, 0, 1, 6><<<gmN, 256, GNT_SMEM>>>(
        x, wqkv, nullptr, QKV, Nn,
        nullptr, nullptr, nullptr, nullptr, nullptr, nullptr);
    // aqk[e] = Q[dst[e]] + K[src[e]]
    aqk_kernel<<<cdiv(Ee, 8), 256>>>(QKV, aqk, dst, src, Ee);
    // fused EwEb GEMM + edge message: conn(fp32) -> cA (half)
    gemm_nt<2, 0, 0, 1, 4><<<gmE, 256, GNT_SMEM>>>(
        conn, wewb, beb, cA, Ee,
        dst, src, aqk, nullptr, nullptr, nullptr);
    // Oe = cA @ WeoT + beo (half) + fused score/clamp/segment-max
    gemm_nt<0, 1, 1, 0, 2><<<gmE, 256, GNT_SMEM>>>(
        cA, weo, beo, Oe, Ee,
        dst, nullptr, nullptr, Aw, scb, smax);

    // ---- fork: e-path output GEMM+LN runs concurrently with attention chain ----
    if (streams_ok) {
        cudaEventRecord(evFork, 0);
        cudaStreamWaitEvent(s1, evFork, 0);
        gemm_ln<0, 256><<<cdiv(Ee, 64), 256, GLN_SMEM, s1>>>(
            Oe, woe, bo_e, conn, ln1eg, ln1eb, outE, nullptr, Ee);
        cudaEventRecord(evJoin, s1);
    } else {
        gemm_ln<0, 256><<<cdiv(Ee, 64), 256, GLN_SMEM>>>(
            Oe, woe, bo_e, conn, ln1eg, ln1eb, outE, nullptr, Ee);
    }

    // attention chain (default stream)
    ex_kernel<<<cdiv(Ee * NHEAD, 256), 256>>>(scb, smax, ssum, dst, Ee);
    scatter_kernel<<<(int)cdiv((long)Ee * 64, 256), 256>>>(scb, ssum, QKV, Oe, agg, rowv, dst, src, Ee);
    combine_kernel<<<cdiv(Nn, 16), 256>>>(agg, rowv, BW, On, Nn);

    // h path: hln = LN1h(x + On @ Wo_h + bo_h), + half copy hlnt
    gemm_ln<1, 256><<<cdiv(Nn, 64), 256, GLN_SMEM>>>(
        On, woh, bo_h, x, ln1hg, ln1hb, hln, hlnt, Nn);

    // FFN: ffn = relu(hlnt @ W1 + b1) (half)
    gemm_nt<1, 1, 0, 0, 4><<<gmN, 256, GNT_SMEM>>>(
        hlnt, w1, b1, ffn, Nn,
        nullptr, nullptr, nullptr, nullptr, nullptr, nullptr);
    // outH = LN2h(hln + ffn @ W2 + b2)  (K=512, fused)
    gemm_ln<0, 512><<<cdiv(Nn, 64), 256, GLN_SMEM>>>(
        ffn, w2, b2, hln, ln2hg, ln2hb, outH, nullptr, Nn);

    // ---- join ----
    if (streams_ok) {
        cudaStreamWaitEvent((cudaStream_t)0, evJoin, 0);
    }
}

// round 14
// speedup vs baseline: 1.7942x; 1.0725x over previous
#include <cuda_runtime.h>
#include <cuda_fp16.h>
#include <math.h>
#include <stdint.h>

#define HIDC 256
#define NHEAD 8
#define CLAMP_V 5.0f

static const int NMAXC = 50000;
static const int EMAXC = 320000;

// ---------------- scratch layout ----------------
#define O_QKV  ((size_t)0)                          // N*768 (half)
#define O_CA   (O_QKV  + (size_t)NMAXC*768)         // E*256 (half)
#define O_AQK  (O_CA   + (size_t)EMAXC*256)         // E*256 (half)
#define O_OE   (O_AQK  + (size_t)EMAXC*128)         // E*256 (half)
#define O_SCB  (O_OE   + (size_t)EMAXC*256)         // E*8  (f32, holds exp(score))
#define O_SSUM (O_SCB  + (size_t)EMAXC*8)           // N*8  (f32)  [contig w/ AGG]
#define O_AGG  (O_SSUM + (size_t)NMAXC*8)           // N*256 (f32)
#define O_ROWV (O_AGG  + (size_t)NMAXC*256)         // N*256 (f32)
#define O_ON   (O_ROWV + (size_t)NMAXC*256)         // N*256 (half)
#define O_HLN  (O_ON   + (size_t)NMAXC*256)         // N*256 (f32)
#define O_HLNT (O_HLN  + (size_t)NMAXC*256)         // N*256 (half)
#define O_FFN  (O_HLNT + (size_t)NMAXC*256)         // N*512 (half)
#define O_WQKV (O_FFN  + (size_t)NMAXC*512)         // 768*256 (half, [N][K])
#define O_WEWB (O_WQKV + (size_t)768*256)           // 512*256 (half)
#define O_WEO  (O_WEWB + (size_t)512*256)           // 256*256 (half)
#define O_WOH  (O_WEO  + (size_t)256*256)           // 256*256 (half)
#define O_WOE  (O_WOH  + (size_t)256*256)           // 256*256 (half)
#define O_W1   (O_WOE  + (size_t)256*256)           // 512*256 (half)
#define O_W2   (O_W1   + (size_t)512*256)           // 256*512 (half)
#define O_TOTAL (O_W2  + (size_t)256*512)

__device__ float g_scratch[O_TOTAL];

static inline int cdiv(int a, int b) { return (a + b - 1) / b; }

// ---------------- helpers ----------------
__device__ __forceinline__ void mma_f16(float c[4], const uint32_t a[4], const uint32_t b[2]) {
    asm volatile(
        "mma.sync.aligned.m16n8k16.row.col.f32.f16.f16.f32 "
        "{%0,%1,%2,%3}, {%4,%5,%6,%7}, {%8,%9}, {%0,%1,%2,%3};"
        : "+f"(c[0]), "+f"(c[1]), "+f"(c[2]), "+f"(c[3])
        : "r"(a[0]), "r"(a[1]), "r"(a[2]), "r"(a[3]), "r"(b[0]), "r"(b[1]));
}

__device__ __forceinline__ void ldsm4(uint32_t& r0, uint32_t& r1, uint32_t& r2, uint32_t& r3,
                                      uint32_t addr) {
    asm volatile("ldmatrix.sync.aligned.m8n8.x4.shared.b16 {%0,%1,%2,%3}, [%4];"
                 : "=r"(r0), "=r"(r1), "=r"(r2), "=r"(r3) : "r"(addr));
}

__device__ __forceinline__ void cp16(uint32_t saddr, const void* g, bool pred) {
    int sz = pred ? 16 : 0;
    asm volatile("cp.async.cg.shared.global [%0], [%1], 16, %2;\n"
                 :: "r"(saddr), "l"(g), "r"(sz));
}
#define CP_COMMIT() asm volatile("cp.async.commit_group;\n" ::)
#define CP_WAIT(n)  asm volatile("cp.async.wait_group %0;\n" :: "n"(n))

__device__ __forceinline__ void redv4(float* addr, float a, float b, float c, float d) {
    asm volatile("red.global.add.v4.f32 [%0], {%1, %2, %3, %4};"
                 :: "l"(addr), "f"(a), "f"(b), "f"(c), "f"(d) : "memory");
}

// ---------------- aqk: per-edge coalesced gather ----------------
__global__ void aqk_kernel(const __half* __restrict__ QKV, __half* __restrict__ aqk,
                           const int* __restrict__ dst, const int* __restrict__ src, int E) {
    int w = (blockIdx.x * 256 + threadIdx.x) >> 5;
    int lane = threadIdx.x & 31;
    if (w >= E) return;
    int dn = dst[w], sn = src[w];
    int4 qv = ((const int4*)(QKV + (size_t)dn * 768))[lane];
    int4 kv = ((const int4*)(QKV + (size_t)sn * 768 + 256))[lane];
    __half2* qh = (__half2*)&qv;
    __half2* kh = (__half2*)&kv;
    int4 out;
    __half2* oh = (__half2*)&out;
#pragma unroll
    for (int i = 0; i < 4; i++) oh[i] = __hadd2(qh[i], kh[i]);
    ((int4*)(aqk + (size_t)w * 256))[lane] = out;
}

// ---------------- gemm_nt: K=256-resident-A fp16 GEMM ----------------
#define SAR 264
#define NTA_BYTES (128 * SAR * 2)
#define SAH 72
#define NTB_TILEH (128 * SAH)
#define NTB_BYTES (NTB_TILEH * 2)
#define GNT_SMEM (NTA_BYTES + 2 * NTB_BYTES)

// ACT: 0 plain, 1 bias+relu, 2 fused edge message
// SCORE: fused score -> exp -> scb + red.add ssum
template <int ACT, int OUTH, int SCORE, int CVTA, int NT>
__global__ __launch_bounds__(256, 2)
void gemm_nt(const void* __restrict__ Av, const __half* __restrict__ B,
             const float* __restrict__ bias,
             void* __restrict__ Cv, int M,
             const int* __restrict__ dst, const int* __restrict__ src,
             const __half* __restrict__ AQK, const float* __restrict__ Aw,
             float* __restrict__ scb, float* __restrict__ ssum) {
    extern __shared__ __half smh[];
    constexpr int Ncol = NT * 128;
    constexpr int NS = 4 * NT;

    const int tid = threadIdx.x;
    const int warp = tid >> 5;
    const int lane = tid & 31;
    const int g = lane >> 2;
    const int t = lane & 3;
    const int warp_m = warp & 3;
    const int warp_n = warp >> 2;
    const int m0 = blockIdx.x * 128;

    const uint32_t sbase = (uint32_t)__cvta_generic_to_shared(smh);
    const uint32_t bbase = sbase + NTA_BYTES;

    const int srow = tid >> 3;
    const int sseg = tid & 7;

    const int lm_row = lane & 15;
    const int lm_k   = (lane >> 4) << 3;

    if (!CVTA) {
        const __half* A = (const __half*)Av;
#pragma unroll
        for (int i = 0; i < 16; i++) {
            int idx = tid + i * 256;
            int row = idx >> 5, seg = idx & 31;
            cp16(sbase + (row * SAR + seg * 8) * 2,
                 A + (size_t)(m0 + row) * 256 + seg * 8, (m0 + row) < M);
        }
    }
#pragma unroll
    for (int u = 0; u < 4; u++) {
        int r = srow + u * 32;
        cp16(bbase + (r * SAH + sseg * 8) * 2, B + (size_t)r * 256 + sseg * 8, true);
    }
    CP_COMMIT();
    if (CVTA) {
        const float* A32 = (const float*)Av;
#pragma unroll
        for (int i = 0; i < 32; i++) {
            int idx = tid + i * 256;
            int row = idx >> 6, c4 = idx & 63;
            float4 v = make_float4(0.f, 0.f, 0.f, 0.f);
            if (m0 + row < M) v = *(const float4*)&A32[(size_t)(m0 + row) * 256 + c4 * 4];
            __half2 h0 = __float22half2_rn(make_float2(v.x, v.y));
            __half2 h1 = __float22half2_rn(make_float2(v.z, v.w));
            *(__half2*)&smh[row * SAR + c4 * 4] = h0;
            *(__half2*)&smh[row * SAR + c4 * 4 + 2] = h1;
        }
    }

    float acc[2][8][4];
#pragma unroll
    for (int i = 0; i < 2; i++)
#pragma unroll
        for (int j = 0; j < 8; j++)
#pragma unroll
            for (int q = 0; q < 4; q++) acc[i][j][q] = 0.0f;

#pragma unroll
    for (int s = 0; s < NS; s++) {
        if (s + 1 < NS) {
            const int nn0 = ((s + 1) >> 2) * 128;
            const int nc0 = ((s + 1) & 3) * 64;
            const int nb = (s + 1) & 1;
#pragma unroll
            for (int u = 0; u < 4; u++) {
                int r = srow + u * 32;
                cp16(bbase + (nb * NTB_TILEH + r * SAH + sseg * 8) * 2,
                     B + (size_t)(nn0 + r) * 256 + nc0 + sseg * 8, true);
            }
            CP_COMMIT();
            CP_WAIT(1);
        } else {
            CP_WAIT(0);
        }
        __syncthreads();

        const uint32_t bbuf = bbase + (s & 1) * NTB_BYTES;
        const int kk_base = (s & 3) * 64;

#pragma unroll
        for (int ks = 0; ks < 4; ks++) {
            const int kk = kk_base + ks * 16;
            const int kkb = ks * 16;
            uint32_t af[2][4];
#pragma unroll
            for (int i = 0; i < 2; i++) {
                int rm = warp_m * 32 + i * 16;
                ldsm4(af[i][0], af[i][1], af[i][2], af[i][3],
                      sbase + ((rm + lm_row) * SAR + kk + lm_k) * 2);
            }
            uint32_t bf[8][2];
#pragma unroll
            for (int jj = 0; jj < 4; jj++) {
                int nb2 = warp_n * 64 + jj * 16;
                uint32_t r0, r1, r2, r3;
                ldsm4(r0, r1, r2, r3, bbuf + ((nb2 + lm_row) * SAH + kkb + lm_k) * 2);
                bf[2 * jj][0] = r0;     bf[2 * jj][1] = r2;
                bf[2 * jj + 1][0] = r1; bf[2 * jj + 1][1] = r3;
            }
#pragma unroll
            for (int i = 0; i < 2; i++)
#pragma unroll
                for (int j = 0; j < 8; j++)
                    mma_f16(acc[i][j], af[i], bf[j]);
        }

        if ((s & 3) == 3) {
            const int n0 = (s >> 2) * 128;
            if (ACT == 2) {
                __half* C = (__half*)Cv;
                float bebv[8];
                int cqv[8];
#pragma unroll
                for (int j = 0; j < 8; j++) {
                    int cq = (n0 >> 1) + warp_n * 32 + j * 4 + t;
                    cqv[j] = cq;
                    bebv[j] = bias[cq];
                }
#pragma unroll
                for (int i = 0; i < 2; i++) {
#pragma unroll
                    for (int half_ = 0; half_ < 2; half_++) {
                        int r = m0 + warp_m * 32 + i * 16 + half_ * 8 + g;
                        if (r >= M) continue;
                        const __half* arow = AQK + (size_t)r * 256;
#pragma unroll
                        for (int j = 0; j < 8; j++) {
                            float ew = acc[i][j][half_ * 2 + 0];
                            float eb = acc[i][j][half_ * 2 + 1] + bebv[j];
                            float aqk = __half2float(arow[cqv[j]]);
                            float c1 = aqk * ew;
                            float c2 = copysignf(sqrtf(fabsf(c1)), c1);
                            C[(size_t)r * 256 + cqv[j]] = __float2half(fmaxf(c2 + eb, 0.f));
                        }
                    }
                }
            } else if (SCORE) {
                __half* C = (__half*)Cv;
                const int h0 = (n0 + warp_n * 64) >> 5;
                float aw0[8], aw1[8];
#pragma unroll
                for (int j4 = 0; j4 < 4; j4++) {
                    int d = j4 * 8 + 2 * t;
                    aw0[2 * j4]     = __ldg(&Aw[d * 8 + h0]);
                    aw0[2 * j4 + 1] = __ldg(&Aw[(d + 1) * 8 + h0]);
                    aw1[2 * j4]     = __ldg(&Aw[d * 8 + h0 + 1]);
                    aw1[2 * j4 + 1] = __ldg(&Aw[(d + 1) * 8 + h0 + 1]);
                }
                float2 bvj[8];
#pragma unroll
                for (int j = 0; j < 8; j++)
                    bvj[j] = *(const float2*)&bias[n0 + warp_n * 64 + j * 8 + 2 * t];
#pragma unroll
                for (int i = 0; i < 2; i++) {
#pragma unroll
                    for (int half_ = 0; half_ < 2; half_++) {
                        int r = m0 + warp_m * 32 + i * 16 + half_ * 8 + g;
                        float s0 = 0.f, s1 = 0.f;
                        if (r < M) {
#pragma unroll
                            for (int j = 0; j < 8; j++) {
                                float ox = acc[i][j][half_ * 2 + 0] + bvj[j].x;
                                float oy = acc[i][j][half_ * 2 + 1] + bvj[j].y;
                                __half2 h2v = __float22half2_rn(make_float2(ox, oy));
                                ox = __half2float(__low2half(h2v));
                                oy = __half2float(__high2half(h2v));
                                int c = n0 + warp_n * 64 + j * 8 + 2 * t;
                                *(__half2*)&C[(size_t)r * Ncol + c] = h2v;
                                if (j < 4) {
                                    s0 += ox * aw0[2 * j] + oy * aw0[2 * j + 1];
                                } else {
                                    s1 += ox * aw1[2 * (j - 4)] + oy * aw1[2 * (j - 4) + 1];
                                }
                            }
                        }
                        s0 += __shfl_xor_sync(0xffffffffu, s0, 1);
                        s0 += __shfl_xor_sync(0xffffffffu, s0, 2);
                        s1 += __shfl_xor_sync(0xffffffffu, s1, 1);
                        s1 += __shfl_xor_sync(0xffffffffu, s1, 2);
                        if (r < M && t == 0) {
                            // clamp -> exp (no max pass needed: |s| <= 5)
                            float e0 = expf(fminf(fmaxf(s0, -CLAMP_V), CLAMP_V));
                            float e1 = expf(fminf(fmaxf(s1, -CLAMP_V), CLAMP_V));
                            scb[(size_t)r * 8 + h0] = e0;
                            scb[(size_t)r * 8 + h0 + 1] = e1;
                            int dn = dst[r];
                            atomicAdd(&ssum[dn * 8 + h0], e0);
                            atomicAdd(&ssum[dn * 8 + h0 + 1], e1);
                        }
                    }
                }
            } else {
#pragma unroll
                for (int j = 0; j < 8; j++) {
                    int c = n0 + warp_n * 64 + j * 8 + 2 * t;
                    float2 bv = make_float2(0.f, 0.f);
                    if (bias) bv = *(const float2*)&bias[c];
#pragma unroll
                    for (int i = 0; i < 2; i++) {
                        int rbase = m0 + warp_m * 32 + i * 16 + g;
#pragma unroll
                        for (int half_ = 0; half_ < 2; half_++) {
                            int r = rbase + half_ * 8;
                            if (r >= M) continue;
                            float ox = acc[i][j][half_ * 2 + 0] + bv.x;
                            float oy = acc[i][j][half_ * 2 + 1] + bv.y;
                            if (ACT == 1) { ox = fmaxf(ox, 0.f); oy = fmaxf(oy, 0.f); }
                            if (OUTH) {
                                *(__half2*)&((__half*)Cv)[(size_t)r * Ncol + c] =
                                    __float22half2_rn(make_float2(ox, oy));
                            } else {
                                *(float2*)&((float*)Cv)[(size_t)r * Ncol + c] =
                                    make_float2(ox, oy);
                            }
                        }
                    }
                }
            }
#pragma unroll
            for (int i = 0; i < 2; i++)
#pragma unroll
                for (int j = 0; j < 8; j++)
#pragma unroll
                    for (int q = 0; q < 4; q++) acc[i][j][q] = 0.0f;
        }
        __syncthreads();
    }
}

// ---------------- fp16 GEMM + fused residual + LayerNorm ----------------
#define LNA_TILEH (64 * SAH)
#define LNA_TILEB (LNA_TILEH * 2)
#define LNB_TILEH (256 * SAH)
#define LNB_TILEB (LNB_TILEH * 2)
#define GLN_SMEM (2 * LNA_TILEB + 2 * LNB_TILEB)

template <int OUT2, int KVAL>
__global__ __launch_bounds__(256, 2)
void gemm_ln(const __half* __restrict__ A, const __half* __restrict__ B,
             const float* __restrict__ bias, const float* __restrict__ resid,
             const float* __restrict__ lng, const float* __restrict__ lnb,
             float* __restrict__ outF, __half* __restrict__ outH, int M) {
    extern __shared__ __half smh[];
    constexpr int KT = KVAL / 64;

    const int tid = threadIdx.x;
    const int warp = tid >> 5;
    const int lane = tid & 31;
    const int g = lane >> 2;
    const int t = lane & 3;
    const int warp_m = warp & 1;
    const int warp_n = warp >> 1;
    const int m0 = blockIdx.x * 64;

    const uint32_t sbase = (uint32_t)__cvta_generic_to_shared(smh);
    const uint32_t bbase = sbase + 2 * LNA_TILEB;

    const int srow = tid >> 3;
    const int sseg = tid & 7;
    const bool apred[2] = { m0 + srow < M, m0 + srow + 32 < M };
    const __half* Aptr = A + (size_t)(m0 + srow) * KVAL + sseg * 8;
    const __half* Bptr = B + (size_t)srow * KVAL + sseg * 8;

    const int lm_row = lane & 15;
    const int lm_k   = (lane >> 4) << 3;

    float acc[2][8][4];
#pragma unroll
    for (int i = 0; i < 2; i++)
#pragma unroll
        for (int j = 0; j < 8; j++)
#pragma unroll
            for (int q = 0; q < 4; q++) acc[i][j][q] = 0.0f;

#pragma unroll
    for (int u = 0; u < 2; u++) {
        int r = srow + u * 32;
        cp16(sbase + (r * SAH + sseg * 8) * 2, Aptr + (size_t)(u * 32) * KVAL, apred[u]);
    }
#pragma unroll
    for (int u = 0; u < 8; u++) {
        int r = srow + u * 32;
        cp16(bbase + (r * SAH + sseg * 8) * 2, Bptr + (size_t)(u * 32) * KVAL, true);
    }
    CP_COMMIT();

#pragma unroll
    for (int kt = 0; kt < KT; kt++) {
        const int buf = kt & 1;
        if (kt + 1 < KT) {
            const int k0 = (kt + 1) << 6;
            const int nb = buf ^ 1;
#pragma unroll
            for (int u = 0; u < 2; u++) {
                int r = srow + u * 32;
                cp16(sbase + (nb * LNA_TILEH + r * SAH + sseg * 8) * 2,
                     Aptr + (size_t)(u * 32) * KVAL + k0, apred[u]);
            }
#pragma unroll
            for (int u = 0; u < 8; u++) {
                int r = srow + u * 32;
                cp16(bbase + (nb * LNB_TILEH + r * SAH + sseg * 8) * 2,
                     Bptr + (size_t)(u * 32) * KVAL + k0, true);
            }
            CP_COMMIT();
            CP_WAIT(1);
        } else {
            CP_WAIT(0);
        }
        __syncthreads();

        const uint32_t abuf = sbase + buf * LNA_TILEB;
        const uint32_t bbuf = bbase + buf * LNB_TILEB;

#pragma unroll
        for (int ks = 0; ks < 4; ks++) {
            const int kk = ks * 16;
            uint32_t af[2][4];
#pragma unroll
            for (int i = 0; i < 2; i++) {
                int rm = warp_m * 32 + i * 16;
                ldsm4(af[i][0], af[i][1], af[i][2], af[i][3],
                      abuf + ((rm + lm_row) * SAH + kk + lm_k) * 2);
            }
            uint32_t bf[8][2];
#pragma unroll
            for (int jj = 0; jj < 4; jj++) {
                int nb2 = warp_n * 64 + jj * 16;
                uint32_t r0, r1, r2, r3;
                ldsm4(r0, r1, r2, r3, bbuf + ((nb2 + lm_row) * SAH + kk + lm_k) * 2);
                bf[2 * jj][0] = r0;     bf[2 * jj][1] = r2;
                bf[2 * jj + 1][0] = r1; bf[2 * jj + 1][1] = r3;
            }
#pragma unroll
            for (int i = 0; i < 2; i++)
#pragma unroll
                for (int j = 0; j < 8; j++)
                    mma_f16(acc[i][j], af[i], bf[j]);
        }
        __syncthreads();
    }

    float* red = (float*)smh;

#pragma unroll
    for (int i = 0; i < 2; i++) {
#pragma unroll
        for (int half_ = 0; half_ < 2; half_++) {
            const int rl = warp_m * 32 + i * 16 + half_ * 8 + g;
            const int r = m0 + rl;
            float s = 0.f, s2 = 0.f;
            if (r < M) {
#pragma unroll
                for (int j = 0; j < 8; j++) {
                    int c = warp_n * 64 + j * 8 + 2 * t;
                    float2 bv = *(const float2*)&bias[c];
                    float2 rv = *(const float2*)&resid[(size_t)r * HIDC + c];
                    float ox = acc[i][j][half_ * 2 + 0] + bv.x + rv.x;
                    float oy = acc[i][j][half_ * 2 + 1] + bv.y + rv.y;
                    acc[i][j][half_ * 2 + 0] = ox;
                    acc[i][j][half_ * 2 + 1] = oy;
                    s += ox + oy;
                    s2 += ox * ox + oy * oy;
                }
            }
            s  += __shfl_xor_sync(0xffffffffu, s, 1);
            s  += __shfl_xor_sync(0xffffffffu, s, 2);
            s2 += __shfl_xor_sync(0xffffffffu, s2, 1);
            s2 += __shfl_xor_sync(0xffffffffu, s2, 2);
            if (t == 0) {
                red[rl * 8 + warp_n] = s;
                red[rl * 8 + 4 + warp_n] = s2;
            }
        }
    }
    __syncthreads();

#pragma unroll
    for (int i = 0; i < 2; i++) {
#pragma unroll
        for (int half_ = 0; half_ < 2; half_++) {
            const int rl = warp_m * 32 + i * 16 + half_ * 8 + g;
            const int r = m0 + rl;
            if (r >= M) continue;
            float S  = red[rl * 8 + 0] + red[rl * 8 + 1] + red[rl * 8 + 2] + red[rl * 8 + 3];
            float S2 = red[rl * 8 + 4] + red[rl * 8 + 5] + red[rl * 8 + 6] + red[rl * 8 + 7];
            float mean = S * (1.0f / HIDC);
            float var = S2 * (1.0f / HIDC) - mean * mean;
            float rstd = rsqrtf(var + 1e-5f);
#pragma unroll
            for (int j = 0; j < 8; j++) {
                int c = warp_n * 64 + j * 8 + 2 * t;
                float2 gv = *(const float2*)&lng[c];
                float2 bv = *(const float2*)&lnb[c];
                float vx = (acc[i][j][half_ * 2 + 0] - mean) * rstd * gv.x + bv.x;
                float vy = (acc[i][j][half_ * 2 + 1] - mean) * rstd * gv.y + bv.y;
                *(float2*)&outF[(size_t)r * HIDC + c] = make_float2(vx, vy);
                if (OUT2)
                    *(__half2*)&outH[(size_t)r * HIDC + c] =
                        __float22half2_rn(make_float2(vx, vy));
            }
        }
    }
}

// ---------------- weight pack ----------------
__global__ void pack_kernel(const float* Wq, const float* Wk, const float* Wv,
                            const float* Wew, const float* Web, const float* Weo,
                            const float* Wo_h, const float* Wo_e,
                            const float* W1, const float* W2, float* S) {
    int i = blockIdx.x * 256 + threadIdx.x;
    if (i < 196608) {
        int n = i >> 8, k = i & 255;
        float v = (n < 256) ? Wq[k * 256 + n]
                : (n < 512) ? Wk[k * 256 + n - 256]
                            : Wv[k * 256 + n - 512];
        ((__half*)(S + O_WQKV))[i] = __float2half(v);
    }
    int i2 = i - 196608;
    if (i2 >= 0 && i2 < 131072) {
        int n = i2 >> 8, k = i2 & 255, c = n >> 1;
        float v = (n & 1) ? Web[k * 256 + c] : Wew[k * 256 + c];
        ((__half*)(S + O_WEWB))[i2] = __float2half(v);
    }
    int i3 = i - 327680;
    if (i3 >= 0 && i3 < 65536) {
        int n = i3 >> 8, k = i3 & 255;
        ((__half*)(S + O_WEO))[i3] = __float2half(Weo[k * 256 + n]);
    }
    int i4 = i - 393216;
    if (i4 >= 0 && i4 < 65536) {
        int n = i4 >> 8, k = i4 & 255;
        ((__half*)(S + O_WOH))[i4] = __float2half(Wo_h[k * 256 + n]);
    }
    int i5 = i - 458752;
    if (i5 >= 0 && i5 < 65536) {
        int n = i5 >> 8, k = i5 & 255;
        ((__half*)(S + O_WOE))[i5] = __float2half(Wo_e[k * 256 + n]);
    }
    int i6 = i - 524288;
    if (i6 >= 0 && i6 < 131072) {
        int n = i6 >> 8, k = i6 & 255;
        ((__half*)(S + O_W1))[i6] = __float2half(W1[k * 512 + n]);
    }
    int i7 = i - 655360;
    if (i7 >= 0 && i7 < 131072) {
        int n = i7 >> 9, k = i7 & 511;
        ((__half*)(S + O_W2))[i7] = __float2half(W2[k * 256 + n]);
    }
}

// ---------------- scatter: unnormalized vector RED ----------------
__global__ void scatter_kernel(const float* __restrict__ exv,
                               const __half* __restrict__ QKV, const __half* __restrict__ Oe,
                               float* __restrict__ agg, float* __restrict__ rowv,
                               const int* __restrict__ dst, const int* __restrict__ src, int E) {
    long t = (long)blockIdx.x * 256 + threadIdx.x;
    if (t >= (long)E * 64) return;
    int e = (int)(t >> 6), q = (int)(t & 63);
    int h = q >> 3;
    int dn = dst[e], sn = src[e];
    float sc = exv[(size_t)e * NHEAD + h];
    const __half2* vp = (const __half2*)(QKV + (size_t)sn * 768 + 512 + q * 4);
    const __half2* op = (const __half2*)(Oe + (size_t)e * HIDC + q * 4);
    float2 v0 = __half22float2(vp[0]), v1 = __half22float2(vp[1]);
    float2 o0 = __half22float2(op[0]), o1 = __half22float2(op[1]);
    redv4(&agg[(size_t)dn * HIDC + q * 4], v0.x * sc, v0.y * sc, v1.x * sc, v1.y * sc);
    redv4(&rowv[(size_t)dn * HIDC + q * 4], o0.x * sc, o0.y * sc, o1.x * sc, o1.y * sc);
}

// ---------------- combine: On = half((agg + einsum(rowv, BW)) / ssum) ----------------
__global__ void combine_kernel(const float* __restrict__ agg, const float* __restrict__ rowv,
                               const float* __restrict__ ssum,
                               const float* __restrict__ BW, __half* __restrict__ On, int Nn) {
    __shared__ float sBW[32 * 8 * 32];
    __shared__ float srv[HIDC];
    int tid = threadIdx.x;
    for (int i = tid; i < 32 * 8 * 32; i += 256) sBW[i] = BW[i];
    int h = tid >> 5, c = tid & 31;
    for (int r = 0; r < 16; r++) {
        int n = blockIdx.x * 16 + r;
        __syncthreads();
        if (n < Nn) srv[tid] = rowv[(size_t)n * HIDC + tid];
        __syncthreads();
        if (n < Nn) {
            float s = agg[(size_t)n * HIDC + tid];
#pragma unroll
            for (int d = 0; d < 32; d++)
                s += srv[h * 32 + d] * sBW[d * HIDC + h * 32 + c];
            float inv = 1.0f / (ssum[n * NHEAD + h] + 1e-16f);
            On[(size_t)n * HIDC + tid] = __float2half(s * inv);
        }
    }
}

// ---------------- launch ----------------
extern "C" void kernel_launch(void* const* d_in, const int* in_sizes, int n_in,
                              void* d_out, int out_size) {
    const float* x     = (const float*)d_in[0];
    const float* conn  = (const float*)d_in[1];
    const float* Wq    = (const float*)d_in[2];
    const float* Wk    = (const float*)d_in[3];
    const float* Wv    = (const float*)d_in[4];
    const float* Wew   = (const float*)d_in[5];
    const float* Web   = (const float*)d_in[6];
    const float* beb   = (const float*)d_in[7];
    const float* Weo   = (const float*)d_in[8];
    const float* beo   = (const float*)d_in[9];
    const float* Aw    = (const float*)d_in[10];
    const float* BW    = (const float*)d_in[11];
    const float* Wo_h  = (const float*)d_in[12];
    const float* bo_h  = (const float*)d_in[13];
    const float* Wo_e  = (const float*)d_in[14];
    const float* bo_e  = (const float*)d_in[15];
    const float* ln1hg = (const float*)d_in[16];
    const float* ln1hb = (const float*)d_in[17];
    const float* ln1eg = (const float*)d_in[18];
    const float* ln1eb = (const float*)d_in[19];
    const float* W1    = (const float*)d_in[20];
    const float* b1    = (const float*)d_in[21];
    const float* W2    = (const float*)d_in[22];
    const float* b2    = (const float*)d_in[23];
    const float* ln2hg = (const float*)d_in[24];
    const float* ln2hb = (const float*)d_in[25];
    const int*   ei    = (const int*)d_in[26];

    int Nn = in_sizes[0] / HIDC;
    int Ee = in_sizes[26] / 2;
    const int* dst = ei;
    const int* src = ei + Ee;

    float* S = nullptr;
    cudaGetSymbolAddress((void**)&S, g_scratch);

    __half* QKV  = (__half*)(S + O_QKV);
    __half* cA   = (__half*)(S + O_CA);
    __half* aqk  = (__half*)(S + O_AQK);
    __half* Oe   = (__half*)(S + O_OE);
    float*  scb  = S + O_SCB;
    float*  ssum = S + O_SSUM;
    float*  agg  = S + O_AGG;
    float*  rowv = S + O_ROWV;
    __half* On   = (__half*)(S + O_ON);
    float*  hln  = S + O_HLN;
    __half* hlnt = (__half*)(S + O_HLNT);
    __half* ffn  = (__half*)(S + O_FFN);
    __half* wqkv = (__half*)(S + O_WQKV);
    __half* wewb = (__half*)(S + O_WEWB);
    __half* weo  = (__half*)(S + O_WEO);
    __half* woh  = (__half*)(S + O_WOH);
    __half* woe  = (__half*)(S + O_WOE);
    __half* w1   = (__half*)(S + O_W1);
    __half* w2   = (__half*)(S + O_W2);

    float* outH = (float*)d_out;
    float* outE = outH + (size_t)Nn * HIDC;

    cudaFuncSetAttribute(gemm_nt<0, 1, 0, 1, 6>, cudaFuncAttributeMaxDynamicSharedMemorySize, GNT_SMEM);
    cudaFuncSetAttribute(gemm_nt<2, 0, 0, 1, 4>, cudaFuncAttributeMaxDynamicSharedMemorySize, GNT_SMEM);
    cudaFuncSetAttribute(gemm_nt<0, 1, 1, 0, 2>, cudaFuncAttributeMaxDynamicSharedMemorySize, GNT_SMEM);
    cudaFuncSetAttribute(gemm_nt<1, 1, 0, 0, 4>, cudaFuncAttributeMaxDynamicSharedMemorySize, GNT_SMEM);
    cudaFuncSetAttribute(gemm_ln<1, 256>, cudaFuncAttributeMaxDynamicSharedMemorySize, GLN_SMEM);
    cudaFuncSetAttribute(gemm_ln<0, 256>, cudaFuncAttributeMaxDynamicSharedMemorySize, GLN_SMEM);
    cudaFuncSetAttribute(gemm_ln<0, 512>, cudaFuncAttributeMaxDynamicSharedMemorySize, GLN_SMEM);

    // side stream + events (created once; fallback to serial)
    static cudaStream_t s1 = nullptr;
    static cudaEvent_t evFork = nullptr, evJoin = nullptr;
    static bool streams_ok = false;
    static bool tried = false;
    if (!tried) {
        tried = true;
        streams_ok =
            (cudaStreamCreateWithFlags(&s1, cudaStreamNonBlocking) == cudaSuccess) &&
            (cudaEventCreateWithFlags(&evFork, cudaEventDisableTiming) == cudaSuccess) &&
            (cudaEventCreateWithFlags(&evJoin, cudaEventDisableTiming) == cudaSuccess);
    }

    // prep: pack weights; zero ssum+agg+rowv in one contiguous memset
    pack_kernel<<<cdiv(786432, 256), 256>>>(Wq, Wk, Wv, Wew, Web, Weo, Wo_h, Wo_e, W1, W2, S);
    cudaMemsetAsync(ssum, 0, ((size_t)NMAXC * 8 + (size_t)Nn * 512) * sizeof(float));

    int gmN = cdiv(Nn, 128);
    int gmE = cdiv(Ee, 128);

    // QKV = x(fp32) @ WqkvT  [N, 768] (half out)
    gemm_nt<0, 1, 0, 1, 6><<<gmN, 256, GNT_SMEM>>>(
        x, wqkv, nullptr, QKV, Nn,
        nullptr, nullptr, nullptr, nullptr, nullptr, nullptr);
    // aqk[e] = Q[dst[e]] + K[src[e]]
    aqk_kernel<<<cdiv(Ee, 8), 256>>>(QKV, aqk, dst, src, Ee);
    // fused EwEb GEMM + edge message: conn(fp32) -> cA (half)
    gemm_nt<2, 0, 0, 1, 4><<<gmE, 256, GNT_SMEM>>>(
        conn, wewb, beb, cA, Ee,
        dst, src, aqk, nullptr, nullptr, nullptr);
    // Oe = cA @ WeoT + beo (half) + fused score/clamp/exp/segment-sum
    gemm_nt<0, 1, 1, 0, 2><<<gmE, 256, GNT_SMEM>>>(
        cA, weo, beo, Oe, Ee,
        dst, nullptr, nullptr, Aw, scb, ssum);

    // ---- fork: e-path output GEMM+LN concurrent with attention chain ----
    if (streams_ok) {
        cudaEventRecord(evFork, 0);
        cudaStreamWaitEvent(s1, evFork, 0);
        gemm_ln<0, 256><<<cdiv(Ee, 64), 256, GLN_SMEM, s1>>>(
            Oe, woe, bo_e, conn, ln1eg, ln1eb, outE, nullptr, Ee);
        cudaEventRecord(evJoin, s1);
    } else {
        gemm_ln<0, 256><<<cdiv(Ee, 64), 256, GLN_SMEM>>>(
            Oe, woe, bo_e, conn, ln1eg, ln1eb, outE, nullptr, Ee);
    }

    // attention chain (default stream): unnormalized scatter, normalize in combine
    scatter_kernel<<<(int)cdiv((long)Ee * 64, 256), 256>>>(scb, QKV, Oe, agg, rowv, dst, src, Ee);
    combine_kernel<<<cdiv(Nn, 16), 256>>>(agg, rowv, ssum, BW, On, Nn);

    // h path: hln = LN1h(x + On @ Wo_h + bo_h), + half copy hlnt
    gemm_ln<1, 256><<<cdiv(Nn, 64), 256, GLN_SMEM>>>(
        On, woh, bo_h, x, ln1hg, ln1hb, hln, hlnt, Nn);

    // FFN: ffn = relu(hlnt @ W1 + b1) (half)
    gemm_nt<1, 1, 0, 0, 4><<<gmN, 256, GNT_SMEM>>>(
        hlnt, w1, b1, ffn, Nn,
        nullptr, nullptr, nullptr, nullptr, nullptr, nullptr);
    // outH = LN2h(hln + ffn @ W2 + b2)  (K=512, fused)
    gemm_ln<0, 512><<<cdiv(Nn, 64), 256, GLN_SMEM>>>(
        ffn, w2, b2, hln, ln2hg, ln2hb, outH, nullptr, Nn);

    // ---- join ----
    if (streams_ok) {
        cudaStreamWaitEvent((cudaStream_t)0, evJoin, 0);
    }
}

// round 15
// speedup vs baseline: 1.7967x; 1.0014x over previous
#include <cuda_runtime.h>
#include <cuda_fp16.h>
#include <math.h>
#include <stdint.h>

#define HIDC 256
#define NHEAD 8
#define CLAMP_V 5.0f

static const int NMAXC = 50000;
static const int EMAXC = 320000;

// ---------------- scratch layout ----------------
#define O_QK   ((size_t)0)                          // N*512 (half)
#define O_V    (O_QK   + (size_t)NMAXC*256)         // N*256 (half)
#define O_CA   (O_V    + (size_t)NMAXC*128)         // E*256 (half)
#define O_AQK  (O_CA   + (size_t)EMAXC*128)         // E*256 (half)
#define O_OE   (O_AQK  + (size_t)EMAXC*128)         // E*256 (half)
#define O_SCB  (O_OE   + (size_t)EMAXC*128)         // E*8  (f32, exp(score))
#define O_SSUM (O_SCB  + (size_t)EMAXC*8)           // N*8  (f32)  [contig w/ AGG]
#define O_AGG  (O_SSUM + (size_t)NMAXC*8)           // N*256 (f32)
#define O_ROWV (O_AGG  + (size_t)NMAXC*256)         // N*256 (f32)
#define O_ON   (O_ROWV + (size_t)NMAXC*256)         // N*256 (half)
#define O_HLN  (O_ON   + (size_t)NMAXC*128)         // N*256 (f32)
#define O_HLNT (O_HLN  + (size_t)NMAXC*256)         // N*256 (half)
#define O_FFN  (O_HLNT + (size_t)NMAXC*128)         // N*512 (half)
#define O_WQKV (O_FFN  + (size_t)NMAXC*256)         // 768*256 (half, [N][K])
#define O_WEWB (O_WQKV + (size_t)768*128)           // 512*256 (half)
#define O_WEO  (O_WEWB + (size_t)512*128)           // 256*256 (half)
#define O_WOH  (O_WEO  + (size_t)256*128)           // 256*256 (half)
#define O_WOE  (O_WOH  + (size_t)256*128)           // 256*256 (half)
#define O_W1   (O_WOE  + (size_t)256*128)           // 512*256 (half)
#define O_W2   (O_W1   + (size_t)512*128)           // 256*512 (half)
#define O_TOTAL (O_W2  + (size_t)256*256)

__device__ float g_scratch[O_TOTAL];

static inline int cdiv(int a, int b) { return (a + b - 1) / b; }

// ---------------- helpers ----------------
__device__ __forceinline__ void mma_f16(float c[4], const uint32_t a[4], const uint32_t b[2]) {
    asm volatile(
        "mma.sync.aligned.m16n8k16.row.col.f32.f16.f16.f32 "
        "{%0,%1,%2,%3}, {%4,%5,%6,%7}, {%8,%9}, {%0,%1,%2,%3};"
        : "+f"(c[0]), "+f"(c[1]), "+f"(c[2]), "+f"(c[3])
        : "r"(a[0]), "r"(a[1]), "r"(a[2]), "r"(a[3]), "r"(b[0]), "r"(b[1]));
}

__device__ __forceinline__ void ldsm4(uint32_t& r0, uint32_t& r1, uint32_t& r2, uint32_t& r3,
                                      uint32_t addr) {
    asm volatile("ldmatrix.sync.aligned.m8n8.x4.shared.b16 {%0,%1,%2,%3}, [%4];"
                 : "=r"(r0), "=r"(r1), "=r"(r2), "=r"(r3) : "r"(addr));
}

__device__ __forceinline__ void cp16(uint32_t saddr, const void* g, bool pred) {
    int sz = pred ? 16 : 0;
    asm volatile("cp.async.cg.shared.global [%0], [%1], 16, %2;\n"
                 :: "r"(saddr), "l"(g), "r"(sz));
}
#define CP_COMMIT() asm volatile("cp.async.commit_group;\n" ::)
#define CP_WAIT(n)  asm volatile("cp.async.wait_group %0;\n" :: "n"(n))

__device__ __forceinline__ void redv4(float* addr, float a, float b, float c, float d) {
    asm volatile("red.global.add.v4.f32 [%0], {%1, %2, %3, %4};"
                 :: "l"(addr), "f"(a), "f"(b), "f"(c), "f"(d) : "memory");
}

// ---------------- aqk: per-edge coalesced gather (QK stride 512) ----------------
__global__ void aqk_kernel(const __half* __restrict__ QK, __half* __restrict__ aqk,
                           const int* __restrict__ dst, const int* __restrict__ src, int E) {
    int w = (blockIdx.x * 256 + threadIdx.x) >> 5;
    int lane = threadIdx.x & 31;
    if (w >= E) return;
    int dn = dst[w], sn = src[w];
    int4 qv = ((const int4*)(QK + (size_t)dn * 512))[lane];
    int4 kv = ((const int4*)(QK + (size_t)sn * 512 + 256))[lane];
    __half2* qh = (__half2*)&qv;
    __half2* kh = (__half2*)&kv;
    int4 out;
    __half2* oh = (__half2*)&out;
#pragma unroll
    for (int i = 0; i < 4; i++) oh[i] = __hadd2(qh[i], kh[i]);
    ((int4*)(aqk + (size_t)w * 256))[lane] = out;
}

// ---------------- gemm_nt: K=256-resident-A fp16 GEMM ----------------
#define SAR 264
#define NTA_BYTES (128 * SAR * 2)
#define SAH 72
#define NTB_TILEH (128 * SAH)
#define NTB_BYTES (NTB_TILEH * 2)
#define GNT_SMEM (NTA_BYTES + 2 * NTB_BYTES)

// ACT: 0 plain, 1 bias+relu, 2 fused edge message
// SCORE: fused score -> exp -> scb + red.add ssum
template <int ACT, int OUTH, int SCORE, int CVTA, int NT>
__global__ __launch_bounds__(256, 2)
void gemm_nt(const void* __restrict__ Av, const __half* __restrict__ B,
             const float* __restrict__ bias,
             void* __restrict__ Cv, int M,
             const int* __restrict__ dst, const int* __restrict__ src,
             const __half* __restrict__ AQK, const float* __restrict__ Aw,
             float* __restrict__ scb, float* __restrict__ ssum) {
    extern __shared__ __half smh[];
    constexpr int Ncol = NT * 128;
    constexpr int NS = 4 * NT;

    const int tid = threadIdx.x;
    const int warp = tid >> 5;
    const int lane = tid & 31;
    const int g = lane >> 2;
    const int t = lane & 3;
    const int warp_m = warp & 3;
    const int warp_n = warp >> 2;
    const int m0 = blockIdx.x * 128;

    const uint32_t sbase = (uint32_t)__cvta_generic_to_shared(smh);
    const uint32_t bbase = sbase + NTA_BYTES;

    const int srow = tid >> 3;
    const int sseg = tid & 7;

    const int lm_row = lane & 15;
    const int lm_k   = (lane >> 4) << 3;

    if (!CVTA) {
        const __half* A = (const __half*)Av;
#pragma unroll
        for (int i = 0; i < 16; i++) {
            int idx = tid + i * 256;
            int row = idx >> 5, seg = idx & 31;
            cp16(sbase + (row * SAR + seg * 8) * 2,
                 A + (size_t)(m0 + row) * 256 + seg * 8, (m0 + row) < M);
        }
    }
#pragma unroll
    for (int u = 0; u < 4; u++) {
        int r = srow + u * 32;
        cp16(bbase + (r * SAH + sseg * 8) * 2, B + (size_t)r * 256 + sseg * 8, true);
    }
    CP_COMMIT();
    if (CVTA) {
        const float* A32 = (const float*)Av;
#pragma unroll
        for (int i = 0; i < 32; i++) {
            int idx = tid + i * 256;
            int row = idx >> 6, c4 = idx & 63;
            float4 v = make_float4(0.f, 0.f, 0.f, 0.f);
            if (m0 + row < M) v = *(const float4*)&A32[(size_t)(m0 + row) * 256 + c4 * 4];
            __half2 h0 = __float22half2_rn(make_float2(v.x, v.y));
            __half2 h1 = __float22half2_rn(make_float2(v.z, v.w));
            *(__half2*)&smh[row * SAR + c4 * 4] = h0;
            *(__half2*)&smh[row * SAR + c4 * 4 + 2] = h1;
        }
    }

    float acc[2][8][4];
#pragma unroll
    for (int i = 0; i < 2; i++)
#pragma unroll
        for (int j = 0; j < 8; j++)
#pragma unroll
            for (int q = 0; q < 4; q++) acc[i][j][q] = 0.0f;

#pragma unroll
    for (int s = 0; s < NS; s++) {
        if (s + 1 < NS) {
            const int nn0 = ((s + 1) >> 2) * 128;
            const int nc0 = ((s + 1) & 3) * 64;
            const int nb = (s + 1) & 1;
#pragma unroll
            for (int u = 0; u < 4; u++) {
                int r = srow + u * 32;
                cp16(bbase + (nb * NTB_TILEH + r * SAH + sseg * 8) * 2,
                     B + (size_t)(nn0 + r) * 256 + nc0 + sseg * 8, true);
            }
            CP_COMMIT();
            CP_WAIT(1);
        } else {
            CP_WAIT(0);
        }
        __syncthreads();

        const uint32_t bbuf = bbase + (s & 1) * NTB_BYTES;
        const int kk_base = (s & 3) * 64;

#pragma unroll
        for (int ks = 0; ks < 4; ks++) {
            const int kk = kk_base + ks * 16;
            const int kkb = ks * 16;
            uint32_t af[2][4];
#pragma unroll
            for (int i = 0; i < 2; i++) {
                int rm = warp_m * 32 + i * 16;
                ldsm4(af[i][0], af[i][1], af[i][2], af[i][3],
                      sbase + ((rm + lm_row) * SAR + kk + lm_k) * 2);
            }
            uint32_t bf[8][2];
#pragma unroll
            for (int jj = 0; jj < 4; jj++) {
                int nb2 = warp_n * 64 + jj * 16;
                uint32_t r0, r1, r2, r3;
                ldsm4(r0, r1, r2, r3, bbuf + ((nb2 + lm_row) * SAH + kkb + lm_k) * 2);
                bf[2 * jj][0] = r0;     bf[2 * jj][1] = r2;
                bf[2 * jj + 1][0] = r1; bf[2 * jj + 1][1] = r3;
            }
#pragma unroll
            for (int i = 0; i < 2; i++)
#pragma unroll
                for (int j = 0; j < 8; j++)
                    mma_f16(acc[i][j], af[i], bf[j]);
        }

        if ((s & 3) == 3) {
            const int n0 = (s >> 2) * 128;
            if (ACT == 2) {
                __half* C = (__half*)Cv;
                float bebv[8];
                int cqv[8];
#pragma unroll
                for (int j = 0; j < 8; j++) {
                    int cq = (n0 >> 1) + warp_n * 32 + j * 4 + t;
                    cqv[j] = cq;
                    bebv[j] = bias[cq];
                }
#pragma unroll
                for (int i = 0; i < 2; i++) {
#pragma unroll
                    for (int half_ = 0; half_ < 2; half_++) {
                        int r = m0 + warp_m * 32 + i * 16 + half_ * 8 + g;
                        if (r >= M) continue;
                        const __half* arow = AQK + (size_t)r * 256;
#pragma unroll
                        for (int j = 0; j < 8; j++) {
                            float ew = acc[i][j][half_ * 2 + 0];
                            float eb = acc[i][j][half_ * 2 + 1] + bebv[j];
                            float aqk = __half2float(arow[cqv[j]]);
                            float c1 = aqk * ew;
                            float c2 = copysignf(sqrtf(fabsf(c1)), c1);
                            C[(size_t)r * 256 + cqv[j]] = __float2half(fmaxf(c2 + eb, 0.f));
                        }
                    }
                }
            } else if (SCORE) {
                __half* C = (__half*)Cv;
                const int h0 = (n0 + warp_n * 64) >> 5;
                float aw0[8], aw1[8];
#pragma unroll
                for (int j4 = 0; j4 < 4; j4++) {
                    int d = j4 * 8 + 2 * t;
                    aw0[2 * j4]     = __ldg(&Aw[d * 8 + h0]);
                    aw0[2 * j4 + 1] = __ldg(&Aw[(d + 1) * 8 + h0]);
                    aw1[2 * j4]     = __ldg(&Aw[d * 8 + h0 + 1]);
                    aw1[2 * j4 + 1] = __ldg(&Aw[(d + 1) * 8 + h0 + 1]);
                }
                float2 bvj[8];
#pragma unroll
                for (int j = 0; j < 8; j++)
                    bvj[j] = *(const float2*)&bias[n0 + warp_n * 64 + j * 8 + 2 * t];
#pragma unroll
                for (int i = 0; i < 2; i++) {
#pragma unroll
                    for (int half_ = 0; half_ < 2; half_++) {
                        int r = m0 + warp_m * 32 + i * 16 + half_ * 8 + g;
                        float s0 = 0.f, s1 = 0.f;
                        if (r < M) {
#pragma unroll
                            for (int j = 0; j < 8; j++) {
                                float ox = acc[i][j][half_ * 2 + 0] + bvj[j].x;
                                float oy = acc[i][j][half_ * 2 + 1] + bvj[j].y;
                                __half2 h2v = __float22half2_rn(make_float2(ox, oy));
                                ox = __half2float(__low2half(h2v));
                                oy = __half2float(__high2half(h2v));
                                int c = n0 + warp_n * 64 + j * 8 + 2 * t;
                                *(__half2*)&C[(size_t)r * Ncol + c] = h2v;
                                if (j < 4) {
                                    s0 += ox * aw0[2 * j] + oy * aw0[2 * j + 1];
                                } else {
                                    s1 += ox * aw1[2 * (j - 4)] + oy * aw1[2 * (j - 4) + 1];
                                }
                            }
                        }
                        s0 += __shfl_xor_sync(0xffffffffu, s0, 1);
                        s0 += __shfl_xor_sync(0xffffffffu, s0, 2);
                        s1 += __shfl_xor_sync(0xffffffffu, s1, 1);
                        s1 += __shfl_xor_sync(0xffffffffu, s1, 2);
                        if (r < M && t == 0) {
                            float e0 = expf(fminf(fmaxf(s0, -CLAMP_V), CLAMP_V));
                            float e1 = expf(fminf(fmaxf(s1, -CLAMP_V), CLAMP_V));
                            scb[(size_t)r * 8 + h0] = e0;
                            scb[(size_t)r * 8 + h0 + 1] = e1;
                            int dn = dst[r];
                            atomicAdd(&ssum[dn * 8 + h0], e0);
                            atomicAdd(&ssum[dn * 8 + h0 + 1], e1);
                        }
                    }
                }
            } else {
#pragma unroll
                for (int j = 0; j < 8; j++) {
                    int c = n0 + warp_n * 64 + j * 8 + 2 * t;
                    float2 bv = make_float2(0.f, 0.f);
                    if (bias) bv = *(const float2*)&bias[c];
#pragma unroll
                    for (int i = 0; i < 2; i++) {
                        int rbase = m0 + warp_m * 32 + i * 16 + g;
#pragma unroll
                        for (int half_ = 0; half_ < 2; half_++) {
                            int r = rbase + half_ * 8;
                            if (r >= M) continue;
                            float ox = acc[i][j][half_ * 2 + 0] + bv.x;
                            float oy = acc[i][j][half_ * 2 + 1] + bv.y;
                            if (ACT == 1) { ox = fmaxf(ox, 0.f); oy = fmaxf(oy, 0.f); }
                            if (OUTH) {
                                *(__half2*)&((__half*)Cv)[(size_t)r * Ncol + c] =
                                    __float22half2_rn(make_float2(ox, oy));
                            } else {
                                *(float2*)&((float*)Cv)[(size_t)r * Ncol + c] =
                                    make_float2(ox, oy);
                            }
                        }
                    }
                }
            }
#pragma unroll
            for (int i = 0; i < 2; i++)
#pragma unroll
                for (int j = 0; j < 8; j++)
#pragma unroll
                    for (int q = 0; q < 4; q++) acc[i][j][q] = 0.0f;
        }
        __syncthreads();
    }
}

// ---------------- fp16 GEMM + fused residual + LayerNorm ----------------
#define LNA_TILEH (64 * SAH)
#define LNA_TILEB (LNA_TILEH * 2)
#define LNB_TILEH (256 * SAH)
#define LNB_TILEB (LNB_TILEH * 2)
#define GLN_SMEM (2 * LNA_TILEB + 2 * LNB_TILEB)

template <int OUT2, int KVAL>
__global__ __launch_bounds__(256, 2)
void gemm_ln(const __half* __restrict__ A, const __half* __restrict__ B,
             const float* __restrict__ bias, const float* __restrict__ resid,
             const float* __restrict__ lng, const float* __restrict__ lnb,
             float* __restrict__ outF, __half* __restrict__ outH, int M) {
    extern __shared__ __half smh[];
    constexpr int KT = KVAL / 64;

    const int tid = threadIdx.x;
    const int warp = tid >> 5;
    const int lane = tid & 31;
    const int g = lane >> 2;
    const int t = lane & 3;
    const int warp_m = warp & 1;
    const int warp_n = warp >> 1;
    const int m0 = blockIdx.x * 64;

    const uint32_t sbase = (uint32_t)__cvta_generic_to_shared(smh);
    const uint32_t bbase = sbase + 2 * LNA_TILEB;

    const int srow = tid >> 3;
    const int sseg = tid & 7;
    const bool apred[2] = { m0 + srow < M, m0 + srow + 32 < M };
    const __half* Aptr = A + (size_t)(m0 + srow) * KVAL + sseg * 8;
    const __half* Bptr = B + (size_t)srow * KVAL + sseg * 8;

    const int lm_row = lane & 15;
    const int lm_k   = (lane >> 4) << 3;

    float acc[2][8][4];
#pragma unroll
    for (int i = 0; i < 2; i++)
#pragma unroll
        for (int j = 0; j < 8; j++)
#pragma unroll
            for (int q = 0; q < 4; q++) acc[i][j][q] = 0.0f;

#pragma unroll
    for (int u = 0; u < 2; u++) {
        int r = srow + u * 32;
        cp16(sbase + (r * SAH + sseg * 8) * 2, Aptr + (size_t)(u * 32) * KVAL, apred[u]);
    }
#pragma unroll
    for (int u = 0; u < 8; u++) {
        int r = srow + u * 32;
        cp16(bbase + (r * SAH + sseg * 8) * 2, Bptr + (size_t)(u * 32) * KVAL, true);
    }
    CP_COMMIT();

#pragma unroll
    for (int kt = 0; kt < KT; kt++) {
        const int buf = kt & 1;
        if (kt + 1 < KT) {
            const int k0 = (kt + 1) << 6;
            const int nb = buf ^ 1;
#pragma unroll
            for (int u = 0; u < 2; u++) {
                int r = srow + u * 32;
                cp16(sbase + (nb * LNA_TILEH + r * SAH + sseg * 8) * 2,
                     Aptr + (size_t)(u * 32) * KVAL + k0, apred[u]);
            }
#pragma unroll
            for (int u = 0; u < 8; u++) {
                int r = srow + u * 32;
                cp16(bbase + (nb * LNB_TILEH + r * SAH + sseg * 8) * 2,
                     Bptr + (size_t)(u * 32) * KVAL + k0, true);
            }
            CP_COMMIT();
            CP_WAIT(1);
        } else {
            CP_WAIT(0);
        }
        __syncthreads();

        const uint32_t abuf = sbase + buf * LNA_TILEB;
        const uint32_t bbuf = bbase + buf * LNB_TILEB;

#pragma unroll
        for (int ks = 0; ks < 4; ks++) {
            const int kk = ks * 16;
            uint32_t af[2][4];
#pragma unroll
            for (int i = 0; i < 2; i++) {
                int rm = warp_m * 32 + i * 16;
                ldsm4(af[i][0], af[i][1], af[i][2], af[i][3],
                      abuf + ((rm + lm_row) * SAH + kk + lm_k) * 2);
            }
            uint32_t bf[8][2];
#pragma unroll
            for (int jj = 0; jj < 4; jj++) {
                int nb2 = warp_n * 64 + jj * 16;
                uint32_t r0, r1, r2, r3;
                ldsm4(r0, r1, r2, r3, bbuf + ((nb2 + lm_row) * SAH + kk + lm_k) * 2);
                bf[2 * jj][0] = r0;     bf[2 * jj][1] = r2;
                bf[2 * jj + 1][0] = r1; bf[2 * jj + 1][1] = r3;
            }
#pragma unroll
            for (int i = 0; i < 2; i++)
#pragma unroll
                for (int j = 0; j < 8; j++)
                    mma_f16(acc[i][j], af[i], bf[j]);
        }
        __syncthreads();
    }

    float* red = (float*)smh;

#pragma unroll
    for (int i = 0; i < 2; i++) {
#pragma unroll
        for (int half_ = 0; half_ < 2; half_++) {
            const int rl = warp_m * 32 + i * 16 + half_ * 8 + g;
            const int r = m0 + rl;
            float s = 0.f, s2 = 0.f;
            if (r < M) {
#pragma unroll
                for (int j = 0; j < 8; j++) {
                    int c = warp_n * 64 + j * 8 + 2 * t;
                    float2 bv = *(const float2*)&bias[c];
                    float2 rv = *(const float2*)&resid[(size_t)r * HIDC + c];
                    float ox = acc[i][j][half_ * 2 + 0] + bv.x + rv.x;
                    float oy = acc[i][j][half_ * 2 + 1] + bv.y + rv.y;
                    acc[i][j][half_ * 2 + 0] = ox;
                    acc[i][j][half_ * 2 + 1] = oy;
                    s += ox + oy;
                    s2 += ox * ox + oy * oy;
                }
            }
            s  += __shfl_xor_sync(0xffffffffu, s, 1);
            s  += __shfl_xor_sync(0xffffffffu, s, 2);
            s2 += __shfl_xor_sync(0xffffffffu, s2, 1);
            s2 += __shfl_xor_sync(0xffffffffu, s2, 2);
            if (t == 0) {
                red[rl * 8 + warp_n] = s;
                red[rl * 8 + 4 + warp_n] = s2;
            }
        }
    }
    __syncthreads();

#pragma unroll
    for (int i = 0; i < 2; i++) {
#pragma unroll
        for (int half_ = 0; half_ < 2; half_++) {
            const int rl = warp_m * 32 + i * 16 + half_ * 8 + g;
            const int r = m0 + rl;
            if (r >= M) continue;
            float S  = red[rl * 8 + 0] + red[rl * 8 + 1] + red[rl * 8 + 2] + red[rl * 8 + 3];
            float S2 = red[rl * 8 + 4] + red[rl * 8 + 5] + red[rl * 8 + 6] + red[rl * 8 + 7];
            float mean = S * (1.0f / HIDC);
            float var = S2 * (1.0f / HIDC) - mean * mean;
            float rstd = rsqrtf(var + 1e-5f);
#pragma unroll
            for (int j = 0; j < 8; j++) {
                int c = warp_n * 64 + j * 8 + 2 * t;
                float2 gv = *(const float2*)&lng[c];
                float2 bv = *(const float2*)&lnb[c];
                float vx = (acc[i][j][half_ * 2 + 0] - mean) * rstd * gv.x + bv.x;
                float vy = (acc[i][j][half_ * 2 + 1] - mean) * rstd * gv.y + bv.y;
                *(float2*)&outF[(size_t)r * HIDC + c] = make_float2(vx, vy);
                if (OUT2)
                    *(__half2*)&outH[(size_t)r * HIDC + c] =
                        __float22half2_rn(make_float2(vx, vy));
            }
        }
    }
}

// ---------------- weight pack ----------------
__global__ void pack_kernel(const float* Wq, const float* Wk, const float* Wv,
                            const float* Wew, const float* Web, const float* Weo,
                            const float* Wo_h, const float* Wo_e,
                            const float* W1, const float* W2, float* S) {
    int i = blockIdx.x * 256 + threadIdx.x;
    if (i < 196608) {
        int n = i >> 8, k = i & 255;
        float v = (n < 256) ? Wq[k * 256 + n]
                : (n < 512) ? Wk[k * 256 + n - 256]
                            : Wv[k * 256 + n - 512];
        ((__half*)(S + O_WQKV))[i] = __float2half(v);
    }
    int i2 = i - 196608;
    if (i2 >= 0 && i2 < 131072) {
        int n = i2 >> 8, k = i2 & 255, c = n >> 1;
        float v = (n & 1) ? Web[k * 256 + c] : Wew[k * 256 + c];
        ((__half*)(S + O_WEWB))[i2] = __float2half(v);
    }
    int i3 = i - 327680;
    if (i3 >= 0 && i3 < 65536) {
        int n = i3 >> 8, k = i3 & 255;
        ((__half*)(S + O_WEO))[i3] = __float2half(Weo[k * 256 + n]);
    }
    int i4 = i - 393216;
    if (i4 >= 0 && i4 < 65536) {
        int n = i4 >> 8, k = i4 & 255;
        ((__half*)(S + O_WOH))[i4] = __float2half(Wo_h[k * 256 + n]);
    }
    int i5 = i - 458752;
    if (i5 >= 0 && i5 < 65536) {
        int n = i5 >> 8, k = i5 & 255;
        ((__half*)(S + O_WOE))[i5] = __float2half(Wo_e[k * 256 + n]);
    }
    int i6 = i - 524288;
    if (i6 >= 0 && i6 < 131072) {
        int n = i6 >> 8, k = i6 & 255;
        ((__half*)(S + O_W1))[i6] = __float2half(W1[k * 512 + n]);
    }
    int i7 = i - 655360;
    if (i7 >= 0 && i7 < 131072) {
        int n = i7 >> 9, k = i7 & 511;
        ((__half*)(S + O_W2))[i7] = __float2half(W2[k * 256 + n]);
    }
}

// ---------------- scatter: unnormalized vector RED (V buffer [N][256]) ----------------
__global__ void scatter_kernel(const float* __restrict__ exv,
                               const __half* __restrict__ V, const __half* __restrict__ Oe,
                               float* __restrict__ agg, float* __restrict__ rowv,
                               const int* __restrict__ dst, const int* __restrict__ src, int E) {
    long t = (long)blockIdx.x * 256 + threadIdx.x;
    if (t >= (long)E * 64) return;
    int e = (int)(t >> 6), q = (int)(t & 63);
    int h = q >> 3;
    int dn = dst[e], sn = src[e];
    float sc = exv[(size_t)e * NHEAD + h];
    const __half2* vp = (const __half2*)(V + (size_t)sn * 256 + q * 4);
    const __half2* op = (const __half2*)(Oe + (size_t)e * HIDC + q * 4);
    float2 v0 = __half22float2(vp[0]), v1 = __half22float2(vp[1]);
    float2 o0 = __half22float2(op[0]), o1 = __half22float2(op[1]);
    redv4(&agg[(size_t)dn * HIDC + q * 4], v0.x * sc, v0.y * sc, v1.x * sc, v1.y * sc);
    redv4(&rowv[(size_t)dn * HIDC + q * 4], o0.x * sc, o0.y * sc, o1.x * sc, o1.y * sc);
}

// ---------------- combine: On = half((agg + einsum(rowv, BW)) / ssum) ----------------
__global__ void combine_kernel(const float* __restrict__ agg, const float* __restrict__ rowv,
                               const float* __restrict__ ssum,
                               const float* __restrict__ BW, __half* __restrict__ On, int Nn) {
    __shared__ float sBW[32 * 8 * 32];
    __shared__ float srv[HIDC];
    int tid = threadIdx.x;
    for (int i = tid; i < 32 * 8 * 32; i += 256) sBW[i] = BW[i];
    int h = tid >> 5, c = tid & 31;
    for (int r = 0; r < 16; r++) {
        int n = blockIdx.x * 16 + r;
        __syncthreads();
        if (n < Nn) srv[tid] = rowv[(size_t)n * HIDC + tid];
        __syncthreads();
        if (n < Nn) {
            float s = agg[(size_t)n * HIDC + tid];
#pragma unroll
            for (int d = 0; d < 32; d++)
                s += srv[h * 32 + d] * sBW[d * HIDC + h * 32 + c];
            float inv = 1.0f / (ssum[n * NHEAD + h] + 1e-16f);
            On[(size_t)n * HIDC + tid] = __float2half(s * inv);
        }
    }
}

// ---------------- launch ----------------
extern "C" void kernel_launch(void* const* d_in, const int* in_sizes, int n_in,
                              void* d_out, int out_size) {
    const float* x     = (const float*)d_in[0];
    const float* conn  = (const float*)d_in[1];
    const float* Wq    = (const float*)d_in[2];
    const float* Wk    = (const float*)d_in[3];
    const float* Wv    = (const float*)d_in[4];
    const float* Wew   = (const float*)d_in[5];
    const float* Web   = (const float*)d_in[6];
    const float* beb   = (const float*)d_in[7];
    const float* Weo   = (const float*)d_in[8];
    const float* beo   = (const float*)d_in[9];
    const float* Aw    = (const float*)d_in[10];
    const float* BW    = (const float*)d_in[11];
    const float* Wo_h  = (const float*)d_in[12];
    const float* bo_h  = (const float*)d_in[13];
    const float* Wo_e  = (const float*)d_in[14];
    const float* bo_e  = (const float*)d_in[15];
    const float* ln1hg = (const float*)d_in[16];
    const float* ln1hb = (const float*)d_in[17];
    const float* ln1eg = (const float*)d_in[18];
    const float* ln1eb = (const float*)d_in[19];
    const float* W1    = (const float*)d_in[20];
    const float* b1    = (const float*)d_in[21];
    const float* W2    = (const float*)d_in[22];
    const float* b2    = (const float*)d_in[23];
    const float* ln2hg = (const float*)d_in[24];
    const float* ln2hb = (const float*)d_in[25];
    const int*   ei    = (const int*)d_in[26];

    int Nn = in_sizes[0] / HIDC;
    int Ee = in_sizes[26] / 2;
    const int* dst = ei;
    const int* src = ei + Ee;

    float* S = nullptr;
    cudaGetSymbolAddress((void**)&S, g_scratch);

    __half* QK   = (__half*)(S + O_QK);
    __half* Vb   = (__half*)(S + O_V);
    __half* cA   = (__half*)(S + O_CA);
    __half* aqk  = (__half*)(S + O_AQK);
    __half* Oe   = (__half*)(S + O_OE);
    float*  scb  = S + O_SCB;
    float*  ssum = S + O_SSUM;
    float*  agg  = S + O_AGG;
    float*  rowv = S + O_ROWV;
    __half* On   = (__half*)(S + O_ON);
    float*  hln  = S + O_HLN;
    __half* hlnt = (__half*)(S + O_HLNT);
    __half* ffn  = (__half*)(S + O_FFN);
    __half* wqkv = (__half*)(S + O_WQKV);
    __half* wewb = (__half*)(S + O_WEWB);
    __half* weo  = (__half*)(S + O_WEO);
    __half* woh  = (__half*)(S + O_WOH);
    __half* woe  = (__half*)(S + O_WOE);
    __half* w1   = (__half*)(S + O_W1);
    __half* w2   = (__half*)(S + O_W2);

    float* outH = (float*)d_out;
    float* outE = outH + (size_t)Nn * HIDC;

    cudaFuncSetAttribute(gemm_nt<0, 1, 0, 1, 4>, cudaFuncAttributeMaxDynamicSharedMemorySize, GNT_SMEM);
    cudaFuncSetAttribute(gemm_nt<0, 1, 0, 1, 2>, cudaFuncAttributeMaxDynamicSharedMemorySize, GNT_SMEM);
    cudaFuncSetAttribute(gemm_nt<2, 0, 0, 1, 4>, cudaFuncAttributeMaxDynamicSharedMemorySize, GNT_SMEM);
    cudaFuncSetAttribute(gemm_nt<0, 1, 1, 0, 2>, cudaFuncAttributeMaxDynamicSharedMemorySize, GNT_SMEM);
    cudaFuncSetAttribute(gemm_nt<1, 1, 0, 0, 4>, cudaFuncAttributeMaxDynamicSharedMemorySize, GNT_SMEM);
    cudaFuncSetAttribute(gemm_ln<1, 256>, cudaFuncAttributeMaxDynamicSharedMemorySize, GLN_SMEM);
    cudaFuncSetAttribute(gemm_ln<0, 256>, cudaFuncAttributeMaxDynamicSharedMemorySize, GLN_SMEM);
    cudaFuncSetAttribute(gemm_ln<0, 512>, cudaFuncAttributeMaxDynamicSharedMemorySize, GLN_SMEM);

    // side stream + events (created once; fallback to serial)
    static cudaStream_t s1 = nullptr;
    static cudaEvent_t evQK = nullptr, evV = nullptr, evFork = nullptr, evJoin = nullptr;
    static bool streams_ok = false;
    static bool tried = false;
    if (!tried) {
        tried = true;
        streams_ok =
            (cudaStreamCreateWithFlags(&s1, cudaStreamNonBlocking) == cudaSuccess) &&
            (cudaEventCreateWithFlags(&evQK, cudaEventDisableTiming) == cudaSuccess) &&
            (cudaEventCreateWithFlags(&evV, cudaEventDisableTiming) == cudaSuccess) &&
            (cudaEventCreateWithFlags(&evFork, cudaEventDisableTiming) == cudaSuccess) &&
            (cudaEventCreateWithFlags(&evJoin, cudaEventDisableTiming) == cudaSuccess);
    }

    // prep: pack weights; zero ssum+agg+rowv in one contiguous memset
    pack_kernel<<<cdiv(786432, 256), 256>>>(Wq, Wk, Wv, Wew, Web, Weo, Wo_h, Wo_e, W1, W2, S);
    cudaMemsetAsync(ssum, 0, ((size_t)NMAXC * 8 + (size_t)Nn * 512) * sizeof(float));

    int gmN = cdiv(Nn, 128);
    int gmE = cdiv(Ee, 128);

    // QK = x @ Wqk  [N, 512] (half out)
    gemm_nt<0, 1, 0, 1, 4><<<gmN, 256, GNT_SMEM>>>(
        x, wqkv, nullptr, QK, Nn,
        nullptr, nullptr, nullptr, nullptr, nullptr, nullptr);

    if (streams_ok) {
        cudaEventRecord(evQK, 0);
        cudaStreamWaitEvent(s1, evQK, 0);
        // V = x @ Wv  [N, 256] on side stream (overlaps aqk + EwEb)
        gemm_nt<0, 1, 0, 1, 2><<<gmN, 256, GNT_SMEM, s1>>>(
            x, wqkv + (size_t)512 * 256, nullptr, Vb, Nn,
            nullptr, nullptr, nullptr, nullptr, nullptr, nullptr);
        cudaEventRecord(evV, s1);
    } else {
        gemm_nt<0, 1, 0, 1, 2><<<gmN, 256, GNT_SMEM>>>(
            x, wqkv + (size_t)512 * 256, nullptr, Vb, Nn,
            nullptr, nullptr, nullptr, nullptr, nullptr, nullptr);
    }

    // aqk[e] = Q[dst[e]] + K[src[e]]
    aqk_kernel<<<cdiv(Ee, 8), 256>>>(QK, aqk, dst, src, Ee);
    // fused EwEb GEMM + edge message: conn(fp32) -> cA (half)
    gemm_nt<2, 0, 0, 1, 4><<<gmE, 256, GNT_SMEM>>>(
        conn, wewb, beb, cA, Ee,
        dst, src, aqk, nullptr, nullptr, nullptr);
    // Oe = cA @ WeoT + beo (half) + fused score/clamp/exp/segment-sum
    gemm_nt<0, 1, 1, 0, 2><<<gmE, 256, GNT_SMEM>>>(
        cA, weo, beo, Oe, Ee,
        dst, nullptr, nullptr, Aw, scb, ssum);

    // ---- fork: e-path output GEMM+LN concurrent with attention chain ----
    if (streams_ok) {
        cudaEventRecord(evFork, 0);
        cudaStreamWaitEvent(s1, evFork, 0);
        gemm_ln<0, 256><<<cdiv(Ee, 64), 256, GLN_SMEM, s1>>>(
            Oe, woe, bo_e, conn, ln1eg, ln1eb, outE, nullptr, Ee);
        cudaEventRecord(evJoin, s1);
        cudaStreamWaitEvent((cudaStream_t)0, evV, 0);  // V ready before scatter
    }

    // attention chain (default stream)
    scatter_kernel<<<(int)cdiv((long)Ee * 64, 256), 256>>>(scb, Vb, Oe, agg, rowv, dst, src, Ee);
    combine_kernel<<<cdiv(Nn, 16), 256>>>(agg, rowv, ssum, BW, On, Nn);

    if (!streams_ok) {
        gemm_ln<0, 256><<<cdiv(Ee, 64), 256, GLN_SMEM>>>(
            Oe, woe, bo_e, conn, ln1eg, ln1eb, outE, nullptr, Ee);
    }

    // h path: hln = LN1h(x + On @ Wo_h + bo_h), + half copy hlnt
    gemm_ln<1, 256><<<cdiv(Nn, 64), 256, GLN_SMEM>>>(
        On, woh, bo_h, x, ln1hg, ln1hb, hln, hlnt, Nn);

    // FFN: ffn = relu(hlnt @ W1 + b1) (half)
    gemm_nt<1, 1, 0, 0, 4><<<gmN, 256, GNT_SMEM>>>(
        hlnt, w1, b1, ffn, Nn,
        nullptr, nullptr, nullptr, nullptr, nullptr, nullptr);
    // outH = LN2h(hln + ffn @ W2 + b2)  (K=512, fused)
    gemm_ln<0, 512><<<cdiv(Nn, 64), 256, GLN_SMEM>>>(
        ffn, w2, b2, hln, ln2hg, ln2hb, outH, nullptr, Nn);

    // ---- join ----
    if (streams_ok) {
        cudaStreamWaitEvent((cudaStream_t)0, evJoin, 0);
    }
}